// round 9
// baseline (speedup 1.0000x reference)
#include <cuda_runtime.h>
#include <cuda_bf16.h>
#include <stdint.h>
#include <math.h>

#define NN 10000
#define FF 128
#define PP 4
#define EE 160000
#define CC 512
#define HIDN 256
#define C4 (CC/4)
#define F4 (FF/4)
#define MB (NN*PP)
#define NG 1536              /* merged gate width */

// ---------------- scratch (static device memory; no allocations) ----------------
__device__ float g_deg[NN];
__device__ float g_dinv[NN];
__device__ float g_normself[NN];
__device__ int   g_counts[NN];
__device__ int   g_rowptr[NN + 1];
__device__ int   g_cursor[NN];
__device__ int   g_csrsrc[EE];
__device__ float g_csrnorm[EE];
__device__ float g_probs[PP];

__device__ float g_Xp[MB * FF];
__device__ float g_T[MB * CC];
__device__ float g_H[MB * CC];
__device__ float g_Z[MB * CC];
__device__ float g_Ht[MB * CC];
__device__ float g_G[MB * NG];        // merged gate pre-activations [Z|R|H]
__device__ float g_hid1[NN * HIDN];
__device__ float g_Mtmp[FF * CC];
__device__ float g_bvzr[2 * CC], g_bvh[CC];

__device__ __nv_bfloat16 g_Xsh[MB * FF], g_Xsl[MB * FF];
__device__ __nv_bfloat16 g_BAh[MB * CC], g_BAl[MB * CC];
__device__ __nv_bfloat16 g_BBh[MB * CC], g_BBl[MB * CC];
__device__ __nv_bfloat16 g_Hh[MB * CC],  g_Hl[MB * CC];
__device__ __nv_bfloat16 g_Rmh[MB * CC], g_Rml[MB * CC];
__device__ __nv_bfloat16 g_RAh[NN * CC], g_RAl[NN * CC];

__device__ __nv_bfloat16 g_W1h[CC * FF], g_W1l[CC * FF];
__device__ __nv_bfloat16 g_W2h[CC * CC], g_W2l[CC * CC];
__device__ __nv_bfloat16 g_W3h[CC * CC], g_W3l[CC * CC];
__device__ __nv_bfloat16 g_W4h[CC * CC], g_W4l[CC * CC];
__device__ __nv_bfloat16 g_W5h[CC * CC], g_W5l[CC * CC];
__device__ __nv_bfloat16 g_MGh[NG * FF], g_MGl[NG * FF];       // [Mz|Mr|Mh]^T
__device__ __nv_bfloat16 g_Lzr2h[2 * CC * CC], g_Lzr2l[2 * CC * CC];  // [Lz2|Lr2]^T
__device__ __nv_bfloat16 g_Lh2h[CC * CC], g_Lh2l[CC * CC];
__device__ __nv_bfloat16 g_L1th[HIDN * CC], g_L1tl[HIDN * CC];

__device__ __forceinline__ void split_bf(float x, __nv_bfloat16& h, __nv_bfloat16& l) {
    h = __float2bfloat16(x);
    l = __float2bfloat16(x - __bfloat162float(h));
}
__device__ __forceinline__ uint32_t pack_bf2(__nv_bfloat16 a, __nv_bfloat16 b) {
    __nv_bfloat162 t(a, b);
    return *(uint32_t*)&t;
}
__device__ __forceinline__ uint32_t split_pack(float a, float b) {
    __nv_bfloat16 h0, l0, h1, l1;
    split_bf(a, h0, l0); split_bf(b, h1, l1);
    return pack_bf2(h0, h1);
}
__device__ __forceinline__ uint32_t split_pack_lo(float a, float b) {
    __nv_bfloat16 h0, l0, h1, l1;
    split_bf(a, h0, l0); split_bf(b, h1, l1);
    return pack_bf2(l0, l1);
}

// ---------------- graph setup kernels ----------------
__global__ void init_node_arrays() {
    int i = blockIdx.x * blockDim.x + threadIdx.x;
    if (i < NN) { g_deg[i] = 0.0f; g_counts[i] = 0; g_cursor[i] = 0; }
}

__global__ void deg_edges_kernel(const int* __restrict__ ei, const float* __restrict__ ea) {
    int e = blockIdx.x * blockDim.x + threadIdx.x;
    if (e < EE) {
        int dst = ei[EE + e];
        atomicAdd(&g_deg[dst], ea[e]);
        atomicAdd(&g_counts[dst], 1);
    }
}

__global__ void deg_finalize_kernel() {
    int i = blockIdx.x * blockDim.x + threadIdx.x;
    if (i < NN) {
        float d = g_deg[i] + 1.0f;
        float di = (d > 0.0f) ? rsqrtf(d) : 0.0f;
        g_dinv[i] = di;
        g_normself[i] = di * di;
    }
}

__global__ void scan_kernel() {
    __shared__ int part[1024];
    const int per = 10;
    int t = threadIdx.x;
    int base = t * per;
    int loc[per];
    int s = 0;
#pragma unroll
    for (int i = 0; i < per; i++) {
        int idx = base + i;
        int v = (idx < NN) ? g_counts[idx] : 0;
        loc[i] = s; s += v;
    }
    part[t] = s;
    __syncthreads();
    for (int off = 1; off < 1024; off <<= 1) {
        int v = (t >= off) ? part[t - off] : 0;
        __syncthreads();
        part[t] += v;
        __syncthreads();
    }
    int offb = (t == 0) ? 0 : part[t - 1];
#pragma unroll
    for (int i = 0; i < per; i++) {
        int idx = base + i;
        if (idx < NN) g_rowptr[idx] = offb + loc[i];
    }
    if (t == 1023) g_rowptr[NN] = part[1023];
}

__global__ void scatter_kernel(const int* __restrict__ ei, const float* __restrict__ ea) {
    int e = blockIdx.x * blockDim.x + threadIdx.x;
    if (e < EE) {
        int src = ei[e];
        int dst = ei[EE + e];
        float nv = g_dinv[src] * ea[e] * g_dinv[dst];
        int pos = atomicAdd(&g_cursor[dst], 1);
        int slot = g_rowptr[dst] + pos;
        g_csrsrc[slot] = src;
        g_csrnorm[slot] = nv;
    }
}

__global__ void softmax4_kernel(const float* __restrict__ attn) {
    if (threadIdx.x == 0 && blockIdx.x == 0) {
        float m = attn[0];
        for (int p = 1; p < PP; p++) m = fmaxf(m, attn[p]);
        float s = 0.0f, e[PP];
        for (int p = 0; p < PP; p++) { e[p] = expf(attn[p] - m); s += e[p]; }
        for (int p = 0; p < PP; p++) g_probs[p] = e[p] / s;
    }
}

__global__ void wt_split_kernel(const float* __restrict__ W, int k0, int N, int Kb,
                                __nv_bfloat16* __restrict__ oh, __nv_bfloat16* __restrict__ ol) {
    int idx = blockIdx.x * blockDim.x + threadIdx.x;
    if (idx < N * Kb) {
        int n = idx / Kb;
        int k = idx - n * Kb;
        float v = W[(size_t)(k0 + k) * N + n];
        __nv_bfloat16 h, l;
        split_bf(v, h, l);
        oh[idx] = h; ol[idx] = l;
    }
}

__global__ void gatefold_kernel(const float* __restrict__ Wsm, const float* __restrict__ Lw,
                                float* __restrict__ M) {
    int idx = blockIdx.x * blockDim.x + threadIdx.x;
    if (idx < FF * CC) {
        int f = idx / CC, n = idx - f * CC;
        float s = 0.0f;
        for (int k = 0; k < CC; k++)
            s = fmaf(Wsm[(size_t)f * CC + k], Lw[(size_t)k * CC + n], s);
        M[idx] = s;
    }
}

__global__ void gate_bias_kernel(const float* __restrict__ Lw, const float* __restrict__ Lb,
                                 const float* __restrict__ bsmall, float* __restrict__ bv) {
    int n = blockIdx.x * blockDim.x + threadIdx.x;
    if (n < CC) {
        float s = Lb[n];
        for (int k = 0; k < CC; k++)
            s = fmaf(bsmall[k], Lw[(size_t)k * CC + n], s);
        bv[n] = s;
    }
}

// ---------------- bf16x3 tensor-core GEMM v4: BM=64, BN=256, cp.async ----------------
#define BM 64
#define BN 256
#define BKC 32
#define TSTR 40
#define A_PL (BM * TSTR)             /* 2560 el */
#define B_PL (BN * TSTR)             /* 10240 el */
#define STG  (2 * A_PL + 2 * B_PL)   /* 25600 el per stage */
#define SMEM_BYTES (2 * STG * 2)     /* 102400 B */

__device__ __forceinline__ void mma16816(float* c, const uint32_t* a, const uint32_t* b) {
    asm volatile(
        "mma.sync.aligned.m16n8k16.row.col.f32.bf16.bf16.f32 "
        "{%0,%1,%2,%3}, {%4,%5,%6,%7}, {%8,%9}, {%0,%1,%2,%3};"
        : "+f"(c[0]), "+f"(c[1]), "+f"(c[2]), "+f"(c[3])
        : "r"(a[0]), "r"(a[1]), "r"(a[2]), "r"(a[3]), "r"(b[0]), "r"(b[1]));
}

__device__ __forceinline__ void ldsm_x4(const void* p, uint32_t* r) {
    uint32_t addr = (uint32_t)__cvta_generic_to_shared(p);
    asm volatile("ldmatrix.sync.aligned.m8n8.x4.shared.b16 {%0,%1,%2,%3}, [%4];"
        : "=r"(r[0]), "=r"(r[1]), "=r"(r[2]), "=r"(r[3]) : "r"(addr));
}

__device__ __forceinline__ void cpa16(void* dst, const void* src, int sz) {
    uint32_t d = (uint32_t)__cvta_generic_to_shared(dst);
    asm volatile("cp.async.cg.shared.global [%0], [%1], 16, %2;"
                 :: "r"(d), "l"(src), "r"(sz));
}
__device__ __forceinline__ void cpa_commit() {
    asm volatile("cp.async.commit_group;");
}
template <int NW>
__device__ __forceinline__ void cpa_wait() {
    asm volatile("cp.async.wait_group %0;" :: "n"(NW));
}

// EPI: 0 store fp32 (ld=N); 1 split(acc+bias)->planes (ld=N);
//      4 relu(acc+bias)->fp32 (ld=N);
//      7 merged ZR: old=OldP strided; col<CC -> sigmoid->Cm fp32 (ld=CC);
//                   col>=CC -> sigmoid*Hp -> oh/ol planes (ld=CC)
//      8 tanh(OldP_strided + acc + bias) -> Cm fp32 (ld=N)
template <int EPI>
__global__ void __launch_bounds__(256, 2) bf3_gemm(
    const __nv_bfloat16* __restrict__ Ah, const __nv_bfloat16* __restrict__ Al,
    const __nv_bfloat16* __restrict__ Bh, const __nv_bfloat16* __restrict__ Bl,
    float* __restrict__ Cm, const float* __restrict__ bias,
    const float* __restrict__ Hp,
    const float* __restrict__ OldP, int oldLd,
    __nv_bfloat16* __restrict__ oh, __nv_bfloat16* __restrict__ ol,
    int M, int N, int K) {
    extern __shared__ __align__(16) __nv_bfloat16 sm[];

    int tid = threadIdx.x;
    int m0 = blockIdx.y * BM;
    int n0 = blockIdx.x * BN;
    int warp = tid >> 5, lane = tid & 31;
    int wm = warp >> 2, wn = warp & 3;   // 2M x 4N warps; warp tile 32x64
    int g = lane >> 2, tg = lane & 3;

    float c[2][8][4];
#pragma unroll
    for (int mt = 0; mt < 2; mt++)
#pragma unroll
        for (int nt = 0; nt < 8; nt++)
#pragma unroll
            for (int i = 0; i < 4; i++) c[mt][nt][i] = 0.0f;

    auto load_stage = [&](int st, int k0) {
        __nv_bfloat16* Ahs = sm + st * STG;
        __nv_bfloat16* Als = Ahs + A_PL;
        __nv_bfloat16* Bhs = Als + A_PL;
        __nv_bfloat16* Bls = Bhs + B_PL;
        // A: 64 rows x 4 q = 256 uint4 per plane; 1 per thread
        {
            int row = tid >> 2, q = tid & 3;
            int m = m0 + row;
            int msz = (m < M) ? 16 : 0;
            size_t asrc = (size_t)(m < M ? m : 0) * K + k0 + q * 8;
            cpa16(Ahs + row * TSTR + q * 8, Ah + asrc, msz);
            cpa16(Als + row * TSTR + q * 8, Al + asrc, msz);
        }
        // B: 256 rows x 4 q = 1024 uint4 per plane; 4 per thread
#pragma unroll
        for (int i = 0; i < 4; i++) {
            int idx = tid + i * 256;
            int row = idx >> 2, q = idx & 3;
            size_t bsrc = (size_t)(n0 + row) * K + k0 + q * 8;
            cpa16(Bhs + row * TSTR + q * 8, Bh + bsrc, 16);
            cpa16(Bls + row * TSTR + q * 8, Bl + bsrc, 16);
        }
        cpa_commit();
    };

    auto compute = [&](int st) {
        const __nv_bfloat16* Ahs = sm + st * STG;
        const __nv_bfloat16* Als = Ahs + A_PL;
        const __nv_bfloat16* Bhs = Als + A_PL;
        const __nv_bfloat16* Bls = Bhs + B_PL;
#pragma unroll
        for (int ks = 0; ks < 2; ks++) {
            uint32_t ahf[2][4], alf[2][4];
            int arow = lane & 15;
            int acol = ks * 16 + (lane >> 4) * 8;
#pragma unroll
            for (int mt = 0; mt < 2; mt++) {
                int r = wm * 32 + mt * 16 + arow;
                ldsm_x4(Ahs + r * TSTR + acol, ahf[mt]);
                ldsm_x4(Als + r * TSTR + acol, alf[mt]);
            }
            uint32_t bf[8][2];
            int bm_ = lane >> 3;
            int brow_in = lane & 7;
            int bro = (bm_ >> 1) * 8 + brow_in;
            int bco = ks * 16 + (bm_ & 1) * 8;
#pragma unroll
            for (int ntp = 0; ntp < 4; ntp++) {
                int nr = wn * 64 + ntp * 16 + bro;
                uint32_t t4[4];
                ldsm_x4(Bhs + nr * TSTR + bco, t4);
                bf[ntp * 2][0] = t4[0]; bf[ntp * 2][1] = t4[1];
                bf[ntp * 2 + 1][0] = t4[2]; bf[ntp * 2 + 1][1] = t4[3];
            }
#pragma unroll
            for (int mt = 0; mt < 2; mt++)
#pragma unroll
                for (int nt = 0; nt < 8; nt++) {
                    mma16816(c[mt][nt], ahf[mt], bf[nt]);  // hi*hi
                    mma16816(c[mt][nt], alf[mt], bf[nt]);  // lo*hi
                }
#pragma unroll
            for (int ntp = 0; ntp < 4; ntp++) {
                int nr = wn * 64 + ntp * 16 + bro;
                uint32_t t4[4];
                ldsm_x4(Bls + nr * TSTR + bco, t4);
                bf[ntp * 2][0] = t4[0]; bf[ntp * 2][1] = t4[1];
                bf[ntp * 2 + 1][0] = t4[2]; bf[ntp * 2 + 1][1] = t4[3];
            }
#pragma unroll
            for (int mt = 0; mt < 2; mt++)
#pragma unroll
                for (int nt = 0; nt < 8; nt++)
                    mma16816(c[mt][nt], ahf[mt], bf[nt]);  // hi*lo
        }
    };

    int nchunks = K / BKC;
    load_stage(0, 0);
    for (int ch = 0; ch < nchunks; ch++) {
        int st = ch & 1;
        if (ch + 1 < nchunks) {
            load_stage(st ^ 1, (ch + 1) * BKC);
            cpa_wait<1>();
        } else {
            cpa_wait<0>();
        }
        __syncthreads();
        compute(st);
        __syncthreads();
    }

#pragma unroll
    for (int mt = 0; mt < 2; mt++) {
#pragma unroll
        for (int nt = 0; nt < 8; nt++) {
            int col = n0 + wn * 64 + nt * 8 + tg * 2;
            float bv0 = 0.f, bv1 = 0.f;
            if (EPI != 0) { bv0 = __ldg(&bias[col]); bv1 = __ldg(&bias[col + 1]); }
#pragma unroll
            for (int half = 0; half < 2; half++) {
                int row = m0 + wm * 32 + mt * 16 + g + half * 8;
                if (row >= M) continue;
                float v0 = c[mt][nt][half * 2 + 0];
                float v1 = c[mt][nt][half * 2 + 1];
                if (EPI == 0) {
                    size_t off = (size_t)row * N + col;
                    *(float2*)(Cm + off) = make_float2(v0, v1);
                } else if (EPI == 1) {
                    size_t off = (size_t)row * N + col;
                    float a0 = v0 + bv0, a1 = v1 + bv1;
                    *(uint32_t*)(oh + off) = split_pack(a0, a1);
                    *(uint32_t*)(ol + off) = split_pack_lo(a0, a1);
                } else if (EPI == 4) {
                    size_t off = (size_t)row * N + col;
                    *(float2*)(Cm + off) = make_float2(fmaxf(v0 + bv0, 0.0f),
                                                       fmaxf(v1 + bv1, 0.0f));
                } else if (EPI == 7) {
                    float2 old = *(const float2*)(OldP + (size_t)row * oldLd + col);
                    float a0 = old.x + v0 + bv0, a1 = old.y + v1 + bv1;
                    float s0 = 1.0f / (1.0f + expf(-a0));
                    float s1 = 1.0f / (1.0f + expf(-a1));
                    if (col < CC) {
                        size_t off = (size_t)row * CC + col;
                        *(float2*)(Cm + off) = make_float2(s0, s1);
                    } else {
                        int c2 = col - CC;
                        size_t off = (size_t)row * CC + c2;
                        float2 hv = *(const float2*)(Hp + off);
                        float m0v = s0 * hv.x, m1v = s1 * hv.y;
                        *(uint32_t*)(oh + off) = split_pack(m0v, m1v);
                        *(uint32_t*)(ol + off) = split_pack_lo(m0v, m1v);
                    }
                } else if (EPI == 8) {
                    float2 old = *(const float2*)(OldP + (size_t)row * oldLd + col);
                    size_t off = (size_t)row * N + col;
                    *(float2*)(Cm + off) = make_float2(tanhf(old.x + v0 + bv0),
                                                       tanhf(old.y + v1 + bv1));
                }
            }
        }
    }
}

// ---------------- batched GCN propagation ----------------
template <bool WF32>
__global__ void __launch_bounds__(128) prop_split_kernel(
    const float* __restrict__ T, const float* __restrict__ bias,
    float* __restrict__ outf,
    __nv_bfloat16* __restrict__ oh, __nv_bfloat16* __restrict__ ol) {
    int r = blockIdx.x;
    int p = r / NN;
    int i = r - p * NN;
    int t = threadIdx.x;
    const float4* T4 = (const float4*)T;
    float4 b = ((const float4*)bias)[t];
    float sn = g_normself[i];
    float4 v = T4[(size_t)r * C4 + t];
    float4 acc = make_float4(b.x + sn * v.x, b.y + sn * v.y, b.z + sn * v.z, b.w + sn * v.w);
    int beg = g_rowptr[i];
    int end = g_rowptr[i + 1];
    int base = p * NN;
    for (int e = beg; e < end; e++) {
        int s = g_csrsrc[e];
        float w = g_csrnorm[e];
        float4 u = T4[(size_t)(base + s) * C4 + t];
        acc.x = fmaf(w, u.x, acc.x);
        acc.y = fmaf(w, u.y, acc.y);
        acc.z = fmaf(w, u.z, acc.z);
        acc.w = fmaf(w, u.w, acc.w);
    }
    if (WF32) ((float4*)outf)[(size_t)r * C4 + t] = acc;
    size_t off = (size_t)r * CC + t * 4;
    *(uint32_t*)(oh + off) = split_pack(acc.x, acc.y);
    *(uint32_t*)(oh + off + 2) = split_pack(acc.z, acc.w);
    *(uint32_t*)(ol + off) = split_pack_lo(acc.x, acc.y);
    *(uint32_t*)(ol + off + 2) = split_pack_lo(acc.z, acc.w);
}

__global__ void __launch_bounds__(128) prop128_kernel(
    const float* __restrict__ Xp,
    __nv_bfloat16* __restrict__ oh, __nv_bfloat16* __restrict__ ol) {
    int r = blockIdx.x * 4 + (threadIdx.x >> 5);
    int t = threadIdx.x & 31;
    if (r >= MB) return;
    int p = r / NN;
    int i = r - p * NN;
    const float4* X4 = (const float4*)Xp;
    float sn = g_normself[i];
    float4 v = X4[(size_t)r * F4 + t];
    float4 acc = make_float4(sn * v.x, sn * v.y, sn * v.z, sn * v.w);
    int beg = g_rowptr[i];
    int end = g_rowptr[i + 1];
    int base = p * NN;
    for (int e = beg; e < end; e++) {
        int s = g_csrsrc[e];
        float w = g_csrnorm[e];
        float4 u = X4[(size_t)(base + s) * F4 + t];
        acc.x = fmaf(w, u.x, acc.x);
        acc.y = fmaf(w, u.y, acc.y);
        acc.z = fmaf(w, u.z, acc.z);
        acc.w = fmaf(w, u.w, acc.w);
    }
    size_t off = (size_t)r * FF + t * 4;
    *(uint32_t*)(oh + off) = split_pack(acc.x, acc.y);
    *(uint32_t*)(oh + off + 2) = split_pack(acc.z, acc.w);
    *(uint32_t*)(ol + off) = split_pack_lo(acc.x, acc.y);
    *(uint32_t*)(ol + off + 2) = split_pack_lo(acc.z, acc.w);
}

// ---------------- elementwise kernels ----------------
__global__ void extract_all_kernel(const float* __restrict__ x, float* __restrict__ Xp) {
    int idx = blockIdx.x * blockDim.x + threadIdx.x;
    if (idx < NN * FF) {
        float4 v = ((const float4*)x)[idx];
        Xp[idx] = v.x;
        Xp[NN * FF + idx] = v.y;
        Xp[2 * NN * FF + idx] = v.z;
        Xp[3 * NN * FF + idx] = v.w;
    }
}

__global__ void gru_reduce_kernel(const float* __restrict__ Z, const float* __restrict__ H,
                                  const float* __restrict__ Ht, float* __restrict__ out,
                                  __nv_bfloat16* __restrict__ oh, __nv_bfloat16* __restrict__ ol) {
    int idx = blockIdx.x * blockDim.x + threadIdx.x;
    if (idx >= NN * C4) return;
    int i = idx >> 7;
    int t = idx & 127;
    float4 acc = make_float4(0.f, 0.f, 0.f, 0.f);
#pragma unroll
    for (int p = 0; p < PP; p++) {
        size_t o4 = (size_t)(p * NN + i) * C4 + t;
        float4 z = ((const float4*)Z)[o4];
        float4 h = ((const float4*)H)[o4];
        float4 ht = ((const float4*)Ht)[o4];
        float pr = g_probs[p];
        acc.x += pr * (z.x * h.x + (1.0f - z.x) * ht.x);
        acc.y += pr * (z.y * h.y + (1.0f - z.y) * ht.y);
        acc.z += pr * (z.z * h.z + (1.0f - z.z) * ht.z);
        acc.w += pr * (z.w * h.w + (1.0f - z.w) * ht.w);
    }
    ((float4*)(out + NN))[idx] = acc;
    float4 v = make_float4(fmaxf(acc.x, 0.f), fmaxf(acc.y, 0.f),
                           fmaxf(acc.z, 0.f), fmaxf(acc.w, 0.f));
    size_t off = (size_t)idx * 4;
    *(uint32_t*)(oh + off) = split_pack(v.x, v.y);
    *(uint32_t*)(oh + off + 2) = split_pack(v.z, v.w);
    *(uint32_t*)(ol + off) = split_pack_lo(v.x, v.y);
    *(uint32_t*)(ol + off + 2) = split_pack_lo(v.z, v.w);
}

__global__ void lin2_kernel(const float* __restrict__ hid, const float* __restrict__ w,
                            const float* __restrict__ b, float* __restrict__ out) {
    int n = blockIdx.x * 8 + (threadIdx.x >> 5);
    int lane = threadIdx.x & 31;
    float s = 0.0f;
    for (int k = lane; k < HIDN; k += 32) s = fmaf(hid[(size_t)n * HIDN + k], w[k], s);
#pragma unroll
    for (int off = 16; off; off >>= 1) s += __shfl_down_sync(0xffffffffu, s, off);
    if (lane == 0) out[n] = s + b[0];
}

// ---------------- host orchestration ----------------
#define GP(sym) ({ void* _p; cudaGetSymbolAddress(&_p, sym); (__nv_bfloat16*)_p; })
#define GPF(sym) ({ void* _p; cudaGetSymbolAddress(&_p, sym); (float*)_p; })

struct GemmArgs {
    const __nv_bfloat16 *Ah, *Al, *Bh, *Bl;
    float* Cm;
    const float* bias;
    const float* Hp;
    const float* OldP;
    int oldLd;
    __nv_bfloat16 *oh, *ol;
    int M, N, K;
};

template <int EPI>
static inline void launch_gemm(const GemmArgs& a) {
    dim3 grid(a.N / BN, (a.M + BM - 1) / BM);
    bf3_gemm<EPI><<<grid, 256, SMEM_BYTES>>>(a.Ah, a.Al, a.Bh, a.Bl, a.Cm, a.bias,
                                             a.Hp, a.OldP, a.oldLd, a.oh, a.ol,
                                             a.M, a.N, a.K);
}

extern "C" void kernel_launch(void* const* d_in, const int* in_sizes, int n_in,
                              void* d_out, int out_size) {
    const float* x     = (const float*)d_in[0];
    const int*   ei    = (const int*)d_in[1];
    const float* ea    = (const float*)d_in[2];
    const float* W1    = (const float*)d_in[3];
    const float* b1    = (const float*)d_in[4];
    const float* W2    = (const float*)d_in[5];
    const float* b2    = (const float*)d_in[6];
    const float* W3    = (const float*)d_in[7];
    const float* b3    = (const float*)d_in[8];
    const float* W4    = (const float*)d_in[9];
    const float* b4    = (const float*)d_in[10];
    const float* W5    = (const float*)d_in[11];
    const float* b5    = (const float*)d_in[12];
    const float* Wz    = (const float*)d_in[13];
    const float* bz    = (const float*)d_in[14];
    const float* Lz_w  = (const float*)d_in[15];
    const float* Lz_b  = (const float*)d_in[16];
    const float* Wr    = (const float*)d_in[17];
    const float* br    = (const float*)d_in[18];
    const float* Lr_w  = (const float*)d_in[19];
    const float* Lr_b  = (const float*)d_in[20];
    const float* Wh    = (const float*)d_in[21];
    const float* bh    = (const float*)d_in[22];
    const float* Lh_w  = (const float*)d_in[23];
    const float* Lh_b  = (const float*)d_in[24];
    const float* attn  = (const float*)d_in[25];
    const float* lin1w = (const float*)d_in[26];
    const float* lin1b = (const float*)d_in[27];
    const float* lin2w = (const float*)d_in[28];
    const float* lin2b = (const float*)d_in[29];
    float* out = (float*)d_out;

    static bool attr_done = false;
    if (!attr_done) {
        cudaFuncSetAttribute(bf3_gemm<0>, cudaFuncAttributeMaxDynamicSharedMemorySize, SMEM_BYTES);
        cudaFuncSetAttribute(bf3_gemm<1>, cudaFuncAttributeMaxDynamicSharedMemorySize, SMEM_BYTES);
        cudaFuncSetAttribute(bf3_gemm<4>, cudaFuncAttributeMaxDynamicSharedMemorySize, SMEM_BYTES);
        cudaFuncSetAttribute(bf3_gemm<7>, cudaFuncAttributeMaxDynamicSharedMemorySize, SMEM_BYTES);
        cudaFuncSetAttribute(bf3_gemm<8>, cudaFuncAttributeMaxDynamicSharedMemorySize, SMEM_BYTES);
        attr_done = true;
    }

    float* pXp   = GPF(g_Xp);
    float* pT    = GPF(g_T);
    float* pH    = GPF(g_H);
    float* pZ    = GPF(g_Z);
    float* pHt   = GPF(g_Ht);
    float* pG    = GPF(g_G);
    float* phid1 = GPF(g_hid1);
    float* pMtmp = GPF(g_Mtmp);
    float* pbvzr = GPF(g_bvzr);
    float* pbvh  = GPF(g_bvh);

    __nv_bfloat16 *pXsh = GP(g_Xsh), *pXsl = GP(g_Xsl);
    __nv_bfloat16 *pBAh = GP(g_BAh), *pBAl = GP(g_BAl);
    __nv_bfloat16 *pBBh = GP(g_BBh), *pBBl = GP(g_BBl);
    __nv_bfloat16 *pHh = GP(g_Hh), *pHl = GP(g_Hl);
    __nv_bfloat16 *pRmh = GP(g_Rmh), *pRml = GP(g_Rml);
    __nv_bfloat16 *pRAh = GP(g_RAh), *pRAl = GP(g_RAl);

    __nv_bfloat16 *pW1h = GP(g_W1h), *pW1l = GP(g_W1l);
    __nv_bfloat16 *pW2h = GP(g_W2h), *pW2l = GP(g_W2l);
    __nv_bfloat16 *pW3h = GP(g_W3h), *pW3l = GP(g_W3l);
    __nv_bfloat16 *pW4h = GP(g_W4h), *pW4l = GP(g_W4l);
    __nv_bfloat16 *pW5h = GP(g_W5h), *pW5l = GP(g_W5l);
    __nv_bfloat16 *pMGh = GP(g_MGh), *pMGl = GP(g_MGl);
    __nv_bfloat16 *pLzr2h = GP(g_Lzr2h), *pLzr2l = GP(g_Lzr2l);
    __nv_bfloat16 *pLh2h = GP(g_Lh2h), *pLh2l = GP(g_Lh2l);
    __nv_bfloat16 *pL1th = GP(g_L1th), *pL1tl = GP(g_L1tl);

    const int gE  = (EE + 255) / 256;
    const int gN  = (NN + 255) / 256;
    const int gNC4 = (NN * C4 + 255) / 256;
    const int gNF = (NN * FF + 255) / 256;
    const int gW512 = (CC * CC + 255) / 256;
    const int gW128 = (CC * FF + 255) / 256;
    const int gWL1 = (HIDN * CC + 255) / 256;

    init_node_arrays<<<gN, 256>>>();
    deg_edges_kernel<<<gE, 256>>>(ei, ea);
    deg_finalize_kernel<<<gN, 256>>>();
    scan_kernel<<<1, 1024>>>();
    scatter_kernel<<<gE, 256>>>(ei, ea);
    softmax4_kernel<<<1, 32>>>(attn);

    wt_split_kernel<<<gW128, 256>>>(W1, 0, CC, FF, pW1h, pW1l);
    wt_split_kernel<<<gW512, 256>>>(W2, 0, CC, CC, pW2h, pW2l);
    wt_split_kernel<<<gW512, 256>>>(W3, 0, CC, CC, pW3h, pW3l);
    wt_split_kernel<<<gW512, 256>>>(W4, 0, CC, CC, pW4h, pW4l);
    wt_split_kernel<<<gW512, 256>>>(W5, 0, CC, CC, pW5h, pW5l);
    // [Lz2|Lr2]^T concat
    wt_split_kernel<<<gW512, 256>>>(Lz_w, CC, CC, CC, pLzr2h, pLzr2l);
    wt_split_kernel<<<gW512, 256>>>(Lr_w, CC, CC, CC, pLzr2h + (size_t)CC * CC,
                                    pLzr2l + (size_t)CC * CC);
    wt_split_kernel<<<gW512, 256>>>(Lh_w, CC, CC, CC, pLh2h, pLh2l);
    wt_split_kernel<<<gWL1, 256>>>(lin1w, 0, HIDN, CC, pL1th, pL1tl);

    // merged gate weight [Mz|Mr|Mh]^T and biases
    gatefold_kernel<<<gW128, 256>>>(Wz, Lz_w, pMtmp);
    wt_split_kernel<<<gW128, 256>>>(pMtmp, 0, CC, FF, pMGh, pMGl);
    gatefold_kernel<<<gW128, 256>>>(Wr, Lr_w, pMtmp);
    wt_split_kernel<<<gW128, 256>>>(pMtmp, 0, CC, FF, pMGh + (size_t)CC * FF,
                                    pMGl + (size_t)CC * FF);
    gatefold_kernel<<<gW128, 256>>>(Wh, Lh_w, pMtmp);
    wt_split_kernel<<<gW128, 256>>>(pMtmp, 0, CC, FF, pMGh + (size_t)2 * CC * FF,
                                    pMGl + (size_t)2 * CC * FF);
    gate_bias_kernel<<<2, 256>>>(Lz_w, Lz_b, bz, pbvzr);
    gate_bias_kernel<<<2, 256>>>(Lr_w, Lr_b, br, pbvzr + CC);
    gate_bias_kernel<<<2, 256>>>(Lh_w, Lh_b, bh, pbvh);

    // ---- batched across all 4 timesteps (M = 40000) ----
    extract_all_kernel<<<gNF, 256>>>(x, pXp);
    prop128_kernel<<<(MB + 3) / 4, 128>>>(pXp, pXsh, pXsl);

    GemmArgs a{};
    // merged gate pre-activations: G = Xs @ [Mz|Mr|Mh]
    a = {pXsh, pXsl, pMGh, pMGl, pG, nullptr, nullptr, nullptr, 0,
         nullptr, nullptr, MB, NG, FF};
    launch_gemm<0>(a);

    // h1 = Xs@W1 + b1 (split out)
    a = {pXsh, pXsl, pW1h, pW1l, nullptr, b1, nullptr, nullptr, 0,
         pBAh, pBAl, MB, CC, FF};
    launch_gemm<1>(a);
    // layers 2..5
    a = {pBAh, pBAl, pW2h, pW2l, pT, nullptr, nullptr, nullptr, 0,
         nullptr, nullptr, MB, CC, CC};
    launch_gemm<0>(a);
    prop_split_kernel<false><<<MB, 128>>>(pT, b2, nullptr, pBBh, pBBl);
    a.Ah = pBBh; a.Al = pBBl; a.Bh = pW3h; a.Bl = pW3l;
    launch_gemm<0>(a);
    prop_split_kernel<false><<<MB, 128>>>(pT, b3, nullptr, pBAh, pBAl);
    a.Ah = pBAh; a.Al = pBAl; a.Bh = pW4h; a.Bl = pW4l;
    launch_gemm<0>(a);
    prop_split_kernel<false><<<MB, 128>>>(pT, b4, nullptr, pBBh, pBBl);
    a.Ah = pBBh; a.Al = pBBl; a.Bh = pW5h; a.Bl = pW5l;
    launch_gemm<0>(a);
    prop_split_kernel<true><<<MB, 128>>>(pT, b5, pH, pHh, pHl);

    // merged ZR: [Z|R] = sigmoid(G[:,0:1024] + H@[Lz2|Lr2] + bvzr)
    //   cols<512 -> Z fp32; cols>=512 -> Rm = R*H planes
    a = {pHh, pHl, pLzr2h, pLzr2l, pZ, pbvzr, pH, pG, NG,
         pRmh, pRml, MB, 2 * CC, CC};
    launch_gemm<7>(a);

    // Ht = tanh(G[:,1024:1536] + Rm@Lh2 + bvh)
    a = {pRmh, pRml, pLh2h, pLh2l, pHt, pbvh, nullptr, pG + 2 * CC, NG,
         nullptr, nullptr, MB, CC, CC};
    launch_gemm<8>(a);

    gru_reduce_kernel<<<gNC4, 256>>>(pZ, pH, pHt, out, pRAh, pRAl);

    a = {pRAh, pRAl, pL1th, pL1tl, phid1, lin1b, nullptr, nullptr, 0,
         nullptr, nullptr, NN, HIDN, CC};
    launch_gemm<4>(a);
    lin2_kernel<<<(NN + 7) / 8, 256>>>(phid1, lin2w, lin2b, out);
}

// round 10
// speedup vs baseline: 1.0698x; 1.0698x over previous
#include <cuda_runtime.h>
#include <cuda_bf16.h>
#include <stdint.h>
#include <math.h>

#define NN 10000
#define FF 128
#define PP 4
#define EE 160000
#define CC 512
#define HIDN 256
#define C4 (CC/4)
#define F4 (FF/4)
#define MB (NN*PP)
#define NG 1536              /* merged gate width */

// ---------------- scratch (static device memory; no allocations) ----------------
__device__ float g_deg[NN];
__device__ float g_dinv[NN];
__device__ float g_normself[NN];
__device__ int   g_counts[NN];
__device__ int   g_rowptr[NN + 1];
__device__ int   g_cursor[NN];
__device__ int   g_csrsrc[EE];
__device__ float g_csrnorm[EE];
__device__ float g_probs[PP];

__device__ float g_Xp[MB * FF];
__device__ float g_T[MB * CC];
__device__ float g_H[MB * CC];
__device__ float g_Z[MB * CC];
__device__ float g_Ht[MB * CC];
__device__ float g_G[MB * NG];        // merged gate pre-activations [Z|R|H]
__device__ float g_hid1[NN * HIDN];
__device__ float g_Mtmp[FF * CC];
__device__ float g_bvzr[2 * CC], g_bvh[CC];

__device__ __nv_bfloat16 g_Xsh[MB * FF], g_Xsl[MB * FF];
__device__ __nv_bfloat16 g_BAh[MB * CC], g_BAl[MB * CC];
__device__ __nv_bfloat16 g_BBh[MB * CC], g_BBl[MB * CC];
__device__ __nv_bfloat16 g_Hh[MB * CC],  g_Hl[MB * CC];
__device__ __nv_bfloat16 g_Rmh[MB * CC], g_Rml[MB * CC];
__device__ __nv_bfloat16 g_RAh[NN * CC], g_RAl[NN * CC];

__device__ __nv_bfloat16 g_W1h[CC * FF], g_W1l[CC * FF];
__device__ __nv_bfloat16 g_W2h[CC * CC], g_W2l[CC * CC];
__device__ __nv_bfloat16 g_W3h[CC * CC], g_W3l[CC * CC];
__device__ __nv_bfloat16 g_W4h[CC * CC], g_W4l[CC * CC];
__device__ __nv_bfloat16 g_W5h[CC * CC], g_W5l[CC * CC];
__device__ __nv_bfloat16 g_MGh[NG * FF], g_MGl[NG * FF];       // [Mz|Mr|Mh]^T
__device__ __nv_bfloat16 g_Lzr2h[2 * CC * CC], g_Lzr2l[2 * CC * CC];  // [Lz2|Lr2]^T
__device__ __nv_bfloat16 g_Lh2h[CC * CC], g_Lh2l[CC * CC];
__device__ __nv_bfloat16 g_L1th[HIDN * CC], g_L1tl[HIDN * CC];

__device__ __forceinline__ void split_bf(float x, __nv_bfloat16& h, __nv_bfloat16& l) {
    h = __float2bfloat16(x);
    l = __float2bfloat16(x - __bfloat162float(h));
}
__device__ __forceinline__ uint32_t pack_bf2(__nv_bfloat16 a, __nv_bfloat16 b) {
    __nv_bfloat162 t(a, b);
    return *(uint32_t*)&t;
}
__device__ __forceinline__ uint32_t split_pack(float a, float b) {
    __nv_bfloat16 h0, l0, h1, l1;
    split_bf(a, h0, l0); split_bf(b, h1, l1);
    return pack_bf2(h0, h1);
}
__device__ __forceinline__ uint32_t split_pack_lo(float a, float b) {
    __nv_bfloat16 h0, l0, h1, l1;
    split_bf(a, h0, l0); split_bf(b, h1, l1);
    return pack_bf2(l0, l1);
}

// ---------------- graph setup kernels ----------------
__global__ void init_node_arrays() {
    int i = blockIdx.x * blockDim.x + threadIdx.x;
    if (i < NN) { g_deg[i] = 0.0f; g_counts[i] = 0; g_cursor[i] = 0; }
}

__global__ void deg_edges_kernel(const int* __restrict__ ei, const float* __restrict__ ea) {
    int e = blockIdx.x * blockDim.x + threadIdx.x;
    if (e < EE) {
        int dst = ei[EE + e];
        atomicAdd(&g_deg[dst], ea[e]);
        atomicAdd(&g_counts[dst], 1);
    }
}

__global__ void deg_finalize_kernel() {
    int i = blockIdx.x * blockDim.x + threadIdx.x;
    if (i < NN) {
        float d = g_deg[i] + 1.0f;
        float di = (d > 0.0f) ? rsqrtf(d) : 0.0f;
        g_dinv[i] = di;
        g_normself[i] = di * di;
    }
}

__global__ void scan_kernel() {
    __shared__ int part[1024];
    const int per = 10;
    int t = threadIdx.x;
    int base = t * per;
    int loc[per];
    int s = 0;
#pragma unroll
    for (int i = 0; i < per; i++) {
        int idx = base + i;
        int v = (idx < NN) ? g_counts[idx] : 0;
        loc[i] = s; s += v;
    }
    part[t] = s;
    __syncthreads();
    for (int off = 1; off < 1024; off <<= 1) {
        int v = (t >= off) ? part[t - off] : 0;
        __syncthreads();
        part[t] += v;
        __syncthreads();
    }
    int offb = (t == 0) ? 0 : part[t - 1];
#pragma unroll
    for (int i = 0; i < per; i++) {
        int idx = base + i;
        if (idx < NN) g_rowptr[idx] = offb + loc[i];
    }
    if (t == 1023) g_rowptr[NN] = part[1023];
}

__global__ void scatter_kernel(const int* __restrict__ ei, const float* __restrict__ ea) {
    int e = blockIdx.x * blockDim.x + threadIdx.x;
    if (e < EE) {
        int src = ei[e];
        int dst = ei[EE + e];
        float nv = g_dinv[src] * ea[e] * g_dinv[dst];
        int pos = atomicAdd(&g_cursor[dst], 1);
        int slot = g_rowptr[dst] + pos;
        g_csrsrc[slot] = src;
        g_csrnorm[slot] = nv;
    }
}

__global__ void softmax4_kernel(const float* __restrict__ attn) {
    if (threadIdx.x == 0 && blockIdx.x == 0) {
        float m = attn[0];
        for (int p = 1; p < PP; p++) m = fmaxf(m, attn[p]);
        float s = 0.0f, e[PP];
        for (int p = 0; p < PP; p++) { e[p] = expf(attn[p] - m); s += e[p]; }
        for (int p = 0; p < PP; p++) g_probs[p] = e[p] / s;
    }
}

__global__ void wt_split_kernel(const float* __restrict__ W, int k0, int N, int Kb,
                                __nv_bfloat16* __restrict__ oh, __nv_bfloat16* __restrict__ ol) {
    int idx = blockIdx.x * blockDim.x + threadIdx.x;
    if (idx < N * Kb) {
        int n = idx / Kb;
        int k = idx - n * Kb;
        float v = W[(size_t)(k0 + k) * N + n];
        __nv_bfloat16 h, l;
        split_bf(v, h, l);
        oh[idx] = h; ol[idx] = l;
    }
}

__global__ void gatefold_kernel(const float* __restrict__ Wsm, const float* __restrict__ Lw,
                                float* __restrict__ M) {
    int idx = blockIdx.x * blockDim.x + threadIdx.x;
    if (idx < FF * CC) {
        int f = idx / CC, n = idx - f * CC;
        float s = 0.0f;
        for (int k = 0; k < CC; k++)
            s = fmaf(Wsm[(size_t)f * CC + k], Lw[(size_t)k * CC + n], s);
        M[idx] = s;
    }
}

__global__ void gate_bias_kernel(const float* __restrict__ Lw, const float* __restrict__ Lb,
                                 const float* __restrict__ bsmall, float* __restrict__ bv) {
    int n = blockIdx.x * blockDim.x + threadIdx.x;
    if (n < CC) {
        float s = Lb[n];
        for (int k = 0; k < CC; k++)
            s = fmaf(bsmall[k], Lw[(size_t)k * CC + n], s);
        bv[n] = s;
    }
}

// ---------------- bf16x3 tensor-core GEMM: BM=128, BN=128, cp.async ----------------
#define BM 128
#define BN 128
#define BKC 32
#define TSTR 40
#define PL_SZ (128 * TSTR)           /* 5120 el per plane */
#define STG  (4 * PL_SZ)             /* Ah,Al,Bh,Bl */
#define SMEM_BYTES (2 * STG * 2)     /* 81920 B */

__device__ __forceinline__ void mma16816(float* c, const uint32_t* a, const uint32_t* b) {
    asm volatile(
        "mma.sync.aligned.m16n8k16.row.col.f32.bf16.bf16.f32 "
        "{%0,%1,%2,%3}, {%4,%5,%6,%7}, {%8,%9}, {%0,%1,%2,%3};"
        : "+f"(c[0]), "+f"(c[1]), "+f"(c[2]), "+f"(c[3])
        : "r"(a[0]), "r"(a[1]), "r"(a[2]), "r"(a[3]), "r"(b[0]), "r"(b[1]));
}

__device__ __forceinline__ void ldsm_x4(const void* p, uint32_t* r) {
    uint32_t addr = (uint32_t)__cvta_generic_to_shared(p);
    asm volatile("ldmatrix.sync.aligned.m8n8.x4.shared.b16 {%0,%1,%2,%3}, [%4];"
        : "=r"(r[0]), "=r"(r[1]), "=r"(r[2]), "=r"(r[3]) : "r"(addr));
}

__device__ __forceinline__ void cpa16(void* dst, const void* src, int sz) {
    uint32_t d = (uint32_t)__cvta_generic_to_shared(dst);
    asm volatile("cp.async.cg.shared.global [%0], [%1], 16, %2;"
                 :: "r"(d), "l"(src), "r"(sz));
}
__device__ __forceinline__ void cpa_commit() {
    asm volatile("cp.async.commit_group;");
}
template <int NW>
__device__ __forceinline__ void cpa_wait() {
    asm volatile("cp.async.wait_group %0;" :: "n"(NW));
}

// EPI: 0 store fp32 (ld=N); 1 split(acc+bias)->planes (ld=N);
//      4 relu(acc+bias)->fp32 (ld=N);
//      7 merged ZR: old=OldP strided; col<CC -> sigmoid->Cm fp32 (ld=CC);
//                   col>=CC -> sigmoid*Hp -> oh/ol planes (ld=CC)
//      8 tanh(OldP_strided + acc + bias) -> Cm fp32 (ld=N)
template <int EPI>
__global__ void __launch_bounds__(256, 2) bf3_gemm(
    const __nv_bfloat16* __restrict__ Ah, const __nv_bfloat16* __restrict__ Al,
    const __nv_bfloat16* __restrict__ Bh, const __nv_bfloat16* __restrict__ Bl,
    float* __restrict__ Cm, const float* __restrict__ bias,
    const float* __restrict__ Hp,
    const float* __restrict__ OldP, int oldLd,
    __nv_bfloat16* __restrict__ oh, __nv_bfloat16* __restrict__ ol,
    int M, int N, int K) {
    extern __shared__ __align__(16) __nv_bfloat16 sm[];

    int tid = threadIdx.x;
    int m0 = blockIdx.y * BM;
    int n0 = blockIdx.x * BN;
    int warp = tid >> 5, lane = tid & 31;
    int wm = warp >> 1, wn = warp & 1;   // 4M x 2N warps; warp tile 32x64
    int g = lane >> 2, tg = lane & 3;

    float c[2][8][4];
#pragma unroll
    for (int mt = 0; mt < 2; mt++)
#pragma unroll
        for (int nt = 0; nt < 8; nt++)
#pragma unroll
            for (int i = 0; i < 4; i++) c[mt][nt][i] = 0.0f;

    int r0 = tid >> 2, q0 = tid & 3;
    int r1 = (tid + 256) >> 2, q1 = (tid + 256) & 3;

    auto load_stage = [&](int st, int k0) {
        __nv_bfloat16* Ahs = sm + st * STG;
        __nv_bfloat16* Als = Ahs + PL_SZ;
        __nv_bfloat16* Bhs = Als + PL_SZ;
        __nv_bfloat16* Bls = Bhs + PL_SZ;
#pragma unroll
        for (int i = 0; i < 2; i++) {
            int row = i == 0 ? r0 : r1;
            int q = i == 0 ? q0 : q1;
            int m = m0 + row;
            int msz = (m < M) ? 16 : 0;
            size_t asrc = (size_t)(m < M ? m : 0) * K + k0 + q * 8;
            cpa16(Ahs + row * TSTR + q * 8, Ah + asrc, msz);
            cpa16(Als + row * TSTR + q * 8, Al + asrc, msz);
            size_t bsrc = (size_t)(n0 + row) * K + k0 + q * 8;
            cpa16(Bhs + row * TSTR + q * 8, Bh + bsrc, 16);
            cpa16(Bls + row * TSTR + q * 8, Bl + bsrc, 16);
        }
        cpa_commit();
    };

    auto compute = [&](int st) {
        const __nv_bfloat16* Ahs = sm + st * STG;
        const __nv_bfloat16* Als = Ahs + PL_SZ;
        const __nv_bfloat16* Bhs = Als + PL_SZ;
        const __nv_bfloat16* Bls = Bhs + PL_SZ;
#pragma unroll
        for (int ks = 0; ks < 2; ks++) {
            uint32_t ahf[2][4], alf[2][4];
            int arow = lane & 15;
            int acol = ks * 16 + (lane >> 4) * 8;
#pragma unroll
            for (int mt = 0; mt < 2; mt++) {
                int r = wm * 32 + mt * 16 + arow;
                ldsm_x4(Ahs + r * TSTR + acol, ahf[mt]);
                ldsm_x4(Als + r * TSTR + acol, alf[mt]);
            }
            uint32_t bf[8][2];
            int bm_ = lane >> 3;
            int brow_in = lane & 7;
            int bro = (bm_ >> 1) * 8 + brow_in;
            int bco = ks * 16 + (bm_ & 1) * 8;
#pragma unroll
            for (int ntp = 0; ntp < 4; ntp++) {
                int nr = wn * 64 + ntp * 16 + bro;
                uint32_t t4[4];
                ldsm_x4(Bhs + nr * TSTR + bco, t4);
                bf[ntp * 2][0] = t4[0]; bf[ntp * 2][1] = t4[1];
                bf[ntp * 2 + 1][0] = t4[2]; bf[ntp * 2 + 1][1] = t4[3];
            }
#pragma unroll
            for (int mt = 0; mt < 2; mt++)
#pragma unroll
                for (int nt = 0; nt < 8; nt++) {
                    mma16816(c[mt][nt], ahf[mt], bf[nt]);  // hi*hi
                    mma16816(c[mt][nt], alf[mt], bf[nt]);  // lo*hi
                }
#pragma unroll
            for (int ntp = 0; ntp < 4; ntp++) {
                int nr = wn * 64 + ntp * 16 + bro;
                uint32_t t4[4];
                ldsm_x4(Bls + nr * TSTR + bco, t4);
                bf[ntp * 2][0] = t4[0]; bf[ntp * 2][1] = t4[1];
                bf[ntp * 2 + 1][0] = t4[2]; bf[ntp * 2 + 1][1] = t4[3];
            }
#pragma unroll
            for (int mt = 0; mt < 2; mt++)
#pragma unroll
                for (int nt = 0; nt < 8; nt++)
                    mma16816(c[mt][nt], ahf[mt], bf[nt]);  // hi*lo
        }
    };

    int nchunks = K / BKC;
    load_stage(0, 0);
    for (int ch = 0; ch < nchunks; ch++) {
        int st = ch & 1;
        if (ch + 1 < nchunks) {
            load_stage(st ^ 1, (ch + 1) * BKC);
            cpa_wait<1>();
        } else {
            cpa_wait<0>();
        }
        __syncthreads();
        compute(st);
        __syncthreads();
    }

#pragma unroll
    for (int mt = 0; mt < 2; mt++) {
#pragma unroll
        for (int nt = 0; nt < 8; nt++) {
            int col = n0 + wn * 64 + nt * 8 + tg * 2;
            float bv0 = 0.f, bv1 = 0.f;
            if (EPI != 0) { bv0 = __ldg(&bias[col]); bv1 = __ldg(&bias[col + 1]); }
#pragma unroll
            for (int half = 0; half < 2; half++) {
                int row = m0 + wm * 32 + mt * 16 + g + half * 8;
                if (row >= M) continue;
                float v0 = c[mt][nt][half * 2 + 0];
                float v1 = c[mt][nt][half * 2 + 1];
                if (EPI == 0) {
                    size_t off = (size_t)row * N + col;
                    *(float2*)(Cm + off) = make_float2(v0, v1);
                } else if (EPI == 1) {
                    size_t off = (size_t)row * N + col;
                    float a0 = v0 + bv0, a1 = v1 + bv1;
                    *(uint32_t*)(oh + off) = split_pack(a0, a1);
                    *(uint32_t*)(ol + off) = split_pack_lo(a0, a1);
                } else if (EPI == 4) {
                    size_t off = (size_t)row * N + col;
                    *(float2*)(Cm + off) = make_float2(fmaxf(v0 + bv0, 0.0f),
                                                       fmaxf(v1 + bv1, 0.0f));
                } else if (EPI == 7) {
                    float2 old = *(const float2*)(OldP + (size_t)row * oldLd + col);
                    float a0 = old.x + v0 + bv0, a1 = old.y + v1 + bv1;
                    float s0 = 1.0f / (1.0f + expf(-a0));
                    float s1 = 1.0f / (1.0f + expf(-a1));
                    if (col < CC) {
                        size_t off = (size_t)row * CC + col;
                        *(float2*)(Cm + off) = make_float2(s0, s1);
                    } else {
                        int c2 = col - CC;
                        size_t off = (size_t)row * CC + c2;
                        float2 hv = *(const float2*)(Hp + off);
                        float m0v = s0 * hv.x, m1v = s1 * hv.y;
                        *(uint32_t*)(oh + off) = split_pack(m0v, m1v);
                        *(uint32_t*)(ol + off) = split_pack_lo(m0v, m1v);
                    }
                } else if (EPI == 8) {
                    float2 old = *(const float2*)(OldP + (size_t)row * oldLd + col);
                    size_t off = (size_t)row * N + col;
                    *(float2*)(Cm + off) = make_float2(tanhf(old.x + v0 + bv0),
                                                       tanhf(old.y + v1 + bv1));
                }
            }
        }
    }
}

// ---------------- batched GCN propagation ----------------
template <bool WF32>
__global__ void __launch_bounds__(128) prop_split_kernel(
    const float* __restrict__ T, const float* __restrict__ bias,
    float* __restrict__ outf,
    __nv_bfloat16* __restrict__ oh, __nv_bfloat16* __restrict__ ol) {
    int r = blockIdx.x;
    int p = r / NN;
    int i = r - p * NN;
    int t = threadIdx.x;
    const float4* T4 = (const float4*)T;
    float4 b = ((const float4*)bias)[t];
    float sn = g_normself[i];
    float4 v = T4[(size_t)r * C4 + t];
    float4 acc = make_float4(b.x + sn * v.x, b.y + sn * v.y, b.z + sn * v.z, b.w + sn * v.w);
    int beg = g_rowptr[i];
    int end = g_rowptr[i + 1];
    int base = p * NN;
    for (int e = beg; e < end; e++) {
        int s = g_csrsrc[e];
        float w = g_csrnorm[e];
        float4 u = T4[(size_t)(base + s) * C4 + t];
        acc.x = fmaf(w, u.x, acc.x);
        acc.y = fmaf(w, u.y, acc.y);
        acc.z = fmaf(w, u.z, acc.z);
        acc.w = fmaf(w, u.w, acc.w);
    }
    if (WF32) ((float4*)outf)[(size_t)r * C4 + t] = acc;
    size_t off = (size_t)r * CC + t * 4;
    *(uint32_t*)(oh + off) = split_pack(acc.x, acc.y);
    *(uint32_t*)(oh + off + 2) = split_pack(acc.z, acc.w);
    *(uint32_t*)(ol + off) = split_pack_lo(acc.x, acc.y);
    *(uint32_t*)(ol + off + 2) = split_pack_lo(acc.z, acc.w);
}

__global__ void __launch_bounds__(128) prop128_kernel(
    const float* __restrict__ Xp,
    __nv_bfloat16* __restrict__ oh, __nv_bfloat16* __restrict__ ol) {
    int r = blockIdx.x * 4 + (threadIdx.x >> 5);
    int t = threadIdx.x & 31;
    if (r >= MB) return;
    int p = r / NN;
    int i = r - p * NN;
    const float4* X4 = (const float4*)Xp;
    float sn = g_normself[i];
    float4 v = X4[(size_t)r * F4 + t];
    float4 acc = make_float4(sn * v.x, sn * v.y, sn * v.z, sn * v.w);
    int beg = g_rowptr[i];
    int end = g_rowptr[i + 1];
    int base = p * NN;
    for (int e = beg; e < end; e++) {
        int s = g_csrsrc[e];
        float w = g_csrnorm[e];
        float4 u = X4[(size_t)(base + s) * F4 + t];
        acc.x = fmaf(w, u.x, acc.x);
        acc.y = fmaf(w, u.y, acc.y);
        acc.z = fmaf(w, u.z, acc.z);
        acc.w = fmaf(w, u.w, acc.w);
    }
    size_t off = (size_t)r * FF + t * 4;
    *(uint32_t*)(oh + off) = split_pack(acc.x, acc.y);
    *(uint32_t*)(oh + off + 2) = split_pack(acc.z, acc.w);
    *(uint32_t*)(ol + off) = split_pack_lo(acc.x, acc.y);
    *(uint32_t*)(ol + off + 2) = split_pack_lo(acc.z, acc.w);
}

// ---------------- elementwise kernels ----------------
__global__ void extract_all_kernel(const float* __restrict__ x, float* __restrict__ Xp) {
    int idx = blockIdx.x * blockDim.x + threadIdx.x;
    if (idx < NN * FF) {
        float4 v = ((const float4*)x)[idx];
        Xp[idx] = v.x;
        Xp[NN * FF + idx] = v.y;
        Xp[2 * NN * FF + idx] = v.z;
        Xp[3 * NN * FF + idx] = v.w;
    }
}

__global__ void gru_reduce_kernel(const float* __restrict__ Z, const float* __restrict__ H,
                                  const float* __restrict__ Ht, float* __restrict__ out,
                                  __nv_bfloat16* __restrict__ oh, __nv_bfloat16* __restrict__ ol) {
    int idx = blockIdx.x * blockDim.x + threadIdx.x;
    if (idx >= NN * C4) return;
    int i = idx >> 7;
    int t = idx & 127;
    float4 acc = make_float4(0.f, 0.f, 0.f, 0.f);
#pragma unroll
    for (int p = 0; p < PP; p++) {
        size_t o4 = (size_t)(p * NN + i) * C4 + t;
        float4 z = ((const float4*)Z)[o4];
        float4 h = ((const float4*)H)[o4];
        float4 ht = ((const float4*)Ht)[o4];
        float pr = g_probs[p];
        acc.x += pr * (z.x * h.x + (1.0f - z.x) * ht.x);
        acc.y += pr * (z.y * h.y + (1.0f - z.y) * ht.y);
        acc.z += pr * (z.z * h.z + (1.0f - z.z) * ht.z);
        acc.w += pr * (z.w * h.w + (1.0f - z.w) * ht.w);
    }
    ((float4*)(out + NN))[idx] = acc;
    float4 v = make_float4(fmaxf(acc.x, 0.f), fmaxf(acc.y, 0.f),
                           fmaxf(acc.z, 0.f), fmaxf(acc.w, 0.f));
    size_t off = (size_t)idx * 4;
    *(uint32_t*)(oh + off) = split_pack(v.x, v.y);
    *(uint32_t*)(oh + off + 2) = split_pack(v.z, v.w);
    *(uint32_t*)(ol + off) = split_pack_lo(v.x, v.y);
    *(uint32_t*)(ol + off + 2) = split_pack_lo(v.z, v.w);
}

__global__ void lin2_kernel(const float* __restrict__ hid, const float* __restrict__ w,
                            const float* __restrict__ b, float* __restrict__ out) {
    int n = blockIdx.x * 8 + (threadIdx.x >> 5);
    int lane = threadIdx.x & 31;
    float s = 0.0f;
    for (int k = lane; k < HIDN; k += 32) s = fmaf(hid[(size_t)n * HIDN + k], w[k], s);
#pragma unroll
    for (int off = 16; off; off >>= 1) s += __shfl_down_sync(0xffffffffu, s, off);
    if (lane == 0) out[n] = s + b[0];
}

// ---------------- host orchestration ----------------
#define GP(sym) ({ void* _p; cudaGetSymbolAddress(&_p, sym); (__nv_bfloat16*)_p; })
#define GPF(sym) ({ void* _p; cudaGetSymbolAddress(&_p, sym); (float*)_p; })

struct GemmArgs {
    const __nv_bfloat16 *Ah, *Al, *Bh, *Bl;
    float* Cm;
    const float* bias;
    const float* Hp;
    const float* OldP;
    int oldLd;
    __nv_bfloat16 *oh, *ol;
    int M, N, K;
};

template <int EPI>
static inline void launch_gemm(const GemmArgs& a) {
    dim3 grid(a.N / BN, (a.M + BM - 1) / BM);
    bf3_gemm<EPI><<<grid, 256, SMEM_BYTES>>>(a.Ah, a.Al, a.Bh, a.Bl, a.Cm, a.bias,
                                             a.Hp, a.OldP, a.oldLd, a.oh, a.ol,
                                             a.M, a.N, a.K);
}

extern "C" void kernel_launch(void* const* d_in, const int* in_sizes, int n_in,
                              void* d_out, int out_size) {
    const float* x     = (const float*)d_in[0];
    const int*   ei    = (const int*)d_in[1];
    const float* ea    = (const float*)d_in[2];
    const float* W1    = (const float*)d_in[3];
    const float* b1    = (const float*)d_in[4];
    const float* W2    = (const float*)d_in[5];
    const float* b2    = (const float*)d_in[6];
    const float* W3    = (const float*)d_in[7];
    const float* b3    = (const float*)d_in[8];
    const float* W4    = (const float*)d_in[9];
    const float* b4    = (const float*)d_in[10];
    const float* W5    = (const float*)d_in[11];
    const float* b5    = (const float*)d_in[12];
    const float* Wz    = (const float*)d_in[13];
    const float* bz    = (const float*)d_in[14];
    const float* Lz_w  = (const float*)d_in[15];
    const float* Lz_b  = (const float*)d_in[16];
    const float* Wr    = (const float*)d_in[17];
    const float* br    = (const float*)d_in[18];
    const float* Lr_w  = (const float*)d_in[19];
    const float* Lr_b  = (const float*)d_in[20];
    const float* Wh    = (const float*)d_in[21];
    const float* bh    = (const float*)d_in[22];
    const float* Lh_w  = (const float*)d_in[23];
    const float* Lh_b  = (const float*)d_in[24];
    const float* attn  = (const float*)d_in[25];
    const float* lin1w = (const float*)d_in[26];
    const float* lin1b = (const float*)d_in[27];
    const float* lin2w = (const float*)d_in[28];
    const float* lin2b = (const float*)d_in[29];
    float* out = (float*)d_out;

    static bool attr_done = false;
    if (!attr_done) {
        cudaFuncSetAttribute(bf3_gemm<0>, cudaFuncAttributeMaxDynamicSharedMemorySize, SMEM_BYTES);
        cudaFuncSetAttribute(bf3_gemm<1>, cudaFuncAttributeMaxDynamicSharedMemorySize, SMEM_BYTES);
        cudaFuncSetAttribute(bf3_gemm<4>, cudaFuncAttributeMaxDynamicSharedMemorySize, SMEM_BYTES);
        cudaFuncSetAttribute(bf3_gemm<7>, cudaFuncAttributeMaxDynamicSharedMemorySize, SMEM_BYTES);
        cudaFuncSetAttribute(bf3_gemm<8>, cudaFuncAttributeMaxDynamicSharedMemorySize, SMEM_BYTES);
        attr_done = true;
    }

    float* pXp   = GPF(g_Xp);
    float* pT    = GPF(g_T);
    float* pH    = GPF(g_H);
    float* pZ    = GPF(g_Z);
    float* pHt   = GPF(g_Ht);
    float* pG    = GPF(g_G);
    float* phid1 = GPF(g_hid1);
    float* pMtmp = GPF(g_Mtmp);
    float* pbvzr = GPF(g_bvzr);
    float* pbvh  = GPF(g_bvh);

    __nv_bfloat16 *pXsh = GP(g_Xsh), *pXsl = GP(g_Xsl);
    __nv_bfloat16 *pBAh = GP(g_BAh), *pBAl = GP(g_BAl);
    __nv_bfloat16 *pBBh = GP(g_BBh), *pBBl = GP(g_BBl);
    __nv_bfloat16 *pHh = GP(g_Hh), *pHl = GP(g_Hl);
    __nv_bfloat16 *pRmh = GP(g_Rmh), *pRml = GP(g_Rml);
    __nv_bfloat16 *pRAh = GP(g_RAh), *pRAl = GP(g_RAl);

    __nv_bfloat16 *pW1h = GP(g_W1h), *pW1l = GP(g_W1l);
    __nv_bfloat16 *pW2h = GP(g_W2h), *pW2l = GP(g_W2l);
    __nv_bfloat16 *pW3h = GP(g_W3h), *pW3l = GP(g_W3l);
    __nv_bfloat16 *pW4h = GP(g_W4h), *pW4l = GP(g_W4l);
    __nv_bfloat16 *pW5h = GP(g_W5h), *pW5l = GP(g_W5l);
    __nv_bfloat16 *pMGh = GP(g_MGh), *pMGl = GP(g_MGl);
    __nv_bfloat16 *pLzr2h = GP(g_Lzr2h), *pLzr2l = GP(g_Lzr2l);
    __nv_bfloat16 *pLh2h = GP(g_Lh2h), *pLh2l = GP(g_Lh2l);
    __nv_bfloat16 *pL1th = GP(g_L1th), *pL1tl = GP(g_L1tl);

    const int gE  = (EE + 255) / 256;
    const int gN  = (NN + 255) / 256;
    const int gNC4 = (NN * C4 + 255) / 256;
    const int gNF = (NN * FF + 255) / 256;
    const int gW512 = (CC * CC + 255) / 256;
    const int gW128 = (CC * FF + 255) / 256;
    const int gWL1 = (HIDN * CC + 255) / 256;

    init_node_arrays<<<gN, 256>>>();
    deg_edges_kernel<<<gE, 256>>>(ei, ea);
    deg_finalize_kernel<<<gN, 256>>>();
    scan_kernel<<<1, 1024>>>();
    scatter_kernel<<<gE, 256>>>(ei, ea);
    softmax4_kernel<<<1, 32>>>(attn);

    wt_split_kernel<<<gW128, 256>>>(W1, 0, CC, FF, pW1h, pW1l);
    wt_split_kernel<<<gW512, 256>>>(W2, 0, CC, CC, pW2h, pW2l);
    wt_split_kernel<<<gW512, 256>>>(W3, 0, CC, CC, pW3h, pW3l);
    wt_split_kernel<<<gW512, 256>>>(W4, 0, CC, CC, pW4h, pW4l);
    wt_split_kernel<<<gW512, 256>>>(W5, 0, CC, CC, pW5h, pW5l);
    // [Lz2|Lr2]^T concat
    wt_split_kernel<<<gW512, 256>>>(Lz_w, CC, CC, CC, pLzr2h, pLzr2l);
    wt_split_kernel<<<gW512, 256>>>(Lr_w, CC, CC, CC, pLzr2h + (size_t)CC * CC,
                                    pLzr2l + (size_t)CC * CC);
    wt_split_kernel<<<gW512, 256>>>(Lh_w, CC, CC, CC, pLh2h, pLh2l);
    wt_split_kernel<<<gWL1, 256>>>(lin1w, 0, HIDN, CC, pL1th, pL1tl);

    // merged gate weight [Mz|Mr|Mh]^T and biases
    gatefold_kernel<<<gW128, 256>>>(Wz, Lz_w, pMtmp);
    wt_split_kernel<<<gW128, 256>>>(pMtmp, 0, CC, FF, pMGh, pMGl);
    gatefold_kernel<<<gW128, 256>>>(Wr, Lr_w, pMtmp);
    wt_split_kernel<<<gW128, 256>>>(pMtmp, 0, CC, FF, pMGh + (size_t)CC * FF,
                                    pMGl + (size_t)CC * FF);
    gatefold_kernel<<<gW128, 256>>>(Wh, Lh_w, pMtmp);
    wt_split_kernel<<<gW128, 256>>>(pMtmp, 0, CC, FF, pMGh + (size_t)2 * CC * FF,
                                    pMGl + (size_t)2 * CC * FF);
    gate_bias_kernel<<<2, 256>>>(Lz_w, Lz_b, bz, pbvzr);
    gate_bias_kernel<<<2, 256>>>(Lr_w, Lr_b, br, pbvzr + CC);
    gate_bias_kernel<<<2, 256>>>(Lh_w, Lh_b, bh, pbvh);

    // ---- batched across all 4 timesteps (M = 40000) ----
    extract_all_kernel<<<gNF, 256>>>(x, pXp);
    prop128_kernel<<<(MB + 3) / 4, 128>>>(pXp, pXsh, pXsl);

    GemmArgs a{};
    // merged gate pre-activations: G = Xs @ [Mz|Mr|Mh]
    a = {pXsh, pXsl, pMGh, pMGl, pG, nullptr, nullptr, nullptr, 0,
         nullptr, nullptr, MB, NG, FF};
    launch_gemm<0>(a);

    // h1 = Xs@W1 + b1 (split out)
    a = {pXsh, pXsl, pW1h, pW1l, nullptr, b1, nullptr, nullptr, 0,
         pBAh, pBAl, MB, CC, FF};
    launch_gemm<1>(a);
    // layers 2..5
    a = {pBAh, pBAl, pW2h, pW2l, pT, nullptr, nullptr, nullptr, 0,
         nullptr, nullptr, MB, CC, CC};
    launch_gemm<0>(a);
    prop_split_kernel<false><<<MB, 128>>>(pT, b2, nullptr, pBBh, pBBl);
    a.Ah = pBBh; a.Al = pBBl; a.Bh = pW3h; a.Bl = pW3l;
    launch_gemm<0>(a);
    prop_split_kernel<false><<<MB, 128>>>(pT, b3, nullptr, pBAh, pBAl);
    a.Ah = pBAh; a.Al = pBAl; a.Bh = pW4h; a.Bl = pW4l;
    launch_gemm<0>(a);
    prop_split_kernel<false><<<MB, 128>>>(pT, b4, nullptr, pBBh, pBBl);
    a.Ah = pBBh; a.Al = pBBl; a.Bh = pW5h; a.Bl = pW5l;
    launch_gemm<0>(a);
    prop_split_kernel<true><<<MB, 128>>>(pT, b5, pH, pHh, pHl);

    // merged ZR: [Z|R] = sigmoid(G[:,0:1024] + H@[Lz2|Lr2] + bvzr)
    //   cols<512 -> Z fp32; cols>=512 -> Rm = R*H planes
    a = {pHh, pHl, pLzr2h, pLzr2l, pZ, pbvzr, pH, pG, NG,
         pRmh, pRml, MB, 2 * CC, CC};
    launch_gemm<7>(a);

    // Ht = tanh(G[:,1024:1536] + Rm@Lh2 + bvh)
    a = {pRmh, pRml, pLh2h, pLh2l, pHt, pbvh, nullptr, pG + 2 * CC, NG,
         nullptr, nullptr, MB, CC, CC};
    launch_gemm<8>(a);

    gru_reduce_kernel<<<gNC4, 256>>>(pZ, pH, pHt, out, pRAh, pRAl);

    a = {pRAh, pRAl, pL1th, pL1tl, phid1, lin1b, nullptr, nullptr, 0,
         nullptr, nullptr, NN, HIDN, CC};
    launch_gemm<4>(a);
    lin2_kernel<<<(NN + 7) / 8, 256>>>(phid1, lin2w, lin2b, out);
}

// round 11
// speedup vs baseline: 1.1358x; 1.0616x over previous
#include <cuda_runtime.h>
#include <cuda_bf16.h>
#include <stdint.h>
#include <math.h>

#define NN 10000
#define FF 128
#define PP 4
#define EE 160000
#define CC 512
#define HIDN 256
#define C4 (CC/4)
#define F4 (FF/4)
#define MB (NN*PP)
#define NFR 2048             /* merged front width: [u2|Gz|Gr|Gh] */

// ---------------- scratch (static device memory; no allocations) ----------------
__device__ float g_deg[NN];
__device__ float g_dinv[NN];
__device__ float g_normself[NN];
__device__ int   g_counts[NN];
__device__ int   g_rowptr[NN + 1];
__device__ int   g_cursor[NN];
__device__ int   g_csrsrc[EE];
__device__ float g_csrnorm[EE];
__device__ float g_probs[PP];

__device__ float g_Xp[MB * FF];
__device__ float g_T[MB * CC];
__device__ float g_H[MB * CC];
__device__ float g_Z[MB * CC];
__device__ float g_Ht[MB * CC];
__device__ float g_GC[MB * NFR];      // merged front output [u2|Gz|Gr|Gh]
__device__ float g_hid1[NN * HIDN];
__device__ float g_Mtmp[FF * CC];
__device__ float g_bvAll[NFR];        // [b12|bvz|bvr|bvh]

__device__ __nv_bfloat16 g_Xsh[MB * FF], g_Xsl[MB * FF];
__device__ __nv_bfloat16 g_BAh[MB * CC], g_BAl[MB * CC];
__device__ __nv_bfloat16 g_BBh[MB * CC], g_BBl[MB * CC];
__device__ __nv_bfloat16 g_Hh[MB * CC],  g_Hl[MB * CC];
__device__ __nv_bfloat16 g_Rmh[MB * CC], g_Rml[MB * CC];
__device__ __nv_bfloat16 g_RAh[NN * CC], g_RAl[NN * CC];

__device__ __nv_bfloat16 g_W3h[CC * CC], g_W3l[CC * CC];
__device__ __nv_bfloat16 g_W4h[CC * CC], g_W4l[CC * CC];
__device__ __nv_bfloat16 g_W5h[CC * CC], g_W5l[CC * CC];
__device__ __nv_bfloat16 g_MFh[NFR * FF], g_MFl[NFR * FF];     // [W12|Mz|Mr|Mh]^T
__device__ __nv_bfloat16 g_Lzr2h[2 * CC * CC], g_Lzr2l[2 * CC * CC];  // [Lz2|Lr2]^T
__device__ __nv_bfloat16 g_Lh2h[CC * CC], g_Lh2l[CC * CC];
__device__ __nv_bfloat16 g_L1th[HIDN * CC], g_L1tl[HIDN * CC];

__device__ __forceinline__ void split_bf(float x, __nv_bfloat16& h, __nv_bfloat16& l) {
    h = __float2bfloat16(x);
    l = __float2bfloat16(x - __bfloat162float(h));
}
__device__ __forceinline__ uint32_t pack_bf2(__nv_bfloat16 a, __nv_bfloat16 b) {
    __nv_bfloat162 t(a, b);
    return *(uint32_t*)&t;
}
__device__ __forceinline__ uint32_t split_pack(float a, float b) {
    __nv_bfloat16 h0, l0, h1, l1;
    split_bf(a, h0, l0); split_bf(b, h1, l1);
    return pack_bf2(h0, h1);
}
__device__ __forceinline__ uint32_t split_pack_lo(float a, float b) {
    __nv_bfloat16 h0, l0, h1, l1;
    split_bf(a, h0, l0); split_bf(b, h1, l1);
    return pack_bf2(l0, l1);
}

// ---------------- graph setup kernels ----------------
__global__ void init_node_arrays() {
    int i = blockIdx.x * blockDim.x + threadIdx.x;
    if (i < NN) { g_deg[i] = 0.0f; g_counts[i] = 0; g_cursor[i] = 0; }
}

__global__ void deg_edges_kernel(const int* __restrict__ ei, const float* __restrict__ ea) {
    int e = blockIdx.x * blockDim.x + threadIdx.x;
    if (e < EE) {
        int dst = ei[EE + e];
        atomicAdd(&g_deg[dst], ea[e]);
        atomicAdd(&g_counts[dst], 1);
    }
}

__global__ void deg_finalize_kernel() {
    int i = blockIdx.x * blockDim.x + threadIdx.x;
    if (i < NN) {
        float d = g_deg[i] + 1.0f;
        float di = (d > 0.0f) ? rsqrtf(d) : 0.0f;
        g_dinv[i] = di;
        g_normself[i] = di * di;
    }
}

__global__ void scan_kernel() {
    __shared__ int part[1024];
    const int per = 10;
    int t = threadIdx.x;
    int base = t * per;
    int loc[per];
    int s = 0;
#pragma unroll
    for (int i = 0; i < per; i++) {
        int idx = base + i;
        int v = (idx < NN) ? g_counts[idx] : 0;
        loc[i] = s; s += v;
    }
    part[t] = s;
    __syncthreads();
    for (int off = 1; off < 1024; off <<= 1) {
        int v = (t >= off) ? part[t - off] : 0;
        __syncthreads();
        part[t] += v;
        __syncthreads();
    }
    int offb = (t == 0) ? 0 : part[t - 1];
#pragma unroll
    for (int i = 0; i < per; i++) {
        int idx = base + i;
        if (idx < NN) g_rowptr[idx] = offb + loc[i];
    }
    if (t == 1023) g_rowptr[NN] = part[1023];
}

__global__ void scatter_kernel(const int* __restrict__ ei, const float* __restrict__ ea) {
    int e = blockIdx.x * blockDim.x + threadIdx.x;
    if (e < EE) {
        int src = ei[e];
        int dst = ei[EE + e];
        float nv = g_dinv[src] * ea[e] * g_dinv[dst];
        int pos = atomicAdd(&g_cursor[dst], 1);
        int slot = g_rowptr[dst] + pos;
        g_csrsrc[slot] = src;
        g_csrnorm[slot] = nv;
    }
}

__global__ void softmax4_kernel(const float* __restrict__ attn) {
    if (threadIdx.x == 0 && blockIdx.x == 0) {
        float m = attn[0];
        for (int p = 1; p < PP; p++) m = fmaxf(m, attn[p]);
        float s = 0.0f, e[PP];
        for (int p = 0; p < PP; p++) { e[p] = expf(attn[p] - m); s += e[p]; }
        for (int p = 0; p < PP; p++) g_probs[p] = e[p] / s;
    }
}

__global__ void wt_split_kernel(const float* __restrict__ W, int k0, int N, int Kb,
                                __nv_bfloat16* __restrict__ oh, __nv_bfloat16* __restrict__ ol) {
    int idx = blockIdx.x * blockDim.x + threadIdx.x;
    if (idx < N * Kb) {
        int n = idx / Kb;
        int k = idx - n * Kb;
        float v = W[(size_t)(k0 + k) * N + n];
        __nv_bfloat16 h, l;
        split_bf(v, h, l);
        oh[idx] = h; ol[idx] = l;
    }
}

// M[f][n] = sum_k A[f][k] * Bw[k][n]   (fp32, 128x512x512)
__global__ void gatefold_kernel(const float* __restrict__ A, const float* __restrict__ Bw,
                                float* __restrict__ M) {
    int idx = blockIdx.x * blockDim.x + threadIdx.x;
    if (idx < FF * CC) {
        int f = idx / CC, n = idx - f * CC;
        float s = 0.0f;
        for (int k = 0; k < CC; k++)
            s = fmaf(A[(size_t)f * CC + k], Bw[(size_t)k * CC + n], s);
        M[idx] = s;
    }
}

// bv[n] = (Lb ? Lb[n] : 0) + sum_k bsmall[k] * Lw[k][n]
__global__ void gate_bias_kernel(const float* __restrict__ Lw, const float* __restrict__ Lb,
                                 const float* __restrict__ bsmall, float* __restrict__ bv) {
    int n = blockIdx.x * blockDim.x + threadIdx.x;
    if (n < CC) {
        float s = (Lb != nullptr) ? Lb[n] : 0.0f;
        for (int k = 0; k < CC; k++)
            s = fmaf(bsmall[k], Lw[(size_t)k * CC + n], s);
        bv[n] = s;
    }
}

// ---------------- bf16x3 tensor-core GEMM: BM=128, BN=128, cp.async ----------------
#define BM 128
#define BN 128
#define BKC 32
#define TSTR 40
#define PL_SZ (128 * TSTR)
#define STG  (4 * PL_SZ)
#define SMEM_BYTES (2 * STG * 2)

__device__ __forceinline__ void mma16816(float* c, const uint32_t* a, const uint32_t* b) {
    asm volatile(
        "mma.sync.aligned.m16n8k16.row.col.f32.bf16.bf16.f32 "
        "{%0,%1,%2,%3}, {%4,%5,%6,%7}, {%8,%9}, {%0,%1,%2,%3};"
        : "+f"(c[0]), "+f"(c[1]), "+f"(c[2]), "+f"(c[3])
        : "r"(a[0]), "r"(a[1]), "r"(a[2]), "r"(a[3]), "r"(b[0]), "r"(b[1]));
}

__device__ __forceinline__ void ldsm_x4(const void* p, uint32_t* r) {
    uint32_t addr = (uint32_t)__cvta_generic_to_shared(p);
    asm volatile("ldmatrix.sync.aligned.m8n8.x4.shared.b16 {%0,%1,%2,%3}, [%4];"
        : "=r"(r[0]), "=r"(r[1]), "=r"(r[2]), "=r"(r[3]) : "r"(addr));
}

__device__ __forceinline__ void cpa16(void* dst, const void* src, int sz) {
    uint32_t d = (uint32_t)__cvta_generic_to_shared(dst);
    asm volatile("cp.async.cg.shared.global [%0], [%1], 16, %2;"
                 :: "r"(d), "l"(src), "r"(sz));
}
__device__ __forceinline__ void cpa_commit() {
    asm volatile("cp.async.commit_group;");
}
template <int NW>
__device__ __forceinline__ void cpa_wait() {
    asm volatile("cp.async.wait_group %0;" :: "n"(NW));
}

// EPI: 0 store fp32;
//      4 relu(acc+bias)->fp32;
//      7 merged ZR (NO bias; old pre-biased): old=OldP strided;
//        col<CC -> sigmoid->Cm fp32 (ld=CC); col>=CC -> sigmoid*Hp -> planes (ld=CC)
//      8 tanh(OldP_strided + acc) -> Cm fp32 (ld=N), no bias
//      9 store(acc + bias) fp32
template <int EPI>
__global__ void __launch_bounds__(256, 2) bf3_gemm(
    const __nv_bfloat16* __restrict__ Ah, const __nv_bfloat16* __restrict__ Al,
    const __nv_bfloat16* __restrict__ Bh, const __nv_bfloat16* __restrict__ Bl,
    float* __restrict__ Cm, const float* __restrict__ bias,
    const float* __restrict__ Hp,
    const float* __restrict__ OldP, int oldLd,
    __nv_bfloat16* __restrict__ oh, __nv_bfloat16* __restrict__ ol,
    int M, int N, int K) {
    extern __shared__ __align__(16) __nv_bfloat16 sm[];

    int tid = threadIdx.x;
    int m0 = blockIdx.y * BM;
    int n0 = blockIdx.x * BN;
    int warp = tid >> 5, lane = tid & 31;
    int wm = warp >> 1, wn = warp & 1;   // 4M x 2N warps; warp tile 32x64
    int g = lane >> 2, tg = lane & 3;

    float c[2][8][4];
#pragma unroll
    for (int mt = 0; mt < 2; mt++)
#pragma unroll
        for (int nt = 0; nt < 8; nt++)
#pragma unroll
            for (int i = 0; i < 4; i++) c[mt][nt][i] = 0.0f;

    int r0 = tid >> 2, q0 = tid & 3;
    int r1 = (tid + 256) >> 2, q1 = (tid + 256) & 3;

    auto load_stage = [&](int st, int k0) {
        __nv_bfloat16* Ahs = sm + st * STG;
        __nv_bfloat16* Als = Ahs + PL_SZ;
        __nv_bfloat16* Bhs = Als + PL_SZ;
        __nv_bfloat16* Bls = Bhs + PL_SZ;
#pragma unroll
        for (int i = 0; i < 2; i++) {
            int row = i == 0 ? r0 : r1;
            int q = i == 0 ? q0 : q1;
            int m = m0 + row;
            int msz = (m < M) ? 16 : 0;
            size_t asrc = (size_t)(m < M ? m : 0) * K + k0 + q * 8;
            cpa16(Ahs + row * TSTR + q * 8, Ah + asrc, msz);
            cpa16(Als + row * TSTR + q * 8, Al + asrc, msz);
            size_t bsrc = (size_t)(n0 + row) * K + k0 + q * 8;
            cpa16(Bhs + row * TSTR + q * 8, Bh + bsrc, 16);
            cpa16(Bls + row * TSTR + q * 8, Bl + bsrc, 16);
        }
        cpa_commit();
    };

    auto compute = [&](int st) {
        const __nv_bfloat16* Ahs = sm + st * STG;
        const __nv_bfloat16* Als = Ahs + PL_SZ;
        const __nv_bfloat16* Bhs = Als + PL_SZ;
        const __nv_bfloat16* Bls = Bhs + PL_SZ;
#pragma unroll
        for (int ks = 0; ks < 2; ks++) {
            uint32_t ahf[2][4], alf[2][4];
            int arow = lane & 15;
            int acol = ks * 16 + (lane >> 4) * 8;
#pragma unroll
            for (int mt = 0; mt < 2; mt++) {
                int r = wm * 32 + mt * 16 + arow;
                ldsm_x4(Ahs + r * TSTR + acol, ahf[mt]);
                ldsm_x4(Als + r * TSTR + acol, alf[mt]);
            }
            uint32_t bf[8][2];
            int bm_ = lane >> 3;
            int brow_in = lane & 7;
            int bro = (bm_ >> 1) * 8 + brow_in;
            int bco = ks * 16 + (bm_ & 1) * 8;
#pragma unroll
            for (int ntp = 0; ntp < 4; ntp++) {
                int nr = wn * 64 + ntp * 16 + bro;
                uint32_t t4[4];
                ldsm_x4(Bhs + nr * TSTR + bco, t4);
                bf[ntp * 2][0] = t4[0]; bf[ntp * 2][1] = t4[1];
                bf[ntp * 2 + 1][0] = t4[2]; bf[ntp * 2 + 1][1] = t4[3];
            }
#pragma unroll
            for (int mt = 0; mt < 2; mt++)
#pragma unroll
                for (int nt = 0; nt < 8; nt++) {
                    mma16816(c[mt][nt], ahf[mt], bf[nt]);  // hi*hi
                    mma16816(c[mt][nt], alf[mt], bf[nt]);  // lo*hi
                }
#pragma unroll
            for (int ntp = 0; ntp < 4; ntp++) {
                int nr = wn * 64 + ntp * 16 + bro;
                uint32_t t4[4];
                ldsm_x4(Bls + nr * TSTR + bco, t4);
                bf[ntp * 2][0] = t4[0]; bf[ntp * 2][1] = t4[1];
                bf[ntp * 2 + 1][0] = t4[2]; bf[ntp * 2 + 1][1] = t4[3];
            }
#pragma unroll
            for (int mt = 0; mt < 2; mt++)
#pragma unroll
                for (int nt = 0; nt < 8; nt++)
                    mma16816(c[mt][nt], ahf[mt], bf[nt]);  // hi*lo
        }
    };

    int nchunks = K / BKC;
    load_stage(0, 0);
    for (int ch = 0; ch < nchunks; ch++) {
        int st = ch & 1;
        if (ch + 1 < nchunks) {
            load_stage(st ^ 1, (ch + 1) * BKC);
            cpa_wait<1>();
        } else {
            cpa_wait<0>();
        }
        __syncthreads();
        compute(st);
        __syncthreads();
    }

#pragma unroll
    for (int mt = 0; mt < 2; mt++) {
#pragma unroll
        for (int nt = 0; nt < 8; nt++) {
            int col = n0 + wn * 64 + nt * 8 + tg * 2;
            float bv0 = 0.f, bv1 = 0.f;
            if (EPI == 4 || EPI == 9) { bv0 = __ldg(&bias[col]); bv1 = __ldg(&bias[col + 1]); }
#pragma unroll
            for (int half = 0; half < 2; half++) {
                int row = m0 + wm * 32 + mt * 16 + g + half * 8;
                if (row >= M) continue;
                float v0 = c[mt][nt][half * 2 + 0];
                float v1 = c[mt][nt][half * 2 + 1];
                if (EPI == 0) {
                    size_t off = (size_t)row * N + col;
                    *(float2*)(Cm + off) = make_float2(v0, v1);
                } else if (EPI == 4) {
                    size_t off = (size_t)row * N + col;
                    *(float2*)(Cm + off) = make_float2(fmaxf(v0 + bv0, 0.0f),
                                                       fmaxf(v1 + bv1, 0.0f));
                } else if (EPI == 7) {
                    float2 old = *(const float2*)(OldP + (size_t)row * oldLd + col);
                    float a0 = old.x + v0, a1 = old.y + v1;
                    float s0 = 1.0f / (1.0f + expf(-a0));
                    float s1 = 1.0f / (1.0f + expf(-a1));
                    if (col < CC) {
                        size_t off = (size_t)row * CC + col;
                        *(float2*)(Cm + off) = make_float2(s0, s1);
                    } else {
                        int c2 = col - CC;
                        size_t off = (size_t)row * CC + c2;
                        float2 hv = *(const float2*)(Hp + off);
                        float m0v = s0 * hv.x, m1v = s1 * hv.y;
                        *(uint32_t*)(oh + off) = split_pack(m0v, m1v);
                        *(uint32_t*)(ol + off) = split_pack_lo(m0v, m1v);
                    }
                } else if (EPI == 8) {
                    float2 old = *(const float2*)(OldP + (size_t)row * oldLd + col);
                    size_t off = (size_t)row * N + col;
                    *(float2*)(Cm + off) = make_float2(tanhf(old.x + v0),
                                                       tanhf(old.y + v1));
                } else if (EPI == 9) {
                    size_t off = (size_t)row * N + col;
                    *(float2*)(Cm + off) = make_float2(v0 + bv0, v1 + bv1);
                }
            }
        }
    }
}

// ---------------- batched GCN propagation ----------------
// ld4 = row stride of T in float4 units
template <bool WF32>
__global__ void __launch_bounds__(128) prop_split_kernel(
    const float* __restrict__ T, int ld4, const float* __restrict__ bias,
    float* __restrict__ outf,
    __nv_bfloat16* __restrict__ oh, __nv_bfloat16* __restrict__ ol) {
    int r = blockIdx.x;
    int p = r / NN;
    int i = r - p * NN;
    int t = threadIdx.x;
    const float4* T4 = (const float4*)T;
    float4 b = ((const float4*)bias)[t];
    float sn = g_normself[i];
    float4 v = T4[(size_t)r * ld4 + t];
    float4 acc = make_float4(b.x + sn * v.x, b.y + sn * v.y, b.z + sn * v.z, b.w + sn * v.w);
    int beg = g_rowptr[i];
    int end = g_rowptr[i + 1];
    int base = p * NN;
    for (int e = beg; e < end; e++) {
        int s = g_csrsrc[e];
        float w = g_csrnorm[e];
        float4 u = T4[(size_t)(base + s) * ld4 + t];
        acc.x = fmaf(w, u.x, acc.x);
        acc.y = fmaf(w, u.y, acc.y);
        acc.z = fmaf(w, u.z, acc.z);
        acc.w = fmaf(w, u.w, acc.w);
    }
    if (WF32) ((float4*)outf)[(size_t)r * C4 + t] = acc;
    size_t off = (size_t)r * CC + t * 4;
    *(uint32_t*)(oh + off) = split_pack(acc.x, acc.y);
    *(uint32_t*)(oh + off + 2) = split_pack(acc.z, acc.w);
    *(uint32_t*)(ol + off) = split_pack_lo(acc.x, acc.y);
    *(uint32_t*)(ol + off + 2) = split_pack_lo(acc.z, acc.w);
}

__global__ void __launch_bounds__(128) prop128_kernel(
    const float* __restrict__ Xp,
    __nv_bfloat16* __restrict__ oh, __nv_bfloat16* __restrict__ ol) {
    int r = blockIdx.x * 4 + (threadIdx.x >> 5);
    int t = threadIdx.x & 31;
    if (r >= MB) return;
    int p = r / NN;
    int i = r - p * NN;
    const float4* X4 = (const float4*)Xp;
    float sn = g_normself[i];
    float4 v = X4[(size_t)r * F4 + t];
    float4 acc = make_float4(sn * v.x, sn * v.y, sn * v.z, sn * v.w);
    int beg = g_rowptr[i];
    int end = g_rowptr[i + 1];
    int base = p * NN;
    for (int e = beg; e < end; e++) {
        int s = g_csrsrc[e];
        float w = g_csrnorm[e];
        float4 u = X4[(size_t)(base + s) * F4 + t];
        acc.x = fmaf(w, u.x, acc.x);
        acc.y = fmaf(w, u.y, acc.y);
        acc.z = fmaf(w, u.z, acc.z);
        acc.w = fmaf(w, u.w, acc.w);
    }
    size_t off = (size_t)r * FF + t * 4;
    *(uint32_t*)(oh + off) = split_pack(acc.x, acc.y);
    *(uint32_t*)(oh + off + 2) = split_pack(acc.z, acc.w);
    *(uint32_t*)(ol + off) = split_pack_lo(acc.x, acc.y);
    *(uint32_t*)(ol + off + 2) = split_pack_lo(acc.z, acc.w);
}

// ---------------- elementwise kernels ----------------
__global__ void extract_all_kernel(const float* __restrict__ x, float* __restrict__ Xp) {
    int idx = blockIdx.x * blockDim.x + threadIdx.x;
    if (idx < NN * FF) {
        float4 v = ((const float4*)x)[idx];
        Xp[idx] = v.x;
        Xp[NN * FF + idx] = v.y;
        Xp[2 * NN * FF + idx] = v.z;
        Xp[3 * NN * FF + idx] = v.w;
    }
}

__global__ void gru_reduce_kernel(const float* __restrict__ Z, const float* __restrict__ H,
                                  const float* __restrict__ Ht, float* __restrict__ out,
                                  __nv_bfloat16* __restrict__ oh, __nv_bfloat16* __restrict__ ol) {
    int idx = blockIdx.x * blockDim.x + threadIdx.x;
    if (idx >= NN * C4) return;
    int i = idx >> 7;
    int t = idx & 127;
    float4 acc = make_float4(0.f, 0.f, 0.f, 0.f);
#pragma unroll
    for (int p = 0; p < PP; p++) {
        size_t o4 = (size_t)(p * NN + i) * C4 + t;
        float4 z = ((const float4*)Z)[o4];
        float4 h = ((const float4*)H)[o4];
        float4 ht = ((const float4*)Ht)[o4];
        float pr = g_probs[p];
        acc.x += pr * (z.x * h.x + (1.0f - z.x) * ht.x);
        acc.y += pr * (z.y * h.y + (1.0f - z.y) * ht.y);
        acc.z += pr * (z.z * h.z + (1.0f - z.z) * ht.z);
        acc.w += pr * (z.w * h.w + (1.0f - z.w) * ht.w);
    }
    ((float4*)(out + NN))[idx] = acc;
    float4 v = make_float4(fmaxf(acc.x, 0.f), fmaxf(acc.y, 0.f),
                           fmaxf(acc.z, 0.f), fmaxf(acc.w, 0.f));
    size_t off = (size_t)idx * 4;
    *(uint32_t*)(oh + off) = split_pack(v.x, v.y);
    *(uint32_t*)(oh + off + 2) = split_pack(v.z, v.w);
    *(uint32_t*)(ol + off) = split_pack_lo(v.x, v.y);
    *(uint32_t*)(ol + off + 2) = split_pack_lo(v.z, v.w);
}

__global__ void lin2_kernel(const float* __restrict__ hid, const float* __restrict__ w,
                            const float* __restrict__ b, float* __restrict__ out) {
    int n = blockIdx.x * 8 + (threadIdx.x >> 5);
    int lane = threadIdx.x & 31;
    float s = 0.0f;
    for (int k = lane; k < HIDN; k += 32) s = fmaf(hid[(size_t)n * HIDN + k], w[k], s);
#pragma unroll
    for (int off = 16; off; off >>= 1) s += __shfl_down_sync(0xffffffffu, s, off);
    if (lane == 0) out[n] = s + b[0];
}

// ---------------- host orchestration ----------------
#define GP(sym) ({ void* _p; cudaGetSymbolAddress(&_p, sym); (__nv_bfloat16*)_p; })
#define GPF(sym) ({ void* _p; cudaGetSymbolAddress(&_p, sym); (float*)_p; })

struct GemmArgs {
    const __nv_bfloat16 *Ah, *Al, *Bh, *Bl;
    float* Cm;
    const float* bias;
    const float* Hp;
    const float* OldP;
    int oldLd;
    __nv_bfloat16 *oh, *ol;
    int M, N, K;
};

template <int EPI>
static inline void launch_gemm(const GemmArgs& a) {
    dim3 grid(a.N / BN, (a.M + BM - 1) / BM);
    bf3_gemm<EPI><<<grid, 256, SMEM_BYTES>>>(a.Ah, a.Al, a.Bh, a.Bl, a.Cm, a.bias,
                                             a.Hp, a.OldP, a.oldLd, a.oh, a.ol,
                                             a.M, a.N, a.K);
}

extern "C" void kernel_launch(void* const* d_in, const int* in_sizes, int n_in,
                              void* d_out, int out_size) {
    const float* x     = (const float*)d_in[0];
    const int*   ei    = (const int*)d_in[1];
    const float* ea    = (const float*)d_in[2];
    const float* W1    = (const float*)d_in[3];
    const float* b1    = (const float*)d_in[4];
    const float* W2    = (const float*)d_in[5];
    const float* b2    = (const float*)d_in[6];
    const float* W3    = (const float*)d_in[7];
    const float* b3    = (const float*)d_in[8];
    const float* W4    = (const float*)d_in[9];
    const float* b4    = (const float*)d_in[10];
    const float* W5    = (const float*)d_in[11];
    const float* b5    = (const float*)d_in[12];
    const float* Wz    = (const float*)d_in[13];
    const float* bz    = (const float*)d_in[14];
    const float* Lz_w  = (const float*)d_in[15];
    const float* Lz_b  = (const float*)d_in[16];
    const float* Wr    = (const float*)d_in[17];
    const float* br    = (const float*)d_in[18];
    const float* Lr_w  = (const float*)d_in[19];
    const float* Lr_b  = (const float*)d_in[20];
    const float* Wh    = (const float*)d_in[21];
    const float* bh    = (const float*)d_in[22];
    const float* Lh_w  = (const float*)d_in[23];
    const float* Lh_b  = (const float*)d_in[24];
    const float* attn  = (const float*)d_in[25];
    const float* lin1w = (const float*)d_in[26];
    const float* lin1b = (const float*)d_in[27];
    const float* lin2w = (const float*)d_in[28];
    const float* lin2b = (const float*)d_in[29];
    float* out = (float*)d_out;

    static bool attr_done = false;
    if (!attr_done) {
        cudaFuncSetAttribute(bf3_gemm<0>, cudaFuncAttributeMaxDynamicSharedMemorySize, SMEM_BYTES);
        cudaFuncSetAttribute(bf3_gemm<4>, cudaFuncAttributeMaxDynamicSharedMemorySize, SMEM_BYTES);
        cudaFuncSetAttribute(bf3_gemm<7>, cudaFuncAttributeMaxDynamicSharedMemorySize, SMEM_BYTES);
        cudaFuncSetAttribute(bf3_gemm<8>, cudaFuncAttributeMaxDynamicSharedMemorySize, SMEM_BYTES);
        cudaFuncSetAttribute(bf3_gemm<9>, cudaFuncAttributeMaxDynamicSharedMemorySize, SMEM_BYTES);
        attr_done = true;
    }

    float* pXp   = GPF(g_Xp);
    float* pT    = GPF(g_T);
    float* pH    = GPF(g_H);
    float* pZ    = GPF(g_Z);
    float* pHt   = GPF(g_Ht);
    float* pGC   = GPF(g_GC);
    float* phid1 = GPF(g_hid1);
    float* pMtmp = GPF(g_Mtmp);
    float* pbvAll = GPF(g_bvAll);

    __nv_bfloat16 *pXsh = GP(g_Xsh), *pXsl = GP(g_Xsl);
    __nv_bfloat16 *pBAh = GP(g_BAh), *pBAl = GP(g_BAl);
    __nv_bfloat16 *pBBh = GP(g_BBh), *pBBl = GP(g_BBl);
    __nv_bfloat16 *pHh = GP(g_Hh), *pHl = GP(g_Hl);
    __nv_bfloat16 *pRmh = GP(g_Rmh), *pRml = GP(g_Rml);
    __nv_bfloat16 *pRAh = GP(g_RAh), *pRAl = GP(g_RAl);

    __nv_bfloat16 *pW3h = GP(g_W3h), *pW3l = GP(g_W3l);
    __nv_bfloat16 *pW4h = GP(g_W4h), *pW4l = GP(g_W4l);
    __nv_bfloat16 *pW5h = GP(g_W5h), *pW5l = GP(g_W5l);
    __nv_bfloat16 *pMFh = GP(g_MFh), *pMFl = GP(g_MFl);
    __nv_bfloat16 *pLzr2h = GP(g_Lzr2h), *pLzr2l = GP(g_Lzr2l);
    __nv_bfloat16 *pLh2h = GP(g_Lh2h), *pLh2l = GP(g_Lh2l);
    __nv_bfloat16 *pL1th = GP(g_L1th), *pL1tl = GP(g_L1tl);

    const int gE  = (EE + 255) / 256;
    const int gN  = (NN + 255) / 256;
    const int gNC4 = (NN * C4 + 255) / 256;
    const int gNF = (NN * FF + 255) / 256;
    const int gW512 = (CC * CC + 255) / 256;
    const int gW128 = (CC * FF + 255) / 256;
    const int gWL1 = (HIDN * CC + 255) / 256;

    init_node_arrays<<<gN, 256>>>();
    deg_edges_kernel<<<gE, 256>>>(ei, ea);
    deg_finalize_kernel<<<gN, 256>>>();
    scan_kernel<<<1, 1024>>>();
    scatter_kernel<<<gE, 256>>>(ei, ea);
    softmax4_kernel<<<1, 32>>>(attn);

    // chain weights
    wt_split_kernel<<<gW512, 256>>>(W3, 0, CC, CC, pW3h, pW3l);
    wt_split_kernel<<<gW512, 256>>>(W4, 0, CC, CC, pW4h, pW4l);
    wt_split_kernel<<<gW512, 256>>>(W5, 0, CC, CC, pW5h, pW5l);
    // [Lz2|Lr2]^T concat
    wt_split_kernel<<<gW512, 256>>>(Lz_w, CC, CC, CC, pLzr2h, pLzr2l);
    wt_split_kernel<<<gW512, 256>>>(Lr_w, CC, CC, CC, pLzr2h + (size_t)CC * CC,
                                    pLzr2l + (size_t)CC * CC);
    wt_split_kernel<<<gW512, 256>>>(Lh_w, CC, CC, CC, pLh2h, pLh2l);
    wt_split_kernel<<<gWL1, 256>>>(lin1w, 0, HIDN, CC, pL1th, pL1tl);

    // merged front weight [W12|Mz|Mr|Mh]^T and bias [b12|bvz|bvr|bvh]
    gatefold_kernel<<<gW128, 256>>>(W1, W2, pMtmp);   // W12 = W1@W2
    wt_split_kernel<<<gW128, 256>>>(pMtmp, 0, CC, FF, pMFh, pMFl);
    gatefold_kernel<<<gW128, 256>>>(Wz, Lz_w, pMtmp);
    wt_split_kernel<<<gW128, 256>>>(pMtmp, 0, CC, FF, pMFh + (size_t)CC * FF,
                                    pMFl + (size_t)CC * FF);
    gatefold_kernel<<<gW128, 256>>>(Wr, Lr_w, pMtmp);
    wt_split_kernel<<<gW128, 256>>>(pMtmp, 0, CC, FF, pMFh + (size_t)2 * CC * FF,
                                    pMFl + (size_t)2 * CC * FF);
    gatefold_kernel<<<gW128, 256>>>(Wh, Lh_w, pMtmp);
    wt_split_kernel<<<gW128, 256>>>(pMtmp, 0, CC, FF, pMFh + (size_t)3 * CC * FF,
                                    pMFl + (size_t)3 * CC * FF);
    gate_bias_kernel<<<2, 256>>>(W2, nullptr, b1, pbvAll);            // b12 = b1@W2
    gate_bias_kernel<<<2, 256>>>(Lz_w, Lz_b, bz, pbvAll + CC);
    gate_bias_kernel<<<2, 256>>>(Lr_w, Lr_b, br, pbvAll + 2 * CC);
    gate_bias_kernel<<<2, 256>>>(Lh_w, Lh_b, bh, pbvAll + 3 * CC);

    // ---- batched across all 4 timesteps (M = 40000) ----
    extract_all_kernel<<<gNF, 256>>>(x, pXp);
    prop128_kernel<<<(MB + 3) / 4, 128>>>(pXp, pXsh, pXsl);

    GemmArgs a{};
    // merged front: GC = Xs @ [W12|Mz|Mr|Mh] + [b12|bvz|bvr|bvh]
    a = {pXsh, pXsl, pMFh, pMFl, pGC, pbvAll, nullptr, nullptr, 0,
         nullptr, nullptr, MB, NFR, FF};
    launch_gemm<9>(a);

    // h2 = S(GC[:,0:512]) + b2  (split planes BA)
    prop_split_kernel<false><<<MB, 128>>>(pGC, NFR / 4, b2, nullptr, pBAh, pBAl);

    // layers 3..5
    a = {pBAh, pBAl, pW3h, pW3l, pT, nullptr, nullptr, nullptr, 0,
         nullptr, nullptr, MB, CC, CC};
    launch_gemm<0>(a);
    prop_split_kernel<false><<<MB, 128>>>(pT, C4, b3, nullptr, pBBh, pBBl);
    a.Ah = pBBh; a.Al = pBBl; a.Bh = pW4h; a.Bl = pW4l;
    launch_gemm<0>(a);
    prop_split_kernel<false><<<MB, 128>>>(pT, C4, b4, nullptr, pBAh, pBAl);
    a.Ah = pBAh; a.Al = pBAl; a.Bh = pW5h; a.Bl = pW5l;
    launch_gemm<0>(a);
    prop_split_kernel<true><<<MB, 128>>>(pT, C4, b5, pH, pHh, pHl);

    // merged ZR: [Z|R] = sigmoid(GC[:,512:1536] + H@[Lz2|Lr2])   (bias pre-added)
    a = {pHh, pHl, pLzr2h, pLzr2l, pZ, nullptr, pH, pGC + CC, NFR,
         pRmh, pRml, MB, 2 * CC, CC};
    launch_gemm<7>(a);

    // Ht = tanh(GC[:,1536:2048] + Rm@Lh2)
    a = {pRmh, pRml, pLh2h, pLh2l, pHt, nullptr, nullptr, pGC + 3 * CC, NFR,
         nullptr, nullptr, MB, CC, CC};
    launch_gemm<8>(a);

    gru_reduce_kernel<<<gNC4, 256>>>(pZ, pH, pHt, out, pRAh, pRAl);

    a = {pRAh, pRAl, pL1th, pL1tl, phid1, lin1b, nullptr, nullptr, 0,
         nullptr, nullptr, NN, HIDN, CC};
    launch_gemm<4>(a);
    lin2_kernel<<<(NN + 7) / 8, 256>>>(phid1, lin2w, lin2b, out);
}

// round 12
// speedup vs baseline: 1.1557x; 1.0175x over previous
#include <cuda_runtime.h>
#include <cuda_bf16.h>
#include <stdint.h>
#include <math.h>

#define NN 10000
#define FF 128
#define PP 4
#define EE 160000
#define CC 512
#define HIDN 256
#define C4 (CC/4)
#define F4 (FF/4)
#define MB (NN*PP)
#define NFR 2048             /* merged front width: [u2|Gz|Gr|Gh] */

// ---------------- scratch (static device memory; no allocations) ----------------
__device__ float g_deg[NN];
__device__ float g_dinv[NN];
__device__ float g_normself[NN];
__device__ int   g_counts[NN];
__device__ int   g_rowptr[NN + 1];
__device__ int   g_cursor[NN];
__device__ int   g_csrsrc[EE];
__device__ float g_csrnorm[EE];
__device__ float g_probs[PP];

__device__ float g_Xp[MB * FF];
__device__ float g_T[MB * CC];
__device__ float g_H[MB * CC];
__device__ float g_Z[MB * CC];
__device__ float g_Ht[MB * CC];
__device__ float g_GC[MB * NFR];      // merged front output [u2|Gz|Gr|Gh]
__device__ float g_hid1[NN * HIDN];
__device__ float g_Mtmp[FF * CC];
__device__ float g_bvAll[NFR];        // [b12|bvz|bvr|bvh]

__device__ __nv_bfloat16 g_Xsh[MB * FF], g_Xsl[MB * FF];
__device__ __nv_bfloat16 g_BAh[MB * CC], g_BAl[MB * CC];
__device__ __nv_bfloat16 g_BBh[MB * CC], g_BBl[MB * CC];
__device__ __nv_bfloat16 g_Hh[MB * CC],  g_Hl[MB * CC];
__device__ __nv_bfloat16 g_Rmh[MB * CC], g_Rml[MB * CC];
__device__ __nv_bfloat16 g_RAh[NN * CC], g_RAl[NN * CC];

__device__ __nv_bfloat16 g_W3h[CC * CC], g_W3l[CC * CC];
__device__ __nv_bfloat16 g_W4h[CC * CC], g_W4l[CC * CC];
__device__ __nv_bfloat16 g_W5h[CC * CC], g_W5l[CC * CC];
__device__ __nv_bfloat16 g_MFh[NFR * FF], g_MFl[NFR * FF];     // [W12|Mz|Mr|Mh]^T
__device__ __nv_bfloat16 g_Lzr2h[2 * CC * CC], g_Lzr2l[2 * CC * CC];  // [Lz2|Lr2]^T
__device__ __nv_bfloat16 g_Lh2h[CC * CC], g_Lh2l[CC * CC];
__device__ __nv_bfloat16 g_L1th[HIDN * CC], g_L1tl[HIDN * CC];

__device__ __forceinline__ void split_bf(float x, __nv_bfloat16& h, __nv_bfloat16& l) {
    h = __float2bfloat16(x);
    l = __float2bfloat16(x - __bfloat162float(h));
}
__device__ __forceinline__ uint32_t pack_bf2(__nv_bfloat16 a, __nv_bfloat16 b) {
    __nv_bfloat162 t(a, b);
    return *(uint32_t*)&t;
}
__device__ __forceinline__ uint32_t split_pack(float a, float b) {
    __nv_bfloat16 h0, l0, h1, l1;
    split_bf(a, h0, l0); split_bf(b, h1, l1);
    return pack_bf2(h0, h1);
}
__device__ __forceinline__ uint32_t split_pack_lo(float a, float b) {
    __nv_bfloat16 h0, l0, h1, l1;
    split_bf(a, h0, l0); split_bf(b, h1, l1);
    return pack_bf2(l0, l1);
}

// ---------------- graph setup kernels ----------------
__global__ void init_node_arrays() {
    int i = blockIdx.x * blockDim.x + threadIdx.x;
    if (i < NN) { g_deg[i] = 0.0f; g_counts[i] = 0; g_cursor[i] = 0; }
}

__global__ void deg_edges_kernel(const int* __restrict__ ei, const float* __restrict__ ea) {
    int e = blockIdx.x * blockDim.x + threadIdx.x;
    if (e < EE) {
        int dst = ei[EE + e];
        atomicAdd(&g_deg[dst], ea[e]);
        atomicAdd(&g_counts[dst], 1);
    }
}

__global__ void deg_finalize_kernel() {
    int i = blockIdx.x * blockDim.x + threadIdx.x;
    if (i < NN) {
        float d = g_deg[i] + 1.0f;
        float di = (d > 0.0f) ? rsqrtf(d) : 0.0f;
        g_dinv[i] = di;
        g_normself[i] = di * di;
    }
}

__global__ void scan_kernel() {
    __shared__ int part[1024];
    const int per = 10;
    int t = threadIdx.x;
    int base = t * per;
    int loc[per];
    int s = 0;
#pragma unroll
    for (int i = 0; i < per; i++) {
        int idx = base + i;
        int v = (idx < NN) ? g_counts[idx] : 0;
        loc[i] = s; s += v;
    }
    part[t] = s;
    __syncthreads();
    for (int off = 1; off < 1024; off <<= 1) {
        int v = (t >= off) ? part[t - off] : 0;
        __syncthreads();
        part[t] += v;
        __syncthreads();
    }
    int offb = (t == 0) ? 0 : part[t - 1];
#pragma unroll
    for (int i = 0; i < per; i++) {
        int idx = base + i;
        if (idx < NN) g_rowptr[idx] = offb + loc[i];
    }
    if (t == 1023) g_rowptr[NN] = part[1023];
}

__global__ void scatter_kernel(const int* __restrict__ ei, const float* __restrict__ ea) {
    int e = blockIdx.x * blockDim.x + threadIdx.x;
    if (e < EE) {
        int src = ei[e];
        int dst = ei[EE + e];
        float nv = g_dinv[src] * ea[e] * g_dinv[dst];
        int pos = atomicAdd(&g_cursor[dst], 1);
        int slot = g_rowptr[dst] + pos;
        g_csrsrc[slot] = src;
        g_csrnorm[slot] = nv;
    }
}

__global__ void softmax4_kernel(const float* __restrict__ attn) {
    if (threadIdx.x == 0 && blockIdx.x == 0) {
        float m = attn[0];
        for (int p = 1; p < PP; p++) m = fmaxf(m, attn[p]);
        float s = 0.0f, e[PP];
        for (int p = 0; p < PP; p++) { e[p] = expf(attn[p] - m); s += e[p]; }
        for (int p = 0; p < PP; p++) g_probs[p] = e[p] / s;
    }
}

__global__ void wt_split_kernel(const float* __restrict__ W, int k0, int N, int Kb,
                                __nv_bfloat16* __restrict__ oh, __nv_bfloat16* __restrict__ ol) {
    int idx = blockIdx.x * blockDim.x + threadIdx.x;
    if (idx < N * Kb) {
        int n = idx / Kb;
        int k = idx - n * Kb;
        float v = W[(size_t)(k0 + k) * N + n];
        __nv_bfloat16 h, l;
        split_bf(v, h, l);
        oh[idx] = h; ol[idx] = l;
    }
}

// M[f][n] = sum_k A[f][k] * Bw[k][n]   (fp32, 128x512x512)
__global__ void gatefold_kernel(const float* __restrict__ A, const float* __restrict__ Bw,
                                float* __restrict__ M) {
    int idx = blockIdx.x * blockDim.x + threadIdx.x;
    if (idx < FF * CC) {
        int f = idx / CC, n = idx - f * CC;
        float s = 0.0f;
        for (int k = 0; k < CC; k++)
            s = fmaf(A[(size_t)f * CC + k], Bw[(size_t)k * CC + n], s);
        M[idx] = s;
    }
}

// bv[n] = (Lb ? Lb[n] : 0) + sum_k bsmall[k] * Lw[k][n]
__global__ void gate_bias_kernel(const float* __restrict__ Lw, const float* __restrict__ Lb,
                                 const float* __restrict__ bsmall, float* __restrict__ bv) {
    int n = blockIdx.x * blockDim.x + threadIdx.x;
    if (n < CC) {
        float s = (Lb != nullptr) ? Lb[n] : 0.0f;
        for (int k = 0; k < CC; k++)
            s = fmaf(bsmall[k], Lw[(size_t)k * CC + n], s);
        bv[n] = s;
    }
}

// ---------------- bf16x3 tensor-core GEMM: BM=128, BN=128, cp.async ----------------
#define BM 128
#define BN 128
#define BKC 32
#define TSTR 40
#define PL_SZ (128 * TSTR)
#define STG  (4 * PL_SZ)
#define SMEM_BYTES (2 * STG * 2)

__device__ __forceinline__ void mma16816(float* c, const uint32_t* a, const uint32_t* b) {
    asm volatile(
        "mma.sync.aligned.m16n8k16.row.col.f32.bf16.bf16.f32 "
        "{%0,%1,%2,%3}, {%4,%5,%6,%7}, {%8,%9}, {%0,%1,%2,%3};"
        : "+f"(c[0]), "+f"(c[1]), "+f"(c[2]), "+f"(c[3])
        : "r"(a[0]), "r"(a[1]), "r"(a[2]), "r"(a[3]), "r"(b[0]), "r"(b[1]));
}

__device__ __forceinline__ void ldsm_x4(const void* p, uint32_t* r) {
    uint32_t addr = (uint32_t)__cvta_generic_to_shared(p);
    asm volatile("ldmatrix.sync.aligned.m8n8.x4.shared.b16 {%0,%1,%2,%3}, [%4];"
        : "=r"(r[0]), "=r"(r[1]), "=r"(r[2]), "=r"(r[3]) : "r"(addr));
}

__device__ __forceinline__ void cpa16(void* dst, const void* src, int sz) {
    uint32_t d = (uint32_t)__cvta_generic_to_shared(dst);
    asm volatile("cp.async.cg.shared.global [%0], [%1], 16, %2;"
                 :: "r"(d), "l"(src), "r"(sz));
}
__device__ __forceinline__ void cpa_commit() {
    asm volatile("cp.async.commit_group;");
}
template <int NW>
__device__ __forceinline__ void cpa_wait() {
    asm volatile("cp.async.wait_group %0;" :: "n"(NW));
}

// EPI: 0 store fp32;
//      4 relu(acc+bias)->fp32;
//      7 merged ZR (NO bias; old pre-biased): old=OldP strided;
//        col<CC -> sigmoid->Cm fp32 (ld=CC); col>=CC -> sigmoid*Hp -> planes (ld=CC)
//      8 tanh(OldP_strided + acc) -> Cm fp32 (ld=N), no bias
//      9 store(acc + bias) fp32
template <int EPI>
__global__ void __launch_bounds__(256, 2) bf3_gemm(
    const __nv_bfloat16* __restrict__ Ah, const __nv_bfloat16* __restrict__ Al,
    const __nv_bfloat16* __restrict__ Bh, const __nv_bfloat16* __restrict__ Bl,
    float* __restrict__ Cm, const float* __restrict__ bias,
    const float* __restrict__ Hp,
    const float* __restrict__ OldP, int oldLd,
    __nv_bfloat16* __restrict__ oh, __nv_bfloat16* __restrict__ ol,
    int M, int N, int K) {
    extern __shared__ __align__(16) __nv_bfloat16 sm[];

    int tid = threadIdx.x;
    int m0 = blockIdx.y * BM;
    int n0 = blockIdx.x * BN;
    int warp = tid >> 5, lane = tid & 31;
    int wm = warp >> 1, wn = warp & 1;   // 4M x 2N warps; warp tile 32x64
    int g = lane >> 2, tg = lane & 3;

    float c[2][8][4];
#pragma unroll
    for (int mt = 0; mt < 2; mt++)
#pragma unroll
        for (int nt = 0; nt < 8; nt++)
#pragma unroll
            for (int i = 0; i < 4; i++) c[mt][nt][i] = 0.0f;

    int r0 = tid >> 2, q0 = tid & 3;
    int r1 = (tid + 256) >> 2, q1 = (tid + 256) & 3;

    auto load_stage = [&](int st, int k0) {
        __nv_bfloat16* Ahs = sm + st * STG;
        __nv_bfloat16* Als = Ahs + PL_SZ;
        __nv_bfloat16* Bhs = Als + PL_SZ;
        __nv_bfloat16* Bls = Bhs + PL_SZ;
#pragma unroll
        for (int i = 0; i < 2; i++) {
            int row = i == 0 ? r0 : r1;
            int q = i == 0 ? q0 : q1;
            int m = m0 + row;
            int msz = (m < M) ? 16 : 0;
            size_t asrc = (size_t)(m < M ? m : 0) * K + k0 + q * 8;
            cpa16(Ahs + row * TSTR + q * 8, Ah + asrc, msz);
            cpa16(Als + row * TSTR + q * 8, Al + asrc, msz);
            size_t bsrc = (size_t)(n0 + row) * K + k0 + q * 8;
            cpa16(Bhs + row * TSTR + q * 8, Bh + bsrc, 16);
            cpa16(Bls + row * TSTR + q * 8, Bl + bsrc, 16);
        }
        cpa_commit();
    };

    auto compute = [&](int st) {
        const __nv_bfloat16* Ahs = sm + st * STG;
        const __nv_bfloat16* Als = Ahs + PL_SZ;
        const __nv_bfloat16* Bhs = Als + PL_SZ;
        const __nv_bfloat16* Bls = Bhs + PL_SZ;
#pragma unroll
        for (int ks = 0; ks < 2; ks++) {
            uint32_t ahf[2][4], alf[2][4];
            int arow = lane & 15;
            int acol = ks * 16 + (lane >> 4) * 8;
#pragma unroll
            for (int mt = 0; mt < 2; mt++) {
                int r = wm * 32 + mt * 16 + arow;
                ldsm_x4(Ahs + r * TSTR + acol, ahf[mt]);
                ldsm_x4(Als + r * TSTR + acol, alf[mt]);
            }
            uint32_t bf[8][2];
            int bm_ = lane >> 3;
            int brow_in = lane & 7;
            int bro = (bm_ >> 1) * 8 + brow_in;
            int bco = ks * 16 + (bm_ & 1) * 8;
#pragma unroll
            for (int ntp = 0; ntp < 4; ntp++) {
                int nr = wn * 64 + ntp * 16 + bro;
                uint32_t t4[4];
                ldsm_x4(Bhs + nr * TSTR + bco, t4);
                bf[ntp * 2][0] = t4[0]; bf[ntp * 2][1] = t4[1];
                bf[ntp * 2 + 1][0] = t4[2]; bf[ntp * 2 + 1][1] = t4[3];
            }
#pragma unroll
            for (int mt = 0; mt < 2; mt++)
#pragma unroll
                for (int nt = 0; nt < 8; nt++) {
                    mma16816(c[mt][nt], ahf[mt], bf[nt]);  // hi*hi
                    mma16816(c[mt][nt], alf[mt], bf[nt]);  // lo*hi
                }
#pragma unroll
            for (int ntp = 0; ntp < 4; ntp++) {
                int nr = wn * 64 + ntp * 16 + bro;
                uint32_t t4[4];
                ldsm_x4(Bls + nr * TSTR + bco, t4);
                bf[ntp * 2][0] = t4[0]; bf[ntp * 2][1] = t4[1];
                bf[ntp * 2 + 1][0] = t4[2]; bf[ntp * 2 + 1][1] = t4[3];
            }
#pragma unroll
            for (int mt = 0; mt < 2; mt++)
#pragma unroll
                for (int nt = 0; nt < 8; nt++)
                    mma16816(c[mt][nt], ahf[mt], bf[nt]);  // hi*lo
        }
    };

    int nchunks = K / BKC;
    load_stage(0, 0);
    for (int ch = 0; ch < nchunks; ch++) {
        int st = ch & 1;
        if (ch + 1 < nchunks) {
            load_stage(st ^ 1, (ch + 1) * BKC);
            cpa_wait<1>();
        } else {
            cpa_wait<0>();
        }
        __syncthreads();
        compute(st);
        __syncthreads();
    }

#pragma unroll
    for (int mt = 0; mt < 2; mt++) {
#pragma unroll
        for (int nt = 0; nt < 8; nt++) {
            int col = n0 + wn * 64 + nt * 8 + tg * 2;
            float bv0 = 0.f, bv1 = 0.f;
            if (EPI == 4 || EPI == 9) { bv0 = __ldg(&bias[col]); bv1 = __ldg(&bias[col + 1]); }
#pragma unroll
            for (int half = 0; half < 2; half++) {
                int row = m0 + wm * 32 + mt * 16 + g + half * 8;
                if (row >= M) continue;
                float v0 = c[mt][nt][half * 2 + 0];
                float v1 = c[mt][nt][half * 2 + 1];
                if (EPI == 0) {
                    size_t off = (size_t)row * N + col;
                    *(float2*)(Cm + off) = make_float2(v0, v1);
                } else if (EPI == 4) {
                    size_t off = (size_t)row * N + col;
                    *(float2*)(Cm + off) = make_float2(fmaxf(v0 + bv0, 0.0f),
                                                       fmaxf(v1 + bv1, 0.0f));
                } else if (EPI == 7) {
                    float2 old = *(const float2*)(OldP + (size_t)row * oldLd + col);
                    float a0 = old.x + v0, a1 = old.y + v1;
                    float s0 = 1.0f / (1.0f + expf(-a0));
                    float s1 = 1.0f / (1.0f + expf(-a1));
                    if (col < CC) {
                        size_t off = (size_t)row * CC + col;
                        *(float2*)(Cm + off) = make_float2(s0, s1);
                    } else {
                        int c2 = col - CC;
                        size_t off = (size_t)row * CC + c2;
                        float2 hv = *(const float2*)(Hp + off);
                        float m0v = s0 * hv.x, m1v = s1 * hv.y;
                        *(uint32_t*)(oh + off) = split_pack(m0v, m1v);
                        *(uint32_t*)(ol + off) = split_pack_lo(m0v, m1v);
                    }
                } else if (EPI == 8) {
                    float2 old = *(const float2*)(OldP + (size_t)row * oldLd + col);
                    size_t off = (size_t)row * N + col;
                    *(float2*)(Cm + off) = make_float2(tanhf(old.x + v0),
                                                       tanhf(old.y + v1));
                } else if (EPI == 9) {
                    size_t off = (size_t)row * N + col;
                    *(float2*)(Cm + off) = make_float2(v0 + bv0, v1 + bv1);
                }
            }
        }
    }
}

// ---------------- batched GCN propagation (edge loop unrolled x4 for MLP) ----------------
// ld4 = row stride of T in float4 units
template <bool WF32>
__global__ void __launch_bounds__(128) prop_split_kernel(
    const float* __restrict__ T, int ld4, const float* __restrict__ bias,
    float* __restrict__ outf,
    __nv_bfloat16* __restrict__ oh, __nv_bfloat16* __restrict__ ol) {
    int r = blockIdx.x;
    int p = r / NN;
    int i = r - p * NN;
    int t = threadIdx.x;
    const float4* T4 = (const float4*)T;
    float4 b = ((const float4*)bias)[t];
    float sn = g_normself[i];
    float4 v = T4[(size_t)r * ld4 + t];
    float4 acc = make_float4(b.x + sn * v.x, b.y + sn * v.y, b.z + sn * v.z, b.w + sn * v.w);
    int beg = g_rowptr[i];
    int end = g_rowptr[i + 1];
    int base = p * NN;
    int e = beg;
    for (; e + 4 <= end; e += 4) {
        int s0 = g_csrsrc[e], s1 = g_csrsrc[e + 1];
        int s2 = g_csrsrc[e + 2], s3 = g_csrsrc[e + 3];
        float w0 = g_csrnorm[e], w1 = g_csrnorm[e + 1];
        float w2 = g_csrnorm[e + 2], w3 = g_csrnorm[e + 3];
        float4 u0 = T4[(size_t)(base + s0) * ld4 + t];
        float4 u1 = T4[(size_t)(base + s1) * ld4 + t];
        float4 u2 = T4[(size_t)(base + s2) * ld4 + t];
        float4 u3 = T4[(size_t)(base + s3) * ld4 + t];
        acc.x = fmaf(w0, u0.x, acc.x); acc.y = fmaf(w0, u0.y, acc.y);
        acc.z = fmaf(w0, u0.z, acc.z); acc.w = fmaf(w0, u0.w, acc.w);
        acc.x = fmaf(w1, u1.x, acc.x); acc.y = fmaf(w1, u1.y, acc.y);
        acc.z = fmaf(w1, u1.z, acc.z); acc.w = fmaf(w1, u1.w, acc.w);
        acc.x = fmaf(w2, u2.x, acc.x); acc.y = fmaf(w2, u2.y, acc.y);
        acc.z = fmaf(w2, u2.z, acc.z); acc.w = fmaf(w2, u2.w, acc.w);
        acc.x = fmaf(w3, u3.x, acc.x); acc.y = fmaf(w3, u3.y, acc.y);
        acc.z = fmaf(w3, u3.z, acc.z); acc.w = fmaf(w3, u3.w, acc.w);
    }
    for (; e < end; e++) {
        int s = g_csrsrc[e];
        float w = g_csrnorm[e];
        float4 u = T4[(size_t)(base + s) * ld4 + t];
        acc.x = fmaf(w, u.x, acc.x);
        acc.y = fmaf(w, u.y, acc.y);
        acc.z = fmaf(w, u.z, acc.z);
        acc.w = fmaf(w, u.w, acc.w);
    }
    if (WF32) ((float4*)outf)[(size_t)r * C4 + t] = acc;
    size_t off = (size_t)r * CC + t * 4;
    *(uint32_t*)(oh + off) = split_pack(acc.x, acc.y);
    *(uint32_t*)(oh + off + 2) = split_pack(acc.z, acc.w);
    *(uint32_t*)(ol + off) = split_pack_lo(acc.x, acc.y);
    *(uint32_t*)(ol + off + 2) = split_pack_lo(acc.z, acc.w);
}

__global__ void __launch_bounds__(128) prop128_kernel(
    const float* __restrict__ Xp,
    __nv_bfloat16* __restrict__ oh, __nv_bfloat16* __restrict__ ol) {
    int r = blockIdx.x * 4 + (threadIdx.x >> 5);
    int t = threadIdx.x & 31;
    if (r >= MB) return;
    int p = r / NN;
    int i = r - p * NN;
    const float4* X4 = (const float4*)Xp;
    float sn = g_normself[i];
    float4 v = X4[(size_t)r * F4 + t];
    float4 acc = make_float4(sn * v.x, sn * v.y, sn * v.z, sn * v.w);
    int beg = g_rowptr[i];
    int end = g_rowptr[i + 1];
    int base = p * NN;
    int e = beg;
    for (; e + 4 <= end; e += 4) {
        int s0 = g_csrsrc[e], s1 = g_csrsrc[e + 1];
        int s2 = g_csrsrc[e + 2], s3 = g_csrsrc[e + 3];
        float w0 = g_csrnorm[e], w1 = g_csrnorm[e + 1];
        float w2 = g_csrnorm[e + 2], w3 = g_csrnorm[e + 3];
        float4 u0 = X4[(size_t)(base + s0) * F4 + t];
        float4 u1 = X4[(size_t)(base + s1) * F4 + t];
        float4 u2 = X4[(size_t)(base + s2) * F4 + t];
        float4 u3 = X4[(size_t)(base + s3) * F4 + t];
        acc.x = fmaf(w0, u0.x, acc.x); acc.y = fmaf(w0, u0.y, acc.y);
        acc.z = fmaf(w0, u0.z, acc.z); acc.w = fmaf(w0, u0.w, acc.w);
        acc.x = fmaf(w1, u1.x, acc.x); acc.y = fmaf(w1, u1.y, acc.y);
        acc.z = fmaf(w1, u1.z, acc.z); acc.w = fmaf(w1, u1.w, acc.w);
        acc.x = fmaf(w2, u2.x, acc.x); acc.y = fmaf(w2, u2.y, acc.y);
        acc.z = fmaf(w2, u2.z, acc.z); acc.w = fmaf(w2, u2.w, acc.w);
        acc.x = fmaf(w3, u3.x, acc.x); acc.y = fmaf(w3, u3.y, acc.y);
        acc.z = fmaf(w3, u3.z, acc.z); acc.w = fmaf(w3, u3.w, acc.w);
    }
    for (; e < end; e++) {
        int s = g_csrsrc[e];
        float w = g_csrnorm[e];
        float4 u = X4[(size_t)(base + s) * F4 + t];
        acc.x = fmaf(w, u.x, acc.x);
        acc.y = fmaf(w, u.y, acc.y);
        acc.z = fmaf(w, u.z, acc.z);
        acc.w = fmaf(w, u.w, acc.w);
    }
    size_t off = (size_t)r * FF + t * 4;
    *(uint32_t*)(oh + off) = split_pack(acc.x, acc.y);
    *(uint32_t*)(oh + off + 2) = split_pack(acc.z, acc.w);
    *(uint32_t*)(ol + off) = split_pack_lo(acc.x, acc.y);
    *(uint32_t*)(ol + off + 2) = split_pack_lo(acc.z, acc.w);
}

// ---------------- elementwise kernels ----------------
__global__ void extract_all_kernel(const float* __restrict__ x, float* __restrict__ Xp) {
    int idx = blockIdx.x * blockDim.x + threadIdx.x;
    if (idx < NN * FF) {
        float4 v = ((const float4*)x)[idx];
        Xp[idx] = v.x;
        Xp[NN * FF + idx] = v.y;
        Xp[2 * NN * FF + idx] = v.z;
        Xp[3 * NN * FF + idx] = v.w;
    }
}

__global__ void gru_reduce_kernel(const float* __restrict__ Z, const float* __restrict__ H,
                                  const float* __restrict__ Ht, float* __restrict__ out,
                                  __nv_bfloat16* __restrict__ oh, __nv_bfloat16* __restrict__ ol) {
    int idx = blockIdx.x * blockDim.x + threadIdx.x;
    if (idx >= NN * C4) return;
    int i = idx >> 7;
    int t = idx & 127;
    float4 acc = make_float4(0.f, 0.f, 0.f, 0.f);
#pragma unroll
    for (int p = 0; p < PP; p++) {
        size_t o4 = (size_t)(p * NN + i) * C4 + t;
        float4 z = ((const float4*)Z)[o4];
        float4 h = ((const float4*)H)[o4];
        float4 ht = ((const float4*)Ht)[o4];
        float pr = g_probs[p];
        acc.x += pr * (z.x * h.x + (1.0f - z.x) * ht.x);
        acc.y += pr * (z.y * h.y + (1.0f - z.y) * ht.y);
        acc.z += pr * (z.z * h.z + (1.0f - z.z) * ht.z);
        acc.w += pr * (z.w * h.w + (1.0f - z.w) * ht.w);
    }
    ((float4*)(out + NN))[idx] = acc;
    float4 v = make_float4(fmaxf(acc.x, 0.f), fmaxf(acc.y, 0.f),
                           fmaxf(acc.z, 0.f), fmaxf(acc.w, 0.f));
    size_t off = (size_t)idx * 4;
    *(uint32_t*)(oh + off) = split_pack(v.x, v.y);
    *(uint32_t*)(oh + off + 2) = split_pack(v.z, v.w);
    *(uint32_t*)(ol + off) = split_pack_lo(v.x, v.y);
    *(uint32_t*)(ol + off + 2) = split_pack_lo(v.z, v.w);
}

__global__ void lin2_kernel(const float* __restrict__ hid, const float* __restrict__ w,
                            const float* __restrict__ b, float* __restrict__ out) {
    int n = blockIdx.x * 8 + (threadIdx.x >> 5);
    int lane = threadIdx.x & 31;
    float s = 0.0f;
    for (int k = lane; k < HIDN; k += 32) s = fmaf(hid[(size_t)n * HIDN + k], w[k], s);
#pragma unroll
    for (int off = 16; off; off >>= 1) s += __shfl_down_sync(0xffffffffu, s, off);
    if (lane == 0) out[n] = s + b[0];
}

// ---------------- host orchestration ----------------
#define GP(sym) ({ void* _p; cudaGetSymbolAddress(&_p, sym); (__nv_bfloat16*)_p; })
#define GPF(sym) ({ void* _p; cudaGetSymbolAddress(&_p, sym); (float*)_p; })

struct GemmArgs {
    const __nv_bfloat16 *Ah, *Al, *Bh, *Bl;
    float* Cm;
    const float* bias;
    const float* Hp;
    const float* OldP;
    int oldLd;
    __nv_bfloat16 *oh, *ol;
    int M, N, K;
};

template <int EPI>
static inline void launch_gemm(const GemmArgs& a) {
    dim3 grid(a.N / BN, (a.M + BM - 1) / BM);
    bf3_gemm<EPI><<<grid, 256, SMEM_BYTES>>>(a.Ah, a.Al, a.Bh, a.Bl, a.Cm, a.bias,
                                             a.Hp, a.OldP, a.oldLd, a.oh, a.ol,
                                             a.M, a.N, a.K);
}

extern "C" void kernel_launch(void* const* d_in, const int* in_sizes, int n_in,
                              void* d_out, int out_size) {
    const float* x     = (const float*)d_in[0];
    const int*   ei    = (const int*)d_in[1];
    const float* ea    = (const float*)d_in[2];
    const float* W1    = (const float*)d_in[3];
    const float* b1    = (const float*)d_in[4];
    const float* W2    = (const float*)d_in[5];
    const float* b2    = (const float*)d_in[6];
    const float* W3    = (const float*)d_in[7];
    const float* b3    = (const float*)d_in[8];
    const float* W4    = (const float*)d_in[9];
    const float* b4    = (const float*)d_in[10];
    const float* W5    = (const float*)d_in[11];
    const float* b5    = (const float*)d_in[12];
    const float* Wz    = (const float*)d_in[13];
    const float* bz    = (const float*)d_in[14];
    const float* Lz_w  = (const float*)d_in[15];
    const float* Lz_b  = (const float*)d_in[16];
    const float* Wr    = (const float*)d_in[17];
    const float* br    = (const float*)d_in[18];
    const float* Lr_w  = (const float*)d_in[19];
    const float* Lr_b  = (const float*)d_in[20];
    const float* Wh    = (const float*)d_in[21];
    const float* bh    = (const float*)d_in[22];
    const float* Lh_w  = (const float*)d_in[23];
    const float* Lh_b  = (const float*)d_in[24];
    const float* attn  = (const float*)d_in[25];
    const float* lin1w = (const float*)d_in[26];
    const float* lin1b = (const float*)d_in[27];
    const float* lin2w = (const float*)d_in[28];
    const float* lin2b = (const float*)d_in[29];
    float* out = (float*)d_out;

    static bool attr_done = false;
    if (!attr_done) {
        cudaFuncSetAttribute(bf3_gemm<0>, cudaFuncAttributeMaxDynamicSharedMemorySize, SMEM_BYTES);
        cudaFuncSetAttribute(bf3_gemm<4>, cudaFuncAttributeMaxDynamicSharedMemorySize, SMEM_BYTES);
        cudaFuncSetAttribute(bf3_gemm<7>, cudaFuncAttributeMaxDynamicSharedMemorySize, SMEM_BYTES);
        cudaFuncSetAttribute(bf3_gemm<8>, cudaFuncAttributeMaxDynamicSharedMemorySize, SMEM_BYTES);
        cudaFuncSetAttribute(bf3_gemm<9>, cudaFuncAttributeMaxDynamicSharedMemorySize, SMEM_BYTES);
        attr_done = true;
    }

    float* pXp   = GPF(g_Xp);
    float* pT    = GPF(g_T);
    float* pH    = GPF(g_H);
    float* pZ    = GPF(g_Z);
    float* pHt   = GPF(g_Ht);
    float* pGC   = GPF(g_GC);
    float* phid1 = GPF(g_hid1);
    float* pMtmp = GPF(g_Mtmp);
    float* pbvAll = GPF(g_bvAll);

    __nv_bfloat16 *pXsh = GP(g_Xsh), *pXsl = GP(g_Xsl);
    __nv_bfloat16 *pBAh = GP(g_BAh), *pBAl = GP(g_BAl);
    __nv_bfloat16 *pBBh = GP(g_BBh), *pBBl = GP(g_BBl);
    __nv_bfloat16 *pHh = GP(g_Hh), *pHl = GP(g_Hl);
    __nv_bfloat16 *pRmh = GP(g_Rmh), *pRml = GP(g_Rml);
    __nv_bfloat16 *pRAh = GP(g_RAh), *pRAl = GP(g_RAl);

    __nv_bfloat16 *pW3h = GP(g_W3h), *pW3l = GP(g_W3l);
    __nv_bfloat16 *pW4h = GP(g_W4h), *pW4l = GP(g_W4l);
    __nv_bfloat16 *pW5h = GP(g_W5h), *pW5l = GP(g_W5l);
    __nv_bfloat16 *pMFh = GP(g_MFh), *pMFl = GP(g_MFl);
    __nv_bfloat16 *pLzr2h = GP(g_Lzr2h), *pLzr2l = GP(g_Lzr2l);
    __nv_bfloat16 *pLh2h = GP(g_Lh2h), *pLh2l = GP(g_Lh2l);
    __nv_bfloat16 *pL1th = GP(g_L1th), *pL1tl = GP(g_L1tl);

    const int gE  = (EE + 255) / 256;
    const int gN  = (NN + 255) / 256;
    const int gNC4 = (NN * C4 + 255) / 256;
    const int gNF = (NN * FF + 255) / 256;
    const int gW512 = (CC * CC + 255) / 256;
    const int gW128 = (CC * FF + 255) / 256;
    const int gWL1 = (HIDN * CC + 255) / 256;

    init_node_arrays<<<gN, 256>>>();
    deg_edges_kernel<<<gE, 256>>>(ei, ea);
    deg_finalize_kernel<<<gN, 256>>>();
    scan_kernel<<<1, 1024>>>();
    scatter_kernel<<<gE, 256>>>(ei, ea);
    softmax4_kernel<<<1, 32>>>(attn);

    // chain weights
    wt_split_kernel<<<gW512, 256>>>(W3, 0, CC, CC, pW3h, pW3l);
    wt_split_kernel<<<gW512, 256>>>(W4, 0, CC, CC, pW4h, pW4l);
    wt_split_kernel<<<gW512, 256>>>(W5, 0, CC, CC, pW5h, pW5l);
    // [Lz2|Lr2]^T concat
    wt_split_kernel<<<gW512, 256>>>(Lz_w, CC, CC, CC, pLzr2h, pLzr2l);
    wt_split_kernel<<<gW512, 256>>>(Lr_w, CC, CC, CC, pLzr2h + (size_t)CC * CC,
                                    pLzr2l + (size_t)CC * CC);
    wt_split_kernel<<<gW512, 256>>>(Lh_w, CC, CC, CC, pLh2h, pLh2l);
    wt_split_kernel<<<gWL1, 256>>>(lin1w, 0, HIDN, CC, pL1th, pL1tl);

    // merged front weight [W12|Mz|Mr|Mh]^T and bias [b12|bvz|bvr|bvh]
    gatefold_kernel<<<gW128, 256>>>(W1, W2, pMtmp);   // W12 = W1@W2
    wt_split_kernel<<<gW128, 256>>>(pMtmp, 0, CC, FF, pMFh, pMFl);
    gatefold_kernel<<<gW128, 256>>>(Wz, Lz_w, pMtmp);
    wt_split_kernel<<<gW128, 256>>>(pMtmp, 0, CC, FF, pMFh + (size_t)CC * FF,
                                    pMFl + (size_t)CC * FF);
    gatefold_kernel<<<gW128, 256>>>(Wr, Lr_w, pMtmp);
    wt_split_kernel<<<gW128, 256>>>(pMtmp, 0, CC, FF, pMFh + (size_t)2 * CC * FF,
                                    pMFl + (size_t)2 * CC * FF);
    gatefold_kernel<<<gW128, 256>>>(Wh, Lh_w, pMtmp);
    wt_split_kernel<<<gW128, 256>>>(pMtmp, 0, CC, FF, pMFh + (size_t)3 * CC * FF,
                                    pMFl + (size_t)3 * CC * FF);
    gate_bias_kernel<<<2, 256>>>(W2, nullptr, b1, pbvAll);            // b12 = b1@W2
    gate_bias_kernel<<<2, 256>>>(Lz_w, Lz_b, bz, pbvAll + CC);
    gate_bias_kernel<<<2, 256>>>(Lr_w, Lr_b, br, pbvAll + 2 * CC);
    gate_bias_kernel<<<2, 256>>>(Lh_w, Lh_b, bh, pbvAll + 3 * CC);

    // ---- batched across all 4 timesteps (M = 40000) ----
    extract_all_kernel<<<gNF, 256>>>(x, pXp);
    prop128_kernel<<<(MB + 3) / 4, 128>>>(pXp, pXsh, pXsl);

    GemmArgs a{};
    // merged front: GC = Xs @ [W12|Mz|Mr|Mh] + [b12|bvz|bvr|bvh]
    a = {pXsh, pXsl, pMFh, pMFl, pGC, pbvAll, nullptr, nullptr, 0,
         nullptr, nullptr, MB, NFR, FF};
    launch_gemm<9>(a);

    // h2 = S(GC[:,0:512]) + b2  (split planes BA)
    prop_split_kernel<false><<<MB, 128>>>(pGC, NFR / 4, b2, nullptr, pBAh, pBAl);

    // layers 3..5
    a = {pBAh, pBAl, pW3h, pW3l, pT, nullptr, nullptr, nullptr, 0,
         nullptr, nullptr, MB, CC, CC};
    launch_gemm<0>(a);
    prop_split_kernel<false><<<MB, 128>>>(pT, C4, b3, nullptr, pBBh, pBBl);
    a.Ah = pBBh; a.Al = pBBl; a.Bh = pW4h; a.Bl = pW4l;
    launch_gemm<0>(a);
    prop_split_kernel<false><<<MB, 128>>>(pT, C4, b4, nullptr, pBAh, pBAl);
    a.Ah = pBAh; a.Al = pBAl; a.Bh = pW5h; a.Bl = pW5l;
    launch_gemm<0>(a);
    prop_split_kernel<true><<<MB, 128>>>(pT, C4, b5, pH, pHh, pHl);

    // merged ZR: [Z|R] = sigmoid(GC[:,512:1536] + H@[Lz2|Lr2])   (bias pre-added)
    a = {pHh, pHl, pLzr2h, pLzr2l, pZ, nullptr, pH, pGC + CC, NFR,
         pRmh, pRml, MB, 2 * CC, CC};
    launch_gemm<7>(a);

    // Ht = tanh(GC[:,1536:2048] + Rm@Lh2)
    a = {pRmh, pRml, pLh2h, pLh2l, pHt, nullptr, nullptr, pGC + 3 * CC, NFR,
         nullptr, nullptr, MB, CC, CC};
    launch_gemm<8>(a);

    gru_reduce_kernel<<<gNC4, 256>>>(pZ, pH, pHt, out, pRAh, pRAl);

    a = {pRAh, pRAl, pL1th, pL1tl, phid1, lin1b, nullptr, nullptr, 0,
         nullptr, nullptr, NN, HIDN, CC};
    launch_gemm<4>(a);
    lin2_kernel<<<(NN + 7) / 8, 256>>>(phid1, lin2w, lin2b, out);
}

// round 13
// speedup vs baseline: 1.1743x; 1.0161x over previous
#include <cuda_runtime.h>
#include <cuda_bf16.h>
#include <stdint.h>
#include <math.h>

#define NN 10000
#define FF 128
#define PP 4
#define EE 160000
#define CC 512
#define HIDN 256
#define C4 (CC/4)
#define F4 (FF/4)
#define MB (NN*PP)
#define NFR 2048             /* merged front width: [u2|Gz|Gr|Gh] */

// ---------------- scratch (static device memory; no allocations) ----------------
__device__ float g_deg[NN];
__device__ float g_dinv[NN];
__device__ float g_normself[NN];
__device__ int   g_counts[NN];
__device__ int   g_rowptr[NN + 1];
__device__ int   g_cursor[NN];
__device__ int   g_csrsrc[EE];
__device__ float g_csrnorm[EE];
__device__ float g_probs[PP];

__device__ float g_Xp[MB * FF];
__device__ float g_T[MB * CC];
__device__ float g_H[MB * CC];
__device__ float g_Z[MB * CC];
__device__ float g_Ht[MB * CC];
__device__ float g_GC[MB * NFR];
__device__ float g_hid1[NN * HIDN];
__device__ float g_Mtmp[FF * CC];
__device__ float g_bvAll[NFR];        // [b12|bvz|bvr|bvh]

__device__ __nv_bfloat16 g_Xsh[MB * FF], g_Xsl[MB * FF];
__device__ __nv_bfloat16 g_BAh[MB * CC], g_BAl[MB * CC];
__device__ __nv_bfloat16 g_BBh[MB * CC], g_BBl[MB * CC];
__device__ __nv_bfloat16 g_Hh[MB * CC],  g_Hl[MB * CC];
__device__ __nv_bfloat16 g_Rmh[MB * CC], g_Rml[MB * CC];
__device__ __nv_bfloat16 g_RAh[NN * CC], g_RAl[NN * CC];

__device__ __nv_bfloat16 g_W3h[CC * CC], g_W3l[CC * CC];
__device__ __nv_bfloat16 g_W4h[CC * CC], g_W4l[CC * CC];
__device__ __nv_bfloat16 g_W5h[CC * CC], g_W5l[CC * CC];
__device__ __nv_bfloat16 g_MFh[NFR * FF], g_MFl[NFR * FF];
__device__ __nv_bfloat16 g_Lzr2h[2 * CC * CC], g_Lzr2l[2 * CC * CC];
__device__ __nv_bfloat16 g_Lh2h[CC * CC], g_Lh2l[CC * CC];
__device__ __nv_bfloat16 g_L1th[HIDN * CC], g_L1tl[HIDN * CC];

__device__ __forceinline__ void split_bf(float x, __nv_bfloat16& h, __nv_bfloat16& l) {
    h = __float2bfloat16(x);
    l = __float2bfloat16(x - __bfloat162float(h));
}
__device__ __forceinline__ uint32_t pack_bf2(__nv_bfloat16 a, __nv_bfloat16 b) {
    __nv_bfloat162 t(a, b);
    return *(uint32_t*)&t;
}
__device__ __forceinline__ uint32_t split_pack(float a, float b) {
    __nv_bfloat16 h0, l0, h1, l1;
    split_bf(a, h0, l0); split_bf(b, h1, l1);
    return pack_bf2(h0, h1);
}
__device__ __forceinline__ uint32_t split_pack_lo(float a, float b) {
    __nv_bfloat16 h0, l0, h1, l1;
    split_bf(a, h0, l0); split_bf(b, h1, l1);
    return pack_bf2(l0, l1);
}

// ---------------- graph setup kernels ----------------
__global__ void init_node_arrays() {
    int i = blockIdx.x * blockDim.x + threadIdx.x;
    if (i < NN) { g_deg[i] = 0.0f; g_counts[i] = 0; g_cursor[i] = 0; }
}

__global__ void deg_edges_kernel(const int* __restrict__ ei, const float* __restrict__ ea) {
    int e = blockIdx.x * blockDim.x + threadIdx.x;
    if (e < EE) {
        int dst = ei[EE + e];
        atomicAdd(&g_deg[dst], ea[e]);
        atomicAdd(&g_counts[dst], 1);
    }
}

__global__ void deg_finalize_kernel() {
    int i = blockIdx.x * blockDim.x + threadIdx.x;
    if (i < NN) {
        float d = g_deg[i] + 1.0f;
        float di = (d > 0.0f) ? rsqrtf(d) : 0.0f;
        g_dinv[i] = di;
        g_normself[i] = di * di;
    }
}

__global__ void scan_kernel() {
    __shared__ int part[1024];
    const int per = 10;
    int t = threadIdx.x;
    int base = t * per;
    int loc[per];
    int s = 0;
#pragma unroll
    for (int i = 0; i < per; i++) {
        int idx = base + i;
        int v = (idx < NN) ? g_counts[idx] : 0;
        loc[i] = s; s += v;
    }
    part[t] = s;
    __syncthreads();
    for (int off = 1; off < 1024; off <<= 1) {
        int v = (t >= off) ? part[t - off] : 0;
        __syncthreads();
        part[t] += v;
        __syncthreads();
    }
    int offb = (t == 0) ? 0 : part[t - 1];
#pragma unroll
    for (int i = 0; i < per; i++) {
        int idx = base + i;
        if (idx < NN) g_rowptr[idx] = offb + loc[i];
    }
    if (t == 1023) g_rowptr[NN] = part[1023];
}

__global__ void scatter_kernel(const int* __restrict__ ei, const float* __restrict__ ea) {
    int e = blockIdx.x * blockDim.x + threadIdx.x;
    if (e < EE) {
        int src = ei[e];
        int dst = ei[EE + e];
        float nv = g_dinv[src] * ea[e] * g_dinv[dst];
        int pos = atomicAdd(&g_cursor[dst], 1);
        int slot = g_rowptr[dst] + pos;
        g_csrsrc[slot] = src;
        g_csrnorm[slot] = nv;
    }
}

__global__ void softmax4_kernel(const float* __restrict__ attn) {
    if (threadIdx.x == 0 && blockIdx.x == 0) {
        float m = attn[0];
        for (int p = 1; p < PP; p++) m = fmaxf(m, attn[p]);
        float s = 0.0f, e[PP];
        for (int p = 0; p < PP; p++) { e[p] = expf(attn[p] - m); s += e[p]; }
        for (int p = 0; p < PP; p++) g_probs[p] = e[p] / s;
    }
}

// tiled transpose+split: out[n*Kb+k] = split(W[(k0+k)*N + n]); coalesced both sides
__global__ void wt_split_kernel(const float* __restrict__ W, int k0, int N, int Kb,
                                __nv_bfloat16* __restrict__ oh, __nv_bfloat16* __restrict__ ol) {
    __shared__ float tile[32][33];
    int nt = blockIdx.x * 32;
    int kt = blockIdx.y * 32;
    int tx = threadIdx.x & 31;
    int ty = threadIdx.x >> 5;   // 0..7
#pragma unroll
    for (int j = 0; j < 32; j += 8)
        tile[ty + j][tx] = W[(size_t)(k0 + kt + ty + j) * N + nt + tx];
    __syncthreads();
#pragma unroll
    for (int j = 0; j < 32; j += 8) {
        int n = nt + ty + j;
        int k = kt + tx;
        float v = tile[tx][ty + j];
        __nv_bfloat16 h, l;
        split_bf(v, h, l);
        oh[(size_t)n * Kb + k] = h;
        ol[(size_t)n * Kb + k] = l;
    }
}

// M[f][n] = sum_k A[f][k] * Lw[k][n]   (fp32, 128x512x512), unrolled x8 for MLP
__global__ void gatefold_kernel(const float* __restrict__ A, const float* __restrict__ Lw,
                                float* __restrict__ M) {
    int idx = blockIdx.x * blockDim.x + threadIdx.x;
    if (idx < FF * CC) {
        int f = idx / CC, n = idx - f * CC;
        float s = 0.0f;
        for (int k = 0; k < CC; k += 8) {
            float4 a0 = *(const float4*)&A[(size_t)f * CC + k];
            float4 a1 = *(const float4*)&A[(size_t)f * CC + k + 4];
            float l0 = Lw[(size_t)(k + 0) * CC + n];
            float l1 = Lw[(size_t)(k + 1) * CC + n];
            float l2 = Lw[(size_t)(k + 2) * CC + n];
            float l3 = Lw[(size_t)(k + 3) * CC + n];
            float l4 = Lw[(size_t)(k + 4) * CC + n];
            float l5 = Lw[(size_t)(k + 5) * CC + n];
            float l6 = Lw[(size_t)(k + 6) * CC + n];
            float l7 = Lw[(size_t)(k + 7) * CC + n];
            s = fmaf(a0.x, l0, s);
            s = fmaf(a0.y, l1, s);
            s = fmaf(a0.z, l2, s);
            s = fmaf(a0.w, l3, s);
            s = fmaf(a1.x, l4, s);
            s = fmaf(a1.y, l5, s);
            s = fmaf(a1.z, l6, s);
            s = fmaf(a1.w, l7, s);
        }
        M[idx] = s;
    }
}

// all four folded biases in one launch: j=0 b12=b1@W2; j=1..3 gate biases
__global__ void gate_bias_all_kernel(
    const float* __restrict__ W2, const float* __restrict__ b1,
    const float* __restrict__ Lz_w, const float* __restrict__ Lz_b, const float* __restrict__ bz,
    const float* __restrict__ Lr_w, const float* __restrict__ Lr_b, const float* __restrict__ br,
    const float* __restrict__ Lh_w, const float* __restrict__ Lh_b, const float* __restrict__ bh,
    float* __restrict__ bvAll) {
    int j = blockIdx.y;
    int n = blockIdx.x * blockDim.x + threadIdx.x;
    if (n >= CC) return;
    const float* Lw;
    const float* Lb;
    const float* bs;
    if (j == 0)      { Lw = W2;   Lb = nullptr; bs = b1; }
    else if (j == 1) { Lw = Lz_w; Lb = Lz_b;    bs = bz; }
    else if (j == 2) { Lw = Lr_w; Lb = Lr_b;    bs = br; }
    else             { Lw = Lh_w; Lb = Lh_b;    bs = bh; }
    float s = (Lb != nullptr) ? Lb[n] : 0.0f;
    for (int k = 0; k < CC; k += 8) {
        float b0 = bs[k + 0], b1v = bs[k + 1], b2v = bs[k + 2], b3v = bs[k + 3];
        float b4v = bs[k + 4], b5v = bs[k + 5], b6v = bs[k + 6], b7v = bs[k + 7];
        float l0 = Lw[(size_t)(k + 0) * CC + n];
        float l1 = Lw[(size_t)(k + 1) * CC + n];
        float l2 = Lw[(size_t)(k + 2) * CC + n];
        float l3 = Lw[(size_t)(k + 3) * CC + n];
        float l4 = Lw[(size_t)(k + 4) * CC + n];
        float l5 = Lw[(size_t)(k + 5) * CC + n];
        float l6 = Lw[(size_t)(k + 6) * CC + n];
        float l7 = Lw[(size_t)(k + 7) * CC + n];
        s = fmaf(b0, l0, s);
        s = fmaf(b1v, l1, s);
        s = fmaf(b2v, l2, s);
        s = fmaf(b3v, l3, s);
        s = fmaf(b4v, l4, s);
        s = fmaf(b5v, l5, s);
        s = fmaf(b6v, l6, s);
        s = fmaf(b7v, l7, s);
    }
    bvAll[j * CC + n] = s;
}

// ---------------- bf16x3 tensor-core GEMM: BM=128, BN=128, cp.async ----------------
#define BM 128
#define BN 128
#define BKC 32
#define TSTR 40
#define PL_SZ (128 * TSTR)
#define STG  (4 * PL_SZ)
#define SMEM_BYTES (2 * STG * 2)

__device__ __forceinline__ void mma16816(float* c, const uint32_t* a, const uint32_t* b) {
    asm volatile(
        "mma.sync.aligned.m16n8k16.row.col.f32.bf16.bf16.f32 "
        "{%0,%1,%2,%3}, {%4,%5,%6,%7}, {%8,%9}, {%0,%1,%2,%3};"
        : "+f"(c[0]), "+f"(c[1]), "+f"(c[2]), "+f"(c[3])
        : "r"(a[0]), "r"(a[1]), "r"(a[2]), "r"(a[3]), "r"(b[0]), "r"(b[1]));
}

__device__ __forceinline__ void ldsm_x4(const void* p, uint32_t* r) {
    uint32_t addr = (uint32_t)__cvta_generic_to_shared(p);
    asm volatile("ldmatrix.sync.aligned.m8n8.x4.shared.b16 {%0,%1,%2,%3}, [%4];"
        : "=r"(r[0]), "=r"(r[1]), "=r"(r[2]), "=r"(r[3]) : "r"(addr));
}

__device__ __forceinline__ void cpa16(void* dst, const void* src, int sz) {
    uint32_t d = (uint32_t)__cvta_generic_to_shared(dst);
    asm volatile("cp.async.cg.shared.global [%0], [%1], 16, %2;"
                 :: "r"(d), "l"(src), "r"(sz));
}
__device__ __forceinline__ void cpa_commit() {
    asm volatile("cp.async.commit_group;");
}
template <int NW>
__device__ __forceinline__ void cpa_wait() {
    asm volatile("cp.async.wait_group %0;" :: "n"(NW));
}

// EPI: 0 store fp32;
//      4 relu(acc+bias)->fp32;
//      7 merged ZR (old pre-biased): col<CC -> sigmoid->Cm fp32 (ld=CC);
//        col>=CC -> sigmoid*Hp -> planes (ld=CC)
//      8 tanh(OldP_strided + acc) -> Cm fp32 (ld=N)
//      9 store(acc + bias) fp32
template <int EPI>
__global__ void __launch_bounds__(256, 2) bf3_gemm(
    const __nv_bfloat16* __restrict__ Ah, const __nv_bfloat16* __restrict__ Al,
    const __nv_bfloat16* __restrict__ Bh, const __nv_bfloat16* __restrict__ Bl,
    float* __restrict__ Cm, const float* __restrict__ bias,
    const float* __restrict__ Hp,
    const float* __restrict__ OldP, int oldLd,
    __nv_bfloat16* __restrict__ oh, __nv_bfloat16* __restrict__ ol,
    int M, int N, int K) {
    extern __shared__ __align__(16) __nv_bfloat16 sm[];

    int tid = threadIdx.x;
    int m0 = blockIdx.y * BM;
    int n0 = blockIdx.x * BN;
    int warp = tid >> 5, lane = tid & 31;
    int wm = warp >> 1, wn = warp & 1;
    int g = lane >> 2, tg = lane & 3;

    float c[2][8][4];
#pragma unroll
    for (int mt = 0; mt < 2; mt++)
#pragma unroll
        for (int nt = 0; nt < 8; nt++)
#pragma unroll
            for (int i = 0; i < 4; i++) c[mt][nt][i] = 0.0f;

    int r0 = tid >> 2, q0 = tid & 3;
    int r1 = (tid + 256) >> 2, q1 = (tid + 256) & 3;

    auto load_stage = [&](int st, int k0) {
        __nv_bfloat16* Ahs = sm + st * STG;
        __nv_bfloat16* Als = Ahs + PL_SZ;
        __nv_bfloat16* Bhs = Als + PL_SZ;
        __nv_bfloat16* Bls = Bhs + PL_SZ;
#pragma unroll
        for (int i = 0; i < 2; i++) {
            int row = i == 0 ? r0 : r1;
            int q = i == 0 ? q0 : q1;
            int m = m0 + row;
            int msz = (m < M) ? 16 : 0;
            size_t asrc = (size_t)(m < M ? m : 0) * K + k0 + q * 8;
            cpa16(Ahs + row * TSTR + q * 8, Ah + asrc, msz);
            cpa16(Als + row * TSTR + q * 8, Al + asrc, msz);
            size_t bsrc = (size_t)(n0 + row) * K + k0 + q * 8;
            cpa16(Bhs + row * TSTR + q * 8, Bh + bsrc, 16);
            cpa16(Bls + row * TSTR + q * 8, Bl + bsrc, 16);
        }
        cpa_commit();
    };

    auto compute = [&](int st) {
        const __nv_bfloat16* Ahs = sm + st * STG;
        const __nv_bfloat16* Als = Ahs + PL_SZ;
        const __nv_bfloat16* Bhs = Als + PL_SZ;
        const __nv_bfloat16* Bls = Bhs + PL_SZ;
#pragma unroll
        for (int ks = 0; ks < 2; ks++) {
            uint32_t ahf[2][4], alf[2][4];
            int arow = lane & 15;
            int acol = ks * 16 + (lane >> 4) * 8;
#pragma unroll
            for (int mt = 0; mt < 2; mt++) {
                int r = wm * 32 + mt * 16 + arow;
                ldsm_x4(Ahs + r * TSTR + acol, ahf[mt]);
                ldsm_x4(Als + r * TSTR + acol, alf[mt]);
            }
            uint32_t bf[8][2];
            int bm_ = lane >> 3;
            int brow_in = lane & 7;
            int bro = (bm_ >> 1) * 8 + brow_in;
            int bco = ks * 16 + (bm_ & 1) * 8;
#pragma unroll
            for (int ntp = 0; ntp < 4; ntp++) {
                int nr = wn * 64 + ntp * 16 + bro;
                uint32_t t4[4];
                ldsm_x4(Bhs + nr * TSTR + bco, t4);
                bf[ntp * 2][0] = t4[0]; bf[ntp * 2][1] = t4[1];
                bf[ntp * 2 + 1][0] = t4[2]; bf[ntp * 2 + 1][1] = t4[3];
            }
#pragma unroll
            for (int mt = 0; mt < 2; mt++)
#pragma unroll
                for (int nt = 0; nt < 8; nt++) {
                    mma16816(c[mt][nt], ahf[mt], bf[nt]);  // hi*hi
                    mma16816(c[mt][nt], alf[mt], bf[nt]);  // lo*hi
                }
#pragma unroll
            for (int ntp = 0; ntp < 4; ntp++) {
                int nr = wn * 64 + ntp * 16 + bro;
                uint32_t t4[4];
                ldsm_x4(Bls + nr * TSTR + bco, t4);
                bf[ntp * 2][0] = t4[0]; bf[ntp * 2][1] = t4[1];
                bf[ntp * 2 + 1][0] = t4[2]; bf[ntp * 2 + 1][1] = t4[3];
            }
#pragma unroll
            for (int mt = 0; mt < 2; mt++)
#pragma unroll
                for (int nt = 0; nt < 8; nt++)
                    mma16816(c[mt][nt], ahf[mt], bf[nt]);  // hi*lo
        }
    };

    int nchunks = K / BKC;
    load_stage(0, 0);
    for (int ch = 0; ch < nchunks; ch++) {
        int st = ch & 1;
        if (ch + 1 < nchunks) {
            load_stage(st ^ 1, (ch + 1) * BKC);
            cpa_wait<1>();
        } else {
            cpa_wait<0>();
        }
        __syncthreads();
        compute(st);
        __syncthreads();
    }

#pragma unroll
    for (int mt = 0; mt < 2; mt++) {
#pragma unroll
        for (int nt = 0; nt < 8; nt++) {
            int col = n0 + wn * 64 + nt * 8 + tg * 2;
            float bv0 = 0.f, bv1 = 0.f;
            if (EPI == 4 || EPI == 9) { bv0 = __ldg(&bias[col]); bv1 = __ldg(&bias[col + 1]); }
#pragma unroll
            for (int half = 0; half < 2; half++) {
                int row = m0 + wm * 32 + mt * 16 + g + half * 8;
                if (row >= M) continue;
                float v0 = c[mt][nt][half * 2 + 0];
                float v1 = c[mt][nt][half * 2 + 1];
                if (EPI == 0) {
                    size_t off = (size_t)row * N + col;
                    *(float2*)(Cm + off) = make_float2(v0, v1);
                } else if (EPI == 4) {
                    size_t off = (size_t)row * N + col;
                    *(float2*)(Cm + off) = make_float2(fmaxf(v0 + bv0, 0.0f),
                                                       fmaxf(v1 + bv1, 0.0f));
                } else if (EPI == 7) {
                    float2 old = *(const float2*)(OldP + (size_t)row * oldLd + col);
                    float a0 = old.x + v0, a1 = old.y + v1;
                    float s0 = 1.0f / (1.0f + expf(-a0));
                    float s1 = 1.0f / (1.0f + expf(-a1));
                    if (col < CC) {
                        size_t off = (size_t)row * CC + col;
                        *(float2*)(Cm + off) = make_float2(s0, s1);
                    } else {
                        int c2 = col - CC;
                        size_t off = (size_t)row * CC + c2;
                        float2 hv = *(const float2*)(Hp + off);
                        float m0v = s0 * hv.x, m1v = s1 * hv.y;
                        *(uint32_t*)(oh + off) = split_pack(m0v, m1v);
                        *(uint32_t*)(ol + off) = split_pack_lo(m0v, m1v);
                    }
                } else if (EPI == 8) {
                    float2 old = *(const float2*)(OldP + (size_t)row * oldLd + col);
                    size_t off = (size_t)row * N + col;
                    *(float2*)(Cm + off) = make_float2(tanhf(old.x + v0),
                                                       tanhf(old.y + v1));
                } else if (EPI == 9) {
                    size_t off = (size_t)row * N + col;
                    *(float2*)(Cm + off) = make_float2(v0 + bv0, v1 + bv1);
                }
            }
        }
    }
}

// ---------------- batched GCN propagation (edge loop unrolled x4) ----------------
template <bool WF32>
__global__ void __launch_bounds__(128) prop_split_kernel(
    const float* __restrict__ T, int ld4, const float* __restrict__ bias,
    float* __restrict__ outf,
    __nv_bfloat16* __restrict__ oh, __nv_bfloat16* __restrict__ ol) {
    int r = blockIdx.x;
    int p = r / NN;
    int i = r - p * NN;
    int t = threadIdx.x;
    const float4* T4 = (const float4*)T;
    float4 b = ((const float4*)bias)[t];
    float sn = g_normself[i];
    float4 v = T4[(size_t)r * ld4 + t];
    float4 acc = make_float4(b.x + sn * v.x, b.y + sn * v.y, b.z + sn * v.z, b.w + sn * v.w);
    int beg = g_rowptr[i];
    int end = g_rowptr[i + 1];
    int base = p * NN;
    int e = beg;
    for (; e + 4 <= end; e += 4) {
        int s0 = g_csrsrc[e], s1 = g_csrsrc[e + 1];
        int s2 = g_csrsrc[e + 2], s3 = g_csrsrc[e + 3];
        float w0 = g_csrnorm[e], w1 = g_csrnorm[e + 1];
        float w2 = g_csrnorm[e + 2], w3 = g_csrnorm[e + 3];
        float4 u0 = T4[(size_t)(base + s0) * ld4 + t];
        float4 u1 = T4[(size_t)(base + s1) * ld4 + t];
        float4 u2 = T4[(size_t)(base + s2) * ld4 + t];
        float4 u3 = T4[(size_t)(base + s3) * ld4 + t];
        acc.x = fmaf(w0, u0.x, acc.x); acc.y = fmaf(w0, u0.y, acc.y);
        acc.z = fmaf(w0, u0.z, acc.z); acc.w = fmaf(w0, u0.w, acc.w);
        acc.x = fmaf(w1, u1.x, acc.x); acc.y = fmaf(w1, u1.y, acc.y);
        acc.z = fmaf(w1, u1.z, acc.z); acc.w = fmaf(w1, u1.w, acc.w);
        acc.x = fmaf(w2, u2.x, acc.x); acc.y = fmaf(w2, u2.y, acc.y);
        acc.z = fmaf(w2, u2.z, acc.z); acc.w = fmaf(w2, u2.w, acc.w);
        acc.x = fmaf(w3, u3.x, acc.x); acc.y = fmaf(w3, u3.y, acc.y);
        acc.z = fmaf(w3, u3.z, acc.z); acc.w = fmaf(w3, u3.w, acc.w);
    }
    for (; e < end; e++) {
        int s = g_csrsrc[e];
        float w = g_csrnorm[e];
        float4 u = T4[(size_t)(base + s) * ld4 + t];
        acc.x = fmaf(w, u.x, acc.x);
        acc.y = fmaf(w, u.y, acc.y);
        acc.z = fmaf(w, u.z, acc.z);
        acc.w = fmaf(w, u.w, acc.w);
    }
    if (WF32) ((float4*)outf)[(size_t)r * C4 + t] = acc;
    size_t off = (size_t)r * CC + t * 4;
    *(uint32_t*)(oh + off) = split_pack(acc.x, acc.y);
    *(uint32_t*)(oh + off + 2) = split_pack(acc.z, acc.w);
    *(uint32_t*)(ol + off) = split_pack_lo(acc.x, acc.y);
    *(uint32_t*)(ol + off + 2) = split_pack_lo(acc.z, acc.w);
}

__global__ void __launch_bounds__(128) prop128_kernel(
    const float* __restrict__ Xp,
    __nv_bfloat16* __restrict__ oh, __nv_bfloat16* __restrict__ ol) {
    int r = blockIdx.x * 4 + (threadIdx.x >> 5);
    int t = threadIdx.x & 31;
    if (r >= MB) return;
    int p = r / NN;
    int i = r - p * NN;
    const float4* X4 = (const float4*)Xp;
    float sn = g_normself[i];
    float4 v = X4[(size_t)r * F4 + t];
    float4 acc = make_float4(sn * v.x, sn * v.y, sn * v.z, sn * v.w);
    int beg = g_rowptr[i];
    int end = g_rowptr[i + 1];
    int base = p * NN;
    int e = beg;
    for (; e + 4 <= end; e += 4) {
        int s0 = g_csrsrc[e], s1 = g_csrsrc[e + 1];
        int s2 = g_csrsrc[e + 2], s3 = g_csrsrc[e + 3];
        float w0 = g_csrnorm[e], w1 = g_csrnorm[e + 1];
        float w2 = g_csrnorm[e + 2], w3 = g_csrnorm[e + 3];
        float4 u0 = X4[(size_t)(base + s0) * F4 + t];
        float4 u1 = X4[(size_t)(base + s1) * F4 + t];
        float4 u2 = X4[(size_t)(base + s2) * F4 + t];
        float4 u3 = X4[(size_t)(base + s3) * F4 + t];
        acc.x = fmaf(w0, u0.x, acc.x); acc.y = fmaf(w0, u0.y, acc.y);
        acc.z = fmaf(w0, u0.z, acc.z); acc.w = fmaf(w0, u0.w, acc.w);
        acc.x = fmaf(w1, u1.x, acc.x); acc.y = fmaf(w1, u1.y, acc.y);
        acc.z = fmaf(w1, u1.z, acc.z); acc.w = fmaf(w1, u1.w, acc.w);
        acc.x = fmaf(w2, u2.x, acc.x); acc.y = fmaf(w2, u2.y, acc.y);
        acc.z = fmaf(w2, u2.z, acc.z); acc.w = fmaf(w2, u2.w, acc.w);
        acc.x = fmaf(w3, u3.x, acc.x); acc.y = fmaf(w3, u3.y, acc.y);
        acc.z = fmaf(w3, u3.z, acc.z); acc.w = fmaf(w3, u3.w, acc.w);
    }
    for (; e < end; e++) {
        int s = g_csrsrc[e];
        float w = g_csrnorm[e];
        float4 u = X4[(size_t)(base + s) * F4 + t];
        acc.x = fmaf(w, u.x, acc.x);
        acc.y = fmaf(w, u.y, acc.y);
        acc.z = fmaf(w, u.z, acc.z);
        acc.w = fmaf(w, u.w, acc.w);
    }
    size_t off = (size_t)r * FF + t * 4;
    *(uint32_t*)(oh + off) = split_pack(acc.x, acc.y);
    *(uint32_t*)(oh + off + 2) = split_pack(acc.z, acc.w);
    *(uint32_t*)(ol + off) = split_pack_lo(acc.x, acc.y);
    *(uint32_t*)(ol + off + 2) = split_pack_lo(acc.z, acc.w);
}

// ---------------- elementwise kernels ----------------
__global__ void extract_all_kernel(const float* __restrict__ x, float* __restrict__ Xp) {
    int idx = blockIdx.x * blockDim.x + threadIdx.x;
    if (idx < NN * FF) {
        float4 v = ((const float4*)x)[idx];
        Xp[idx] = v.x;
        Xp[NN * FF + idx] = v.y;
        Xp[2 * NN * FF + idx] = v.z;
        Xp[3 * NN * FF + idx] = v.w;
    }
}

__global__ void gru_reduce_kernel(const float* __restrict__ Z, const float* __restrict__ H,
                                  const float* __restrict__ Ht, float* __restrict__ out,
                                  __nv_bfloat16* __restrict__ oh, __nv_bfloat16* __restrict__ ol) {
    int idx = blockIdx.x * blockDim.x + threadIdx.x;
    if (idx >= NN * C4) return;
    int i = idx >> 7;
    int t = idx & 127;
    float4 acc = make_float4(0.f, 0.f, 0.f, 0.f);
#pragma unroll
    for (int p = 0; p < PP; p++) {
        size_t o4 = (size_t)(p * NN + i) * C4 + t;
        float4 z = ((const float4*)Z)[o4];
        float4 h = ((const float4*)H)[o4];
        float4 ht = ((const float4*)Ht)[o4];
        float pr = g_probs[p];
        acc.x += pr * (z.x * h.x + (1.0f - z.x) * ht.x);
        acc.y += pr * (z.y * h.y + (1.0f - z.y) * ht.y);
        acc.z += pr * (z.z * h.z + (1.0f - z.z) * ht.z);
        acc.w += pr * (z.w * h.w + (1.0f - z.w) * ht.w);
    }
    ((float4*)(out + NN))[idx] = acc;
    float4 v = make_float4(fmaxf(acc.x, 0.f), fmaxf(acc.y, 0.f),
                           fmaxf(acc.z, 0.f), fmaxf(acc.w, 0.f));
    size_t off = (size_t)idx * 4;
    *(uint32_t*)(oh + off) = split_pack(v.x, v.y);
    *(uint32_t*)(oh + off + 2) = split_pack(v.z, v.w);
    *(uint32_t*)(ol + off) = split_pack_lo(v.x, v.y);
    *(uint32_t*)(ol + off + 2) = split_pack_lo(v.z, v.w);
}

__global__ void lin2_kernel(const float* __restrict__ hid, const float* __restrict__ w,
                            const float* __restrict__ b, float* __restrict__ out) {
    int n = blockIdx.x * 8 + (threadIdx.x >> 5);
    int lane = threadIdx.x & 31;
    float s = 0.0f;
    for (int k = lane; k < HIDN; k += 32) s = fmaf(hid[(size_t)n * HIDN + k], w[k], s);
#pragma unroll
    for (int off = 16; off; off >>= 1) s += __shfl_down_sync(0xffffffffu, s, off);
    if (lane == 0) out[n] = s + b[0];
}

// ---------------- host orchestration ----------------
#define GP(sym) ({ void* _p; cudaGetSymbolAddress(&_p, sym); (__nv_bfloat16*)_p; })
#define GPF(sym) ({ void* _p; cudaGetSymbolAddress(&_p, sym); (float*)_p; })

struct GemmArgs {
    const __nv_bfloat16 *Ah, *Al, *Bh, *Bl;
    float* Cm;
    const float* bias;
    const float* Hp;
    const float* OldP;
    int oldLd;
    __nv_bfloat16 *oh, *ol;
    int M, N, K;
};

template <int EPI>
static inline void launch_gemm(const GemmArgs& a) {
    dim3 grid(a.N / BN, (a.M + BM - 1) / BM);
    bf3_gemm<EPI><<<grid, 256, SMEM_BYTES>>>(a.Ah, a.Al, a.Bh, a.Bl, a.Cm, a.bias,
                                             a.Hp, a.OldP, a.oldLd, a.oh, a.ol,
                                             a.M, a.N, a.K);
}

static inline void launch_wts(const float* W, int k0, int N, int Kb,
                              __nv_bfloat16* oh, __nv_bfloat16* ol) {
    dim3 grid(N / 32, Kb / 32);
    wt_split_kernel<<<grid, 256>>>(W, k0, N, Kb, oh, ol);
}

extern "C" void kernel_launch(void* const* d_in, const int* in_sizes, int n_in,
                              void* d_out, int out_size) {
    const float* x     = (const float*)d_in[0];
    const int*   ei    = (const int*)d_in[1];
    const float* ea    = (const float*)d_in[2];
    const float* W1    = (const float*)d_in[3];
    const float* b1    = (const float*)d_in[4];
    const float* W2    = (const float*)d_in[5];
    const float* b2    = (const float*)d_in[6];
    const float* W3    = (const float*)d_in[7];
    const float* b3    = (const float*)d_in[8];
    const float* W4    = (const float*)d_in[9];
    const float* b4    = (const float*)d_in[10];
    const float* W5    = (const float*)d_in[11];
    const float* b5    = (const float*)d_in[12];
    const float* Wz    = (const float*)d_in[13];
    const float* bz    = (const float*)d_in[14];
    const float* Lz_w  = (const float*)d_in[15];
    const float* Lz_b  = (const float*)d_in[16];
    const float* Wr    = (const float*)d_in[17];
    const float* br    = (const float*)d_in[18];
    const float* Lr_w  = (const float*)d_in[19];
    const float* Lr_b  = (const float*)d_in[20];
    const float* Wh    = (const float*)d_in[21];
    const float* bh    = (const float*)d_in[22];
    const float* Lh_w  = (const float*)d_in[23];
    const float* Lh_b  = (const float*)d_in[24];
    const float* attn  = (const float*)d_in[25];
    const float* lin1w = (const float*)d_in[26];
    const float* lin1b = (const float*)d_in[27];
    const float* lin2w = (const float*)d_in[28];
    const float* lin2b = (const float*)d_in[29];
    float* out = (float*)d_out;

    static bool attr_done = false;
    if (!attr_done) {
        cudaFuncSetAttribute(bf3_gemm<0>, cudaFuncAttributeMaxDynamicSharedMemorySize, SMEM_BYTES);
        cudaFuncSetAttribute(bf3_gemm<4>, cudaFuncAttributeMaxDynamicSharedMemorySize, SMEM_BYTES);
        cudaFuncSetAttribute(bf3_gemm<7>, cudaFuncAttributeMaxDynamicSharedMemorySize, SMEM_BYTES);
        cudaFuncSetAttribute(bf3_gemm<8>, cudaFuncAttributeMaxDynamicSharedMemorySize, SMEM_BYTES);
        cudaFuncSetAttribute(bf3_gemm<9>, cudaFuncAttributeMaxDynamicSharedMemorySize, SMEM_BYTES);
        attr_done = true;
    }

    float* pXp   = GPF(g_Xp);
    float* pT    = GPF(g_T);
    float* pH    = GPF(g_H);
    float* pZ    = GPF(g_Z);
    float* pHt   = GPF(g_Ht);
    float* pGC   = GPF(g_GC);
    float* phid1 = GPF(g_hid1);
    float* pMtmp = GPF(g_Mtmp);
    float* pbvAll = GPF(g_bvAll);

    __nv_bfloat16 *pXsh = GP(g_Xsh), *pXsl = GP(g_Xsl);
    __nv_bfloat16 *pBAh = GP(g_BAh), *pBAl = GP(g_BAl);
    __nv_bfloat16 *pBBh = GP(g_BBh), *pBBl = GP(g_BBl);
    __nv_bfloat16 *pHh = GP(g_Hh), *pHl = GP(g_Hl);
    __nv_bfloat16 *pRmh = GP(g_Rmh), *pRml = GP(g_Rml);
    __nv_bfloat16 *pRAh = GP(g_RAh), *pRAl = GP(g_RAl);

    __nv_bfloat16 *pW3h = GP(g_W3h), *pW3l = GP(g_W3l);
    __nv_bfloat16 *pW4h = GP(g_W4h), *pW4l = GP(g_W4l);
    __nv_bfloat16 *pW5h = GP(g_W5h), *pW5l = GP(g_W5l);
    __nv_bfloat16 *pMFh = GP(g_MFh), *pMFl = GP(g_MFl);
    __nv_bfloat16 *pLzr2h = GP(g_Lzr2h), *pLzr2l = GP(g_Lzr2l);
    __nv_bfloat16 *pLh2h = GP(g_Lh2h), *pLh2l = GP(g_Lh2l);
    __nv_bfloat16 *pL1th = GP(g_L1th), *pL1tl = GP(g_L1tl);

    const int gE  = (EE + 255) / 256;
    const int gN  = (NN + 255) / 256;
    const int gNC4 = (NN * C4 + 255) / 256;
    const int gNF = (NN * FF + 255) / 256;
    const int gW128 = (CC * FF + 255) / 256;

    init_node_arrays<<<gN, 256>>>();
    deg_edges_kernel<<<gE, 256>>>(ei, ea);
    deg_finalize_kernel<<<gN, 256>>>();
    scan_kernel<<<1, 1024>>>();
    scatter_kernel<<<gE, 256>>>(ei, ea);
    softmax4_kernel<<<1, 32>>>(attn);

    // chain weights (tiled transpose-split)
    launch_wts(W3, 0, CC, CC, pW3h, pW3l);
    launch_wts(W4, 0, CC, CC, pW4h, pW4l);
    launch_wts(W5, 0, CC, CC, pW5h, pW5l);
    launch_wts(Lz_w, CC, CC, CC, pLzr2h, pLzr2l);
    launch_wts(Lr_w, CC, CC, CC, pLzr2h + (size_t)CC * CC, pLzr2l + (size_t)CC * CC);
    launch_wts(Lh_w, CC, CC, CC, pLh2h, pLh2l);
    launch_wts(lin1w, 0, HIDN, CC, pL1th, pL1tl);

    // merged front weight [W12|Mz|Mr|Mh]^T and bias [b12|bvz|bvr|bvh]
    gatefold_kernel<<<gW128, 256>>>(W1, W2, pMtmp);   // W12 = W1@W2
    launch_wts(pMtmp, 0, CC, FF, pMFh, pMFl);
    gatefold_kernel<<<gW128, 256>>>(Wz, Lz_w, pMtmp);
    launch_wts(pMtmp, 0, CC, FF, pMFh + (size_t)CC * FF, pMFl + (size_t)CC * FF);
    gatefold_kernel<<<gW128, 256>>>(Wr, Lr_w, pMtmp);
    launch_wts(pMtmp, 0, CC, FF, pMFh + (size_t)2 * CC * FF, pMFl + (size_t)2 * CC * FF);
    gatefold_kernel<<<gW128, 256>>>(Wh, Lh_w, pMtmp);
    launch_wts(pMtmp, 0, CC, FF, pMFh + (size_t)3 * CC * FF, pMFl + (size_t)3 * CC * FF);
    {
        dim3 grid(2, 4);
        gate_bias_all_kernel<<<grid, 256>>>(W2, b1, Lz_w, Lz_b, bz,
                                            Lr_w, Lr_b, br, Lh_w, Lh_b, bh, pbvAll);
    }

    // ---- batched across all 4 timesteps (M = 40000) ----
    extract_all_kernel<<<gNF, 256>>>(x, pXp);
    prop128_kernel<<<(MB + 3) / 4, 128>>>(pXp, pXsh, pXsl);

    GemmArgs a{};
    // merged front: GC = Xs @ [W12|Mz|Mr|Mh] + [b12|bvz|bvr|bvh]
    a = {pXsh, pXsl, pMFh, pMFl, pGC, pbvAll, nullptr, nullptr, 0,
         nullptr, nullptr, MB, NFR, FF};
    launch_gemm<9>(a);

    // h2 = S(GC[:,0:512]) + b2  (split planes BA)
    prop_split_kernel<false><<<MB, 128>>>(pGC, NFR / 4, b2, nullptr, pBAh, pBAl);

    // layers 3..5
    a = {pBAh, pBAl, pW3h, pW3l, pT, nullptr, nullptr, nullptr, 0,
         nullptr, nullptr, MB, CC, CC};
    launch_gemm<0>(a);
    prop_split_kernel<false><<<MB, 128>>>(pT, C4, b3, nullptr, pBBh, pBBl);
    a.Ah = pBBh; a.Al = pBBl; a.Bh = pW4h; a.Bl = pW4l;
    launch_gemm<0>(a);
    prop_split_kernel<false><<<MB, 128>>>(pT, C4, b4, nullptr, pBAh, pBAl);
    a.Ah = pBAh; a.Al = pBAl; a.Bh = pW5h; a.Bl = pW5l;
    launch_gemm<0>(a);
    prop_split_kernel<true><<<MB, 128>>>(pT, C4, b5, pH, pHh, pHl);

    // merged ZR: [Z|R] = sigmoid(GC[:,512:1536] + H@[Lz2|Lr2])   (bias pre-added)
    a = {pHh, pHl, pLzr2h, pLzr2l, pZ, nullptr, pH, pGC + CC, NFR,
         pRmh, pRml, MB, 2 * CC, CC};
    launch_gemm<7>(a);

    // Ht = tanh(GC[:,1536:2048] + Rm@Lh2)
    a = {pRmh, pRml, pLh2h, pLh2l, pHt, nullptr, nullptr, pGC + 3 * CC, NFR,
         nullptr, nullptr, MB, CC, CC};
    launch_gemm<8>(a);

    gru_reduce_kernel<<<gNC4, 256>>>(pZ, pH, pHt, out, pRAh, pRAl);

    a = {pRAh, pRAl, pL1th, pL1tl, phid1, lin1b, nullptr, nullptr, 0,
         nullptr, nullptr, NN, HIDN, CC};
    launch_gemm<4>(a);
    lin2_kernel<<<(NN + 7) / 8, 256>>>(phid1, lin2w, lin2b, out);
}

// round 14
// speedup vs baseline: 1.4464x; 1.2317x over previous
#include <cuda_runtime.h>
#include <cuda_bf16.h>
#include <stdint.h>
#include <math.h>

#define NN 10000
#define FF 128
#define PP 4
#define EE 160000
#define CC 512
#define HIDN 256
#define C4 (CC/4)
#define F4 (FF/4)
#define MB (NN*PP)
#define NFR 1536             /* merged gate width [Gz|Gr|Gh] */

// ---------------- scratch (static device memory; no allocations) ----------------
__device__ float g_deg[NN];
__device__ float g_dinv[NN];
__device__ float g_normself[NN];
__device__ int   g_counts[NN];
__device__ int   g_rowptr[NN + 1];
__device__ int   g_cursor[NN];
__device__ int   g_csrsrc[EE];
__device__ float g_csrnorm[EE];
__device__ float g_probs[PP];

__device__ float g_Xp[MB * FF];
__device__ float g_XA[MB * FF];
__device__ float g_XB[MB * FF];
__device__ float g_H[MB * CC];
__device__ float g_Z[MB * CC];
__device__ float g_Ht[MB * CC];
__device__ float g_GC[MB * NFR];
__device__ float g_hid1[NN * HIDN];
__device__ float g_Mtmp[FF * CC];
__device__ float g_Mtmp2[FF * CC];
__device__ float g_bvAll[NFR];        // [bvz|bvr|bvh]
__device__ float g_ev[4 * CC];        // e1|e2|e3|e4
__device__ float g_vt1[CC], g_vt2[CC];
__device__ float g_dv[4 * NN];        // d1|d2|d3|d4

__device__ __nv_bfloat16 g_Xsh[MB * FF], g_Xsl[MB * FF];   // X1 planes
__device__ __nv_bfloat16 g_X5h[MB * FF], g_X5l[MB * FF];   // X5 planes
__device__ __nv_bfloat16 g_Hh[MB * CC],  g_Hl[MB * CC];
__device__ __nv_bfloat16 g_Rmh[MB * CC], g_Rml[MB * CC];
__device__ __nv_bfloat16 g_RAh[NN * CC], g_RAl[NN * CC];

__device__ __nv_bfloat16 g_WCh[CC * FF], g_WCl[CC * FF];   // (W1..W5)^T
__device__ __nv_bfloat16 g_MFh[NFR * FF], g_MFl[NFR * FF]; // [Mz|Mr|Mh]^T
__device__ __nv_bfloat16 g_Lzr2h[2 * CC * CC], g_Lzr2l[2 * CC * CC];
__device__ __nv_bfloat16 g_Lh2h[CC * CC], g_Lh2l[CC * CC];
__device__ __nv_bfloat16 g_L1th[HIDN * CC], g_L1tl[HIDN * CC];

__device__ __forceinline__ void split_bf(float x, __nv_bfloat16& h, __nv_bfloat16& l) {
    h = __float2bfloat16(x);
    l = __float2bfloat16(x - __bfloat162float(h));
}
__device__ __forceinline__ uint32_t pack_bf2(__nv_bfloat16 a, __nv_bfloat16 b) {
    __nv_bfloat162 t(a, b);
    return *(uint32_t*)&t;
}
__device__ __forceinline__ uint32_t split_pack(float a, float b) {
    __nv_bfloat16 h0, l0, h1, l1;
    split_bf(a, h0, l0); split_bf(b, h1, l1);
    return pack_bf2(h0, h1);
}
__device__ __forceinline__ uint32_t split_pack_lo(float a, float b) {
    __nv_bfloat16 h0, l0, h1, l1;
    split_bf(a, h0, l0); split_bf(b, h1, l1);
    return pack_bf2(l0, l1);
}

// ---------------- graph setup kernels ----------------
__global__ void init_node_arrays() {
    int i = blockIdx.x * blockDim.x + threadIdx.x;
    if (i < NN) { g_deg[i] = 0.0f; g_counts[i] = 0; g_cursor[i] = 0; }
}

__global__ void deg_edges_kernel(const int* __restrict__ ei, const float* __restrict__ ea) {
    int e = blockIdx.x * blockDim.x + threadIdx.x;
    if (e < EE) {
        int dst = ei[EE + e];
        atomicAdd(&g_deg[dst], ea[e]);
        atomicAdd(&g_counts[dst], 1);
    }
}

__global__ void deg_finalize_kernel() {
    int i = blockIdx.x * blockDim.x + threadIdx.x;
    if (i < NN) {
        float d = g_deg[i] + 1.0f;
        float di = (d > 0.0f) ? rsqrtf(d) : 0.0f;
        g_dinv[i] = di;
        g_normself[i] = di * di;
    }
}

__global__ void scan_kernel() {
    __shared__ int part[1024];
    const int per = 10;
    int t = threadIdx.x;
    int base = t * per;
    int loc[per];
    int s = 0;
#pragma unroll
    for (int i = 0; i < per; i++) {
        int idx = base + i;
        int v = (idx < NN) ? g_counts[idx] : 0;
        loc[i] = s; s += v;
    }
    part[t] = s;
    __syncthreads();
    for (int off = 1; off < 1024; off <<= 1) {
        int v = (t >= off) ? part[t - off] : 0;
        __syncthreads();
        part[t] += v;
        __syncthreads();
    }
    int offb = (t == 0) ? 0 : part[t - 1];
#pragma unroll
    for (int i = 0; i < per; i++) {
        int idx = base + i;
        if (idx < NN) g_rowptr[idx] = offb + loc[i];
    }
    if (t == 1023) g_rowptr[NN] = part[1023];
}

__global__ void scatter_kernel(const int* __restrict__ ei, const float* __restrict__ ea) {
    int e = blockIdx.x * blockDim.x + threadIdx.x;
    if (e < EE) {
        int src = ei[e];
        int dst = ei[EE + e];
        float nv = g_dinv[src] * ea[e] * g_dinv[dst];
        int pos = atomicAdd(&g_cursor[dst], 1);
        int slot = g_rowptr[dst] + pos;
        g_csrsrc[slot] = src;
        g_csrnorm[slot] = nv;
    }
}

__global__ void softmax4_kernel(const float* __restrict__ attn) {
    if (threadIdx.x == 0 && blockIdx.x == 0) {
        float m = attn[0];
        for (int p = 1; p < PP; p++) m = fmaxf(m, attn[p]);
        float s = 0.0f, e[PP];
        for (int p = 0; p < PP; p++) { e[p] = expf(attn[p] - m); s += e[p]; }
        for (int p = 0; p < PP; p++) g_probs[p] = e[p] / s;
    }
}

// d_{k}[i] = normself[i]*d_{k-1}[i] + sum norm*d_{k-1}[src]; din==null -> all ones
__global__ void d_iter_kernel(const float* __restrict__ din, float* __restrict__ dout) {
    int i = blockIdx.x * blockDim.x + threadIdx.x;
    if (i >= NN) return;
    float self = (din != nullptr) ? din[i] : 1.0f;
    float acc = g_normself[i] * self;
    int beg = g_rowptr[i], end = g_rowptr[i + 1];
    for (int e = beg; e < end; e++) {
        float u = (din != nullptr) ? din[g_csrsrc[e]] : 1.0f;
        acc = fmaf(g_csrnorm[e], u, acc);
    }
    dout[i] = acc;
}

// out[n] = sum_k v[k]*W[k*CC+n]
__global__ void vecmat_kernel(const float* __restrict__ v, const float* __restrict__ W,
                              float* __restrict__ out) {
    int n = blockIdx.x * blockDim.x + threadIdx.x;
    if (n >= CC) return;
    float s = 0.0f;
    for (int k = 0; k < CC; k += 8) {
#pragma unroll
        for (int j = 0; j < 8; j++)
            s = fmaf(v[k + j], W[(size_t)(k + j) * CC + n], s);
    }
    out[n] = s;
}

// tiled transpose+split: out[n*Kb+k] = split(W[(k0+k)*N + n])
__global__ void wt_split_kernel(const float* __restrict__ W, int k0, int N, int Kb,
                                __nv_bfloat16* __restrict__ oh, __nv_bfloat16* __restrict__ ol) {
    __shared__ float tile[32][33];
    int nt = blockIdx.x * 32;
    int kt = blockIdx.y * 32;
    int tx = threadIdx.x & 31;
    int ty = threadIdx.x >> 5;
#pragma unroll
    for (int j = 0; j < 32; j += 8)
        tile[ty + j][tx] = W[(size_t)(k0 + kt + ty + j) * N + nt + tx];
    __syncthreads();
#pragma unroll
    for (int j = 0; j < 32; j += 8) {
        int n = nt + ty + j;
        int k = kt + tx;
        float v = tile[tx][ty + j];
        __nv_bfloat16 h, l;
        split_bf(v, h, l);
        oh[(size_t)n * Kb + k] = h;
        ol[(size_t)n * Kb + k] = l;
    }
}

// M[f][n] = sum_k A[f][k] * Lw[k][n]   (fp32, 128x512x512)
__global__ void gatefold_kernel(const float* __restrict__ A, const float* __restrict__ Lw,
                                float* __restrict__ M) {
    int idx = blockIdx.x * blockDim.x + threadIdx.x;
    if (idx < FF * CC) {
        int f = idx / CC, n = idx - f * CC;
        float s = 0.0f;
        for (int k = 0; k < CC; k += 8) {
            float4 a0 = *(const float4*)&A[(size_t)f * CC + k];
            float4 a1 = *(const float4*)&A[(size_t)f * CC + k + 4];
            s = fmaf(a0.x, Lw[(size_t)(k + 0) * CC + n], s);
            s = fmaf(a0.y, Lw[(size_t)(k + 1) * CC + n], s);
            s = fmaf(a0.z, Lw[(size_t)(k + 2) * CC + n], s);
            s = fmaf(a0.w, Lw[(size_t)(k + 3) * CC + n], s);
            s = fmaf(a1.x, Lw[(size_t)(k + 4) * CC + n], s);
            s = fmaf(a1.y, Lw[(size_t)(k + 5) * CC + n], s);
            s = fmaf(a1.z, Lw[(size_t)(k + 6) * CC + n], s);
            s = fmaf(a1.w, Lw[(size_t)(k + 7) * CC + n], s);
        }
        M[idx] = s;
    }
}

// three folded gate biases: j=0 z, 1 r, 2 h
__global__ void gate_bias_all_kernel(
    const float* __restrict__ Lz_w, const float* __restrict__ Lz_b, const float* __restrict__ bz,
    const float* __restrict__ Lr_w, const float* __restrict__ Lr_b, const float* __restrict__ br,
    const float* __restrict__ Lh_w, const float* __restrict__ Lh_b, const float* __restrict__ bh,
    float* __restrict__ bvAll) {
    int j = blockIdx.y;
    int n = blockIdx.x * blockDim.x + threadIdx.x;
    if (n >= CC) return;
    const float* Lw;
    const float* Lb;
    const float* bs;
    if (j == 0)      { Lw = Lz_w; Lb = Lz_b; bs = bz; }
    else if (j == 1) { Lw = Lr_w; Lb = Lr_b; bs = br; }
    else             { Lw = Lh_w; Lb = Lh_b; bs = bh; }
    float s = Lb[n];
    for (int k = 0; k < CC; k += 8) {
#pragma unroll
        for (int q = 0; q < 8; q++)
            s = fmaf(bs[k + q], Lw[(size_t)(k + q) * CC + n], s);
    }
    bvAll[j * CC + n] = s;
}

// ---------------- bf16x3 tensor-core GEMM: BM=128, BN=128, cp.async ----------------
#define BM 128
#define BN 128
#define BKC 32
#define TSTR 40
#define PL_SZ (128 * TSTR)
#define STG  (4 * PL_SZ)
#define SMEM_BYTES (2 * STG * 2)

__device__ __forceinline__ void mma16816(float* c, const uint32_t* a, const uint32_t* b) {
    asm volatile(
        "mma.sync.aligned.m16n8k16.row.col.f32.bf16.bf16.f32 "
        "{%0,%1,%2,%3}, {%4,%5,%6,%7}, {%8,%9}, {%0,%1,%2,%3};"
        : "+f"(c[0]), "+f"(c[1]), "+f"(c[2]), "+f"(c[3])
        : "r"(a[0]), "r"(a[1]), "r"(a[2]), "r"(a[3]), "r"(b[0]), "r"(b[1]));
}

__device__ __forceinline__ void ldsm_x4(const void* p, uint32_t* r) {
    uint32_t addr = (uint32_t)__cvta_generic_to_shared(p);
    asm volatile("ldmatrix.sync.aligned.m8n8.x4.shared.b16 {%0,%1,%2,%3}, [%4];"
        : "=r"(r[0]), "=r"(r[1]), "=r"(r[2]), "=r"(r[3]) : "r"(addr));
}

__device__ __forceinline__ void cpa16(void* dst, const void* src, int sz) {
    uint32_t d = (uint32_t)__cvta_generic_to_shared(dst);
    asm volatile("cp.async.cg.shared.global [%0], [%1], 16, %2;"
                 :: "r"(d), "l"(src), "r"(sz));
}
__device__ __forceinline__ void cpa_commit() {
    asm volatile("cp.async.commit_group;");
}
template <int NW>
__device__ __forceinline__ void cpa_wait() {
    asm volatile("cp.async.wait_group %0;" :: "n"(NW));
}

// EPI: 4 relu(acc+bias)->fp32;
//      7 merged ZR (old pre-biased): col<CC -> sigmoid->Cm fp32 (ld=CC);
//        col>=CC -> sigmoid*Hp -> planes (ld=CC)
//      8 tanh(OldP_strided + acc) -> Cm fp32 (ld=N)
//      9 store(acc + bias) fp32
//      10 chain-collapse H: acc + d4*e1 + d3*e2 + d2*e3 + d1*e4 + b5;
//         write fp32 Cm + planes. Hp=dvec[4*NN], OldP=evec[4*CC].
template <int EPI>
__global__ void __launch_bounds__(256, 2) bf3_gemm(
    const __nv_bfloat16* __restrict__ Ah, const __nv_bfloat16* __restrict__ Al,
    const __nv_bfloat16* __restrict__ Bh, const __nv_bfloat16* __restrict__ Bl,
    float* __restrict__ Cm, const float* __restrict__ bias,
    const float* __restrict__ Hp,
    const float* __restrict__ OldP, int oldLd,
    __nv_bfloat16* __restrict__ oh, __nv_bfloat16* __restrict__ ol,
    int M, int N, int K) {
    extern __shared__ __align__(16) __nv_bfloat16 sm[];

    int tid = threadIdx.x;
    int m0 = blockIdx.y * BM;
    int n0 = blockIdx.x * BN;
    int warp = tid >> 5, lane = tid & 31;
    int wm = warp >> 1, wn = warp & 1;
    int g = lane >> 2, tg = lane & 3;

    float c[2][8][4];
#pragma unroll
    for (int mt = 0; mt < 2; mt++)
#pragma unroll
        for (int nt = 0; nt < 8; nt++)
#pragma unroll
            for (int i = 0; i < 4; i++) c[mt][nt][i] = 0.0f;

    int r0 = tid >> 2, q0 = tid & 3;
    int r1 = (tid + 256) >> 2, q1 = (tid + 256) & 3;

    auto load_stage = [&](int st, int k0) {
        __nv_bfloat16* Ahs = sm + st * STG;
        __nv_bfloat16* Als = Ahs + PL_SZ;
        __nv_bfloat16* Bhs = Als + PL_SZ;
        __nv_bfloat16* Bls = Bhs + PL_SZ;
#pragma unroll
        for (int i = 0; i < 2; i++) {
            int row = i == 0 ? r0 : r1;
            int q = i == 0 ? q0 : q1;
            int m = m0 + row;
            int msz = (m < M) ? 16 : 0;
            size_t asrc = (size_t)(m < M ? m : 0) * K + k0 + q * 8;
            cpa16(Ahs + row * TSTR + q * 8, Ah + asrc, msz);
            cpa16(Als + row * TSTR + q * 8, Al + asrc, msz);
            size_t bsrc = (size_t)(n0 + row) * K + k0 + q * 8;
            cpa16(Bhs + row * TSTR + q * 8, Bh + bsrc, 16);
            cpa16(Bls + row * TSTR + q * 8, Bl + bsrc, 16);
        }
        cpa_commit();
    };

    auto compute = [&](int st) {
        const __nv_bfloat16* Ahs = sm + st * STG;
        const __nv_bfloat16* Als = Ahs + PL_SZ;
        const __nv_bfloat16* Bhs = Als + PL_SZ;
        const __nv_bfloat16* Bls = Bhs + PL_SZ;
#pragma unroll
        for (int ks = 0; ks < 2; ks++) {
            uint32_t ahf[2][4], alf[2][4];
            int arow = lane & 15;
            int acol = ks * 16 + (lane >> 4) * 8;
#pragma unroll
            for (int mt = 0; mt < 2; mt++) {
                int r = wm * 32 + mt * 16 + arow;
                ldsm_x4(Ahs + r * TSTR + acol, ahf[mt]);
                ldsm_x4(Als + r * TSTR + acol, alf[mt]);
            }
            uint32_t bf[8][2];
            int bm_ = lane >> 3;
            int brow_in = lane & 7;
            int bro = (bm_ >> 1) * 8 + brow_in;
            int bco = ks * 16 + (bm_ & 1) * 8;
#pragma unroll
            for (int ntp = 0; ntp < 4; ntp++) {
                int nr = wn * 64 + ntp * 16 + bro;
                uint32_t t4[4];
                ldsm_x4(Bhs + nr * TSTR + bco, t4);
                bf[ntp * 2][0] = t4[0]; bf[ntp * 2][1] = t4[1];
                bf[ntp * 2 + 1][0] = t4[2]; bf[ntp * 2 + 1][1] = t4[3];
            }
#pragma unroll
            for (int mt = 0; mt < 2; mt++)
#pragma unroll
                for (int nt = 0; nt < 8; nt++) {
                    mma16816(c[mt][nt], ahf[mt], bf[nt]);  // hi*hi
                    mma16816(c[mt][nt], alf[mt], bf[nt]);  // lo*hi
                }
#pragma unroll
            for (int ntp = 0; ntp < 4; ntp++) {
                int nr = wn * 64 + ntp * 16 + bro;
                uint32_t t4[4];
                ldsm_x4(Bls + nr * TSTR + bco, t4);
                bf[ntp * 2][0] = t4[0]; bf[ntp * 2][1] = t4[1];
                bf[ntp * 2 + 1][0] = t4[2]; bf[ntp * 2 + 1][1] = t4[3];
            }
#pragma unroll
            for (int mt = 0; mt < 2; mt++)
#pragma unroll
                for (int nt = 0; nt < 8; nt++)
                    mma16816(c[mt][nt], ahf[mt], bf[nt]);  // hi*lo
        }
    };

    int nchunks = K / BKC;
    load_stage(0, 0);
    for (int ch = 0; ch < nchunks; ch++) {
        int st = ch & 1;
        if (ch + 1 < nchunks) {
            load_stage(st ^ 1, (ch + 1) * BKC);
            cpa_wait<1>();
        } else {
            cpa_wait<0>();
        }
        __syncthreads();
        compute(st);
        __syncthreads();
    }

#pragma unroll
    for (int mt = 0; mt < 2; mt++) {
#pragma unroll
        for (int nt = 0; nt < 8; nt++) {
            int col = n0 + wn * 64 + nt * 8 + tg * 2;
            float bv0 = 0.f, bv1 = 0.f;
            if (EPI == 4 || EPI == 9 || EPI == 10) {
                bv0 = __ldg(&bias[col]); bv1 = __ldg(&bias[col + 1]);
            }
#pragma unroll
            for (int half = 0; half < 2; half++) {
                int row = m0 + wm * 32 + mt * 16 + g + half * 8;
                if (row >= M) continue;
                float v0 = c[mt][nt][half * 2 + 0];
                float v1 = c[mt][nt][half * 2 + 1];
                if (EPI == 4) {
                    size_t off = (size_t)row * N + col;
                    *(float2*)(Cm + off) = make_float2(fmaxf(v0 + bv0, 0.0f),
                                                       fmaxf(v1 + bv1, 0.0f));
                } else if (EPI == 7) {
                    float2 old = *(const float2*)(OldP + (size_t)row * oldLd + col);
                    float a0 = old.x + v0, a1 = old.y + v1;
                    float s0 = 1.0f / (1.0f + expf(-a0));
                    float s1 = 1.0f / (1.0f + expf(-a1));
                    if (col < CC) {
                        size_t off = (size_t)row * CC + col;
                        *(float2*)(Cm + off) = make_float2(s0, s1);
                    } else {
                        int c2 = col - CC;
                        size_t off = (size_t)row * CC + c2;
                        float2 hv = *(const float2*)(Hp + off);
                        float m0v = s0 * hv.x, m1v = s1 * hv.y;
                        *(uint32_t*)(oh + off) = split_pack(m0v, m1v);
                        *(uint32_t*)(ol + off) = split_pack_lo(m0v, m1v);
                    }
                } else if (EPI == 8) {
                    float2 old = *(const float2*)(OldP + (size_t)row * oldLd + col);
                    size_t off = (size_t)row * N + col;
                    *(float2*)(Cm + off) = make_float2(tanhf(old.x + v0),
                                                       tanhf(old.y + v1));
                } else if (EPI == 9) {
                    size_t off = (size_t)row * N + col;
                    *(float2*)(Cm + off) = make_float2(v0 + bv0, v1 + bv1);
                } else if (EPI == 10) {
                    int nodei = row % NN;
                    float d1v = Hp[nodei];
                    float d2v = Hp[NN + nodei];
                    float d3v = Hp[2 * NN + nodei];
                    float d4v = Hp[3 * NN + nodei];
                    float cr0 = bv0, cr1 = bv1;
                    cr0 = fmaf(d4v, __ldg(&OldP[col]), cr0);
                    cr1 = fmaf(d4v, __ldg(&OldP[col + 1]), cr1);
                    cr0 = fmaf(d3v, __ldg(&OldP[CC + col]), cr0);
                    cr1 = fmaf(d3v, __ldg(&OldP[CC + col + 1]), cr1);
                    cr0 = fmaf(d2v, __ldg(&OldP[2 * CC + col]), cr0);
                    cr1 = fmaf(d2v, __ldg(&OldP[2 * CC + col + 1]), cr1);
                    cr0 = fmaf(d1v, __ldg(&OldP[3 * CC + col]), cr0);
                    cr1 = fmaf(d1v, __ldg(&OldP[3 * CC + col + 1]), cr1);
                    float h0 = v0 + cr0, h1 = v1 + cr1;
                    size_t off = (size_t)row * N + col;
                    *(float2*)(Cm + off) = make_float2(h0, h1);
                    *(uint32_t*)(oh + off) = split_pack(h0, h1);
                    *(uint32_t*)(ol + off) = split_pack_lo(h0, h1);
                }
            }
        }
    }
}

// ---------------- 128-wide batched propagation, unrolled x4 ----------------
// Xin fp32 [MB][FF] -> optional Xout fp32, optional bf16 planes
template <bool WF32, bool WPL>
__global__ void __launch_bounds__(128) prop128_kernel(
    const float* __restrict__ Xin, float* __restrict__ Xout,
    __nv_bfloat16* __restrict__ oh, __nv_bfloat16* __restrict__ ol) {
    int r = blockIdx.x * 4 + (threadIdx.x >> 5);
    int t = threadIdx.x & 31;
    if (r >= MB) return;
    int p = r / NN;
    int i = r - p * NN;
    const float4* X4 = (const float4*)Xin;
    float sn = g_normself[i];
    float4 v = X4[(size_t)r * F4 + t];
    float4 acc = make_float4(sn * v.x, sn * v.y, sn * v.z, sn * v.w);
    int beg = g_rowptr[i];
    int end = g_rowptr[i + 1];
    int base = p * NN;
    int e = beg;
    for (; e + 4 <= end; e += 4) {
        int s0 = g_csrsrc[e], s1 = g_csrsrc[e + 1];
        int s2 = g_csrsrc[e + 2], s3 = g_csrsrc[e + 3];
        float w0 = g_csrnorm[e], w1 = g_csrnorm[e + 1];
        float w2 = g_csrnorm[e + 2], w3 = g_csrnorm[e + 3];
        float4 u0 = X4[(size_t)(base + s0) * F4 + t];
        float4 u1 = X4[(size_t)(base + s1) * F4 + t];
        float4 u2 = X4[(size_t)(base + s2) * F4 + t];
        float4 u3 = X4[(size_t)(base + s3) * F4 + t];
        acc.x = fmaf(w0, u0.x, acc.x); acc.y = fmaf(w0, u0.y, acc.y);
        acc.z = fmaf(w0, u0.z, acc.z); acc.w = fmaf(w0, u0.w, acc.w);
        acc.x = fmaf(w1, u1.x, acc.x); acc.y = fmaf(w1, u1.y, acc.y);
        acc.z = fmaf(w1, u1.z, acc.z); acc.w = fmaf(w1, u1.w, acc.w);
        acc.x = fmaf(w2, u2.x, acc.x); acc.y = fmaf(w2, u2.y, acc.y);
        acc.z = fmaf(w2, u2.z, acc.z); acc.w = fmaf(w2, u2.w, acc.w);
        acc.x = fmaf(w3, u3.x, acc.x); acc.y = fmaf(w3, u3.y, acc.y);
        acc.z = fmaf(w3, u3.z, acc.z); acc.w = fmaf(w3, u3.w, acc.w);
    }
    for (; e < end; e++) {
        int s = g_csrsrc[e];
        float w = g_csrnorm[e];
        float4 u = X4[(size_t)(base + s) * F4 + t];
        acc.x = fmaf(w, u.x, acc.x);
        acc.y = fmaf(w, u.y, acc.y);
        acc.z = fmaf(w, u.z, acc.z);
        acc.w = fmaf(w, u.w, acc.w);
    }
    if (WF32) ((float4*)Xout)[(size_t)r * F4 + t] = acc;
    if (WPL) {
        size_t off = (size_t)r * FF + t * 4;
        *(uint32_t*)(oh + off) = split_pack(acc.x, acc.y);
        *(uint32_t*)(oh + off + 2) = split_pack(acc.z, acc.w);
        *(uint32_t*)(ol + off) = split_pack_lo(acc.x, acc.y);
        *(uint32_t*)(ol + off + 2) = split_pack_lo(acc.z, acc.w);
    }
}

// ---------------- elementwise kernels ----------------
__global__ void extract_all_kernel(const float* __restrict__ x, float* __restrict__ Xp) {
    int idx = blockIdx.x * blockDim.x + threadIdx.x;
    if (idx < NN * FF) {
        float4 v = ((const float4*)x)[idx];
        Xp[idx] = v.x;
        Xp[NN * FF + idx] = v.y;
        Xp[2 * NN * FF + idx] = v.z;
        Xp[3 * NN * FF + idx] = v.w;
    }
}

__global__ void gru_reduce_kernel(const float* __restrict__ Z, const float* __restrict__ H,
                                  const float* __restrict__ Ht, float* __restrict__ out,
                                  __nv_bfloat16* __restrict__ oh, __nv_bfloat16* __restrict__ ol) {
    int idx = blockIdx.x * blockDim.x + threadIdx.x;
    if (idx >= NN * C4) return;
    int i = idx >> 7;
    int t = idx & 127;
    float4 acc = make_float4(0.f, 0.f, 0.f, 0.f);
#pragma unroll
    for (int p = 0; p < PP; p++) {
        size_t o4 = (size_t)(p * NN + i) * C4 + t;
        float4 z = ((const float4*)Z)[o4];
        float4 h = ((const float4*)H)[o4];
        float4 ht = ((const float4*)Ht)[o4];
        float pr = g_probs[p];
        acc.x += pr * (z.x * h.x + (1.0f - z.x) * ht.x);
        acc.y += pr * (z.y * h.y + (1.0f - z.y) * ht.y);
        acc.z += pr * (z.z * h.z + (1.0f - z.z) * ht.z);
        acc.w += pr * (z.w * h.w + (1.0f - z.w) * ht.w);
    }
    ((float4*)(out + NN))[idx] = acc;
    float4 v = make_float4(fmaxf(acc.x, 0.f), fmaxf(acc.y, 0.f),
                           fmaxf(acc.z, 0.f), fmaxf(acc.w, 0.f));
    size_t off = (size_t)idx * 4;
    *(uint32_t*)(oh + off) = split_pack(v.x, v.y);
    *(uint32_t*)(oh + off + 2) = split_pack(v.z, v.w);
    *(uint32_t*)(ol + off) = split_pack_lo(v.x, v.y);
    *(uint32_t*)(ol + off + 2) = split_pack_lo(v.z, v.w);
}

__global__ void lin2_kernel(const float* __restrict__ hid, const float* __restrict__ w,
                            const float* __restrict__ b, float* __restrict__ out) {
    int n = blockIdx.x * 8 + (threadIdx.x >> 5);
    int lane = threadIdx.x & 31;
    float s = 0.0f;
    for (int k = lane; k < HIDN; k += 32) s = fmaf(hid[(size_t)n * HIDN + k], w[k], s);
#pragma unroll
    for (int off = 16; off; off >>= 1) s += __shfl_down_sync(0xffffffffu, s, off);
    if (lane == 0) out[n] = s + b[0];
}

// ---------------- host orchestration ----------------
#define GP(sym) ({ void* _p; cudaGetSymbolAddress(&_p, sym); (__nv_bfloat16*)_p; })
#define GPF(sym) ({ void* _p; cudaGetSymbolAddress(&_p, sym); (float*)_p; })

struct GemmArgs {
    const __nv_bfloat16 *Ah, *Al, *Bh, *Bl;
    float* Cm;
    const float* bias;
    const float* Hp;
    const float* OldP;
    int oldLd;
    __nv_bfloat16 *oh, *ol;
    int M, N, K;
};

template <int EPI>
static inline void launch_gemm(const GemmArgs& a) {
    dim3 grid(a.N / BN, (a.M + BM - 1) / BM);
    bf3_gemm<EPI><<<grid, 256, SMEM_BYTES>>>(a.Ah, a.Al, a.Bh, a.Bl, a.Cm, a.bias,
                                             a.Hp, a.OldP, a.oldLd, a.oh, a.ol,
                                             a.M, a.N, a.K);
}

static inline void launch_wts(const float* W, int k0, int N, int Kb,
                              __nv_bfloat16* oh, __nv_bfloat16* ol) {
    dim3 grid(N / 32, Kb / 32);
    wt_split_kernel<<<grid, 256>>>(W, k0, N, Kb, oh, ol);
}

extern "C" void kernel_launch(void* const* d_in, const int* in_sizes, int n_in,
                              void* d_out, int out_size) {
    const float* x     = (const float*)d_in[0];
    const int*   ei    = (const int*)d_in[1];
    const float* ea    = (const float*)d_in[2];
    const float* W1    = (const float*)d_in[3];
    const float* b1    = (const float*)d_in[4];
    const float* W2    = (const float*)d_in[5];
    const float* b2    = (const float*)d_in[6];
    const float* W3    = (const float*)d_in[7];
    const float* b3    = (const float*)d_in[8];
    const float* W4    = (const float*)d_in[9];
    const float* b4    = (const float*)d_in[10];
    const float* W5    = (const float*)d_in[11];
    const float* b5    = (const float*)d_in[12];
    const float* Wz    = (const float*)d_in[13];
    const float* bz    = (const float*)d_in[14];
    const float* Lz_w  = (const float*)d_in[15];
    const float* Lz_b  = (const float*)d_in[16];
    const float* Wr    = (const float*)d_in[17];
    const float* br    = (const float*)d_in[18];
    const float* Lr_w  = (const float*)d_in[19];
    const float* Lr_b  = (const float*)d_in[20];
    const float* Wh    = (const float*)d_in[21];
    const float* bh    = (const float*)d_in[22];
    const float* Lh_w  = (const float*)d_in[23];
    const float* Lh_b  = (const float*)d_in[24];
    const float* attn  = (const float*)d_in[25];
    const float* lin1w = (const float*)d_in[26];
    const float* lin1b = (const float*)d_in[27];
    const float* lin2w = (const float*)d_in[28];
    const float* lin2b = (const float*)d_in[29];
    float* out = (float*)d_out;

    static bool attr_done = false;
    if (!attr_done) {
        cudaFuncSetAttribute(bf3_gemm<4>, cudaFuncAttributeMaxDynamicSharedMemorySize, SMEM_BYTES);
        cudaFuncSetAttribute(bf3_gemm<7>, cudaFuncAttributeMaxDynamicSharedMemorySize, SMEM_BYTES);
        cudaFuncSetAttribute(bf3_gemm<8>, cudaFuncAttributeMaxDynamicSharedMemorySize, SMEM_BYTES);
        cudaFuncSetAttribute(bf3_gemm<9>, cudaFuncAttributeMaxDynamicSharedMemorySize, SMEM_BYTES);
        cudaFuncSetAttribute(bf3_gemm<10>, cudaFuncAttributeMaxDynamicSharedMemorySize, SMEM_BYTES);
        attr_done = true;
    }

    float* pXp   = GPF(g_Xp);
    float* pXA   = GPF(g_XA);
    float* pXB   = GPF(g_XB);
    float* pH    = GPF(g_H);
    float* pZ    = GPF(g_Z);
    float* pHt   = GPF(g_Ht);
    float* pGC   = GPF(g_GC);
    float* phid1 = GPF(g_hid1);
    float* pMtmp = GPF(g_Mtmp);
    float* pMtmp2 = GPF(g_Mtmp2);
    float* pbvAll = GPF(g_bvAll);
    float* pev   = GPF(g_ev);
    float* pvt1  = GPF(g_vt1);
    float* pvt2  = GPF(g_vt2);
    float* pdv   = GPF(g_dv);

    __nv_bfloat16 *pXsh = GP(g_Xsh), *pXsl = GP(g_Xsl);
    __nv_bfloat16 *pX5h = GP(g_X5h), *pX5l = GP(g_X5l);
    __nv_bfloat16 *pHh = GP(g_Hh), *pHl = GP(g_Hl);
    __nv_bfloat16 *pRmh = GP(g_Rmh), *pRml = GP(g_Rml);
    __nv_bfloat16 *pRAh = GP(g_RAh), *pRAl = GP(g_RAl);

    __nv_bfloat16 *pWCh = GP(g_WCh), *pWCl = GP(g_WCl);
    __nv_bfloat16 *pMFh = GP(g_MFh), *pMFl = GP(g_MFl);
    __nv_bfloat16 *pLzr2h = GP(g_Lzr2h), *pLzr2l = GP(g_Lzr2l);
    __nv_bfloat16 *pLh2h = GP(g_Lh2h), *pLh2l = GP(g_Lh2l);
    __nv_bfloat16 *pL1th = GP(g_L1th), *pL1tl = GP(g_L1tl);

    const int gE  = (EE + 255) / 256;
    const int gN  = (NN + 255) / 256;
    const int gNC4 = (NN * C4 + 255) / 256;
    const int gNF = (NN * FF + 255) / 256;
    const int gW128 = (CC * FF + 255) / 256;

    // graph setup + CSR
    init_node_arrays<<<gN, 256>>>();
    deg_edges_kernel<<<gE, 256>>>(ei, ea);
    deg_finalize_kernel<<<gN, 256>>>();
    scan_kernel<<<1, 1024>>>();
    scatter_kernel<<<gE, 256>>>(ei, ea);
    softmax4_kernel<<<1, 32>>>(attn);

    // d vectors: d1..d4 = S^k * 1
    d_iter_kernel<<<gN, 256>>>(nullptr, pdv);
    d_iter_kernel<<<gN, 256>>>(pdv, pdv + NN);
    d_iter_kernel<<<gN, 256>>>(pdv + NN, pdv + 2 * NN);
    d_iter_kernel<<<gN, 256>>>(pdv + 2 * NN, pdv + 3 * NN);

    // e vectors: e1=b1W2W3W4W5, e2=b2W3W4W5, e3=b3W4W5, e4=b4W5
    vecmat_kernel<<<2, 256>>>(b4, W5, pev + 3 * CC);
    vecmat_kernel<<<2, 256>>>(b3, W4, pvt1);
    vecmat_kernel<<<2, 256>>>(pvt1, W5, pev + 2 * CC);
    vecmat_kernel<<<2, 256>>>(b2, W3, pvt1);
    vecmat_kernel<<<2, 256>>>(pvt1, W4, pvt2);
    vecmat_kernel<<<2, 256>>>(pvt2, W5, pev + CC);
    vecmat_kernel<<<2, 256>>>(b1, W2, pvt1);
    vecmat_kernel<<<2, 256>>>(pvt1, W3, pvt2);
    vecmat_kernel<<<2, 256>>>(pvt2, W4, pvt1);
    vecmat_kernel<<<2, 256>>>(pvt1, W5, pev);

    // gate/tail weights
    launch_wts(Lz_w, CC, CC, CC, pLzr2h, pLzr2l);
    launch_wts(Lr_w, CC, CC, CC, pLzr2h + (size_t)CC * CC, pLzr2l + (size_t)CC * CC);
    launch_wts(Lh_w, CC, CC, CC, pLh2h, pLh2l);
    launch_wts(lin1w, 0, HIDN, CC, pL1th, pL1tl);

    // chain fold W~ = W1@W2@W3@W4@W5 (fp32) -> split planes
    gatefold_kernel<<<gW128, 256>>>(W1, W2, pMtmp);
    gatefold_kernel<<<gW128, 256>>>(pMtmp, W3, pMtmp2);
    gatefold_kernel<<<gW128, 256>>>(pMtmp2, W4, pMtmp);
    gatefold_kernel<<<gW128, 256>>>(pMtmp, W5, pMtmp2);
    launch_wts(pMtmp2, 0, CC, FF, pWCh, pWCl);

    // gate folds [Mz|Mr|Mh]^T and biases [bvz|bvr|bvh]
    gatefold_kernel<<<gW128, 256>>>(Wz, Lz_w, pMtmp);
    launch_wts(pMtmp, 0, CC, FF, pMFh, pMFl);
    gatefold_kernel<<<gW128, 256>>>(Wr, Lr_w, pMtmp);
    launch_wts(pMtmp, 0, CC, FF, pMFh + (size_t)CC * FF, pMFl + (size_t)CC * FF);
    gatefold_kernel<<<gW128, 256>>>(Wh, Lh_w, pMtmp);
    launch_wts(pMtmp, 0, CC, FF, pMFh + (size_t)2 * CC * FF, pMFl + (size_t)2 * CC * FF);
    {
        dim3 grid(2, 3);
        gate_bias_all_kernel<<<grid, 256>>>(Lz_w, Lz_b, bz, Lr_w, Lr_b, br,
                                            Lh_w, Lh_b, bh, pbvAll);
    }

    // ---- batched across all 4 timesteps (M = 40000) ----
    extract_all_kernel<<<gNF, 256>>>(x, pXp);

    const int gP = (MB + 3) / 4;
    // X1 = S Xp (fp32 + planes for gates)
    prop128_kernel<true, true><<<gP, 128>>>(pXp, pXA, pXsh, pXsl);
    // front gates: GC = X1 @ [Mz|Mr|Mh] + [bvz|bvr|bvh]
    GemmArgs a{};
    a = {pXsh, pXsl, pMFh, pMFl, pGC, pbvAll, nullptr, nullptr, 0,
         nullptr, nullptr, MB, NFR, FF};
    launch_gemm<9>(a);
    // X2..X4 fp32 only; X5 planes only
    prop128_kernel<true, false><<<gP, 128>>>(pXA, pXB, nullptr, nullptr);
    prop128_kernel<true, false><<<gP, 128>>>(pXB, pXA, nullptr, nullptr);
    prop128_kernel<true, false><<<gP, 128>>>(pXA, pXB, nullptr, nullptr);
    prop128_kernel<false, true><<<gP, 128>>>(pXB, nullptr, pX5h, pX5l);

    // H = X5 @ W~ + rank-4 bias correction + b5 (fp32 + planes)
    a = {pX5h, pX5l, pWCh, pWCl, pH, b5, pdv, pev, 0,
         pHh, pHl, MB, CC, FF};
    launch_gemm<10>(a);

    // merged ZR: [Z|R] = sigmoid(GC[:,0:1024] + H@[Lz2|Lr2])
    a = {pHh, pHl, pLzr2h, pLzr2l, pZ, nullptr, pH, pGC, NFR,
         pRmh, pRml, MB, 2 * CC, CC};
    launch_gemm<7>(a);

    // Ht = tanh(GC[:,1024:1536] + Rm@Lh2)
    a = {pRmh, pRml, pLh2h, pLh2l, pHt, nullptr, nullptr, pGC + 2 * CC, NFR,
         nullptr, nullptr, MB, CC, CC};
    launch_gemm<8>(a);

    gru_reduce_kernel<<<gNC4, 256>>>(pZ, pH, pHt, out, pRAh, pRAl);

    a = {pRAh, pRAl, pL1th, pL1tl, phid1, lin1b, nullptr, nullptr, 0,
         nullptr, nullptr, NN, HIDN, CC};
    launch_gemm<4>(a);
    lin2_kernel<<<(NN + 7) / 8, 256>>>(phid1, lin2w, lin2b, out);
}

// round 15
// speedup vs baseline: 1.4586x; 1.0084x over previous
#include <cuda_runtime.h>
#include <cuda_bf16.h>
#include <stdint.h>
#include <math.h>

#define NN 10000
#define FF 128
#define PP 4
#define EE 160000
#define CC 512
#define HIDN 256
#define C4 (CC/4)
#define F4 (FF/4)
#define MB (NN*PP)
#define NFR 1536             /* merged gate width [Gz|Gr|Gh] */
#define NZR (2*CC)           /* ZR width 1024 */

// ---------------- scratch (static device memory; no allocations) ----------------
__device__ float g_deg[NN];
__device__ float g_dinv[NN];
__device__ float g_normself[NN];
__device__ int   g_counts[NN];
__device__ int   g_rowptr[NN + 1];
__device__ int   g_cursor[NN];
__device__ int   g_csrsrc[EE];
__device__ float g_csrnorm[EE];
__device__ float g_probs[PP];

__device__ float g_Xp[MB * FF];
__device__ float g_XA[MB * FF];
__device__ float g_XB[MB * FF];
__device__ float g_H[MB * CC];
__device__ float g_Z[MB * CC];
__device__ float g_Ht[MB * CC];
__device__ float g_GC[MB * NFR];
__device__ float g_hid1[NN * HIDN];
__device__ float g_Mtmp[FF * CC];
__device__ float g_Mtmp2[FF * CC];
__device__ float g_Wc[FF * CC];       // W1..W5 folded (fp32)
__device__ float g_bvAll[NFR];        // [bvz+b5Lz2 | bvr+b5Lr2 | bvh]
__device__ float g_ev[4 * CC];        // e1|e2|e3|e4
__device__ float g_Ev[4 * NZR];       // e_k @ [Lz2|Lr2]
__device__ float g_vt1[CC], g_vt2[CC];
__device__ float g_dv[4 * NN];        // d1|d2|d3|d4

__device__ __nv_bfloat16 g_Xsh[MB * FF], g_Xsl[MB * FF];   // X1 planes
__device__ __nv_bfloat16 g_X5h[MB * FF], g_X5l[MB * FF];   // X5 planes
__device__ __nv_bfloat16 g_Rmh[MB * CC], g_Rml[MB * CC];
__device__ __nv_bfloat16 g_RAh[NN * CC], g_RAl[NN * CC];

__device__ __nv_bfloat16 g_WCh[CC * FF], g_WCl[CC * FF];       // W~^T
__device__ __nv_bfloat16 g_MZRh[NZR * FF], g_MZRl[NZR * FF];   // (W~[Lz2|Lr2])^T
__device__ __nv_bfloat16 g_MFh[NFR * FF], g_MFl[NFR * FF];     // [Mz|Mr|Mh]^T
__device__ __nv_bfloat16 g_Lh2h[CC * CC], g_Lh2l[CC * CC];
__device__ __nv_bfloat16 g_L1th[HIDN * CC], g_L1tl[HIDN * CC];

__device__ __forceinline__ void split_bf(float x, __nv_bfloat16& h, __nv_bfloat16& l) {
    h = __float2bfloat16(x);
    l = __float2bfloat16(x - __bfloat162float(h));
}
__device__ __forceinline__ uint32_t pack_bf2(__nv_bfloat16 a, __nv_bfloat16 b) {
    __nv_bfloat162 t(a, b);
    return *(uint32_t*)&t;
}
__device__ __forceinline__ uint32_t split_pack(float a, float b) {
    __nv_bfloat16 h0, l0, h1, l1;
    split_bf(a, h0, l0); split_bf(b, h1, l1);
    return pack_bf2(h0, h1);
}
__device__ __forceinline__ uint32_t split_pack_lo(float a, float b) {
    __nv_bfloat16 h0, l0, h1, l1;
    split_bf(a, h0, l0); split_bf(b, h1, l1);
    return pack_bf2(l0, l1);
}

// ---------------- graph setup kernels ----------------
__global__ void init_node_arrays() {
    int i = blockIdx.x * blockDim.x + threadIdx.x;
    if (i < NN) { g_deg[i] = 0.0f; g_counts[i] = 0; g_cursor[i] = 0; }
}

__global__ void deg_edges_kernel(const int* __restrict__ ei, const float* __restrict__ ea) {
    int e = blockIdx.x * blockDim.x + threadIdx.x;
    if (e < EE) {
        int dst = ei[EE + e];
        atomicAdd(&g_deg[dst], ea[e]);
        atomicAdd(&g_counts[dst], 1);
    }
}

__global__ void deg_finalize_kernel() {
    int i = blockIdx.x * blockDim.x + threadIdx.x;
    if (i < NN) {
        float d = g_deg[i] + 1.0f;
        float di = (d > 0.0f) ? rsqrtf(d) : 0.0f;
        g_dinv[i] = di;
        g_normself[i] = di * di;
    }
}

__global__ void scan_kernel() {
    __shared__ int part[1024];
    const int per = 10;
    int t = threadIdx.x;
    int base = t * per;
    int loc[per];
    int s = 0;
#pragma unroll
    for (int i = 0; i < per; i++) {
        int idx = base + i;
        int v = (idx < NN) ? g_counts[idx] : 0;
        loc[i] = s; s += v;
    }
    part[t] = s;
    __syncthreads();
    for (int off = 1; off < 1024; off <<= 1) {
        int v = (t >= off) ? part[t - off] : 0;
        __syncthreads();
        part[t] += v;
        __syncthreads();
    }
    int offb = (t == 0) ? 0 : part[t - 1];
#pragma unroll
    for (int i = 0; i < per; i++) {
        int idx = base + i;
        if (idx < NN) g_rowptr[idx] = offb + loc[i];
    }
    if (t == 1023) g_rowptr[NN] = part[1023];
}

__global__ void scatter_kernel(const int* __restrict__ ei, const float* __restrict__ ea) {
    int e = blockIdx.x * blockDim.x + threadIdx.x;
    if (e < EE) {
        int src = ei[e];
        int dst = ei[EE + e];
        float nv = g_dinv[src] * ea[e] * g_dinv[dst];
        int pos = atomicAdd(&g_cursor[dst], 1);
        int slot = g_rowptr[dst] + pos;
        g_csrsrc[slot] = src;
        g_csrnorm[slot] = nv;
    }
}

__global__ void softmax4_kernel(const float* __restrict__ attn) {
    if (threadIdx.x == 0 && blockIdx.x == 0) {
        float m = attn[0];
        for (int p = 1; p < PP; p++) m = fmaxf(m, attn[p]);
        float s = 0.0f, e[PP];
        for (int p = 0; p < PP; p++) { e[p] = expf(attn[p] - m); s += e[p]; }
        for (int p = 0; p < PP; p++) g_probs[p] = e[p] / s;
    }
}

__global__ void d_iter_kernel(const float* __restrict__ din, float* __restrict__ dout) {
    int i = blockIdx.x * blockDim.x + threadIdx.x;
    if (i >= NN) return;
    float self = (din != nullptr) ? din[i] : 1.0f;
    float acc = g_normself[i] * self;
    int beg = g_rowptr[i], end = g_rowptr[i + 1];
    for (int e = beg; e < end; e++) {
        float u = (din != nullptr) ? din[g_csrsrc[e]] : 1.0f;
        acc = fmaf(g_csrnorm[e], u, acc);
    }
    dout[i] = acc;
}

// out[n] = sum_k v[k]*W[k*CC+n]
__global__ void vecmat_kernel(const float* __restrict__ v, const float* __restrict__ W,
                              float* __restrict__ out) {
    int n = blockIdx.x * blockDim.x + threadIdx.x;
    if (n >= CC) return;
    float s = 0.0f;
    for (int k = 0; k < CC; k += 8) {
#pragma unroll
        for (int j = 0; j < 8; j++)
            s = fmaf(v[k + j], W[(size_t)(k + j) * CC + n], s);
    }
    out[n] = s;
}

// out[n] += sum_k v[k]*W[k*CC+n]
__global__ void vecmat_add_kernel(const float* __restrict__ v, const float* __restrict__ W,
                                  float* __restrict__ out) {
    int n = blockIdx.x * blockDim.x + threadIdx.x;
    if (n >= CC) return;
    float s = 0.0f;
    for (int k = 0; k < CC; k += 8) {
#pragma unroll
        for (int j = 0; j < 8; j++)
            s = fmaf(v[k + j], W[(size_t)(k + j) * CC + n], s);
    }
    out[n] += s;
}

// tiled transpose+split: out[n*Kb+k] = split(W[(k0+k)*N + n])
__global__ void wt_split_kernel(const float* __restrict__ W, int k0, int N, int Kb,
                                __nv_bfloat16* __restrict__ oh, __nv_bfloat16* __restrict__ ol) {
    __shared__ float tile[32][33];
    int nt = blockIdx.x * 32;
    int kt = blockIdx.y * 32;
    int tx = threadIdx.x & 31;
    int ty = threadIdx.x >> 5;
#pragma unroll
    for (int j = 0; j < 32; j += 8)
        tile[ty + j][tx] = W[(size_t)(k0 + kt + ty + j) * N + nt + tx];
    __syncthreads();
#pragma unroll
    for (int j = 0; j < 32; j += 8) {
        int n = nt + ty + j;
        int k = kt + tx;
        float v = tile[tx][ty + j];
        __nv_bfloat16 h, l;
        split_bf(v, h, l);
        oh[(size_t)n * Kb + k] = h;
        ol[(size_t)n * Kb + k] = l;
    }
}

// M[f][n] = sum_k A[f][k] * Lw[k][n]   (fp32, 128x512x512)
__global__ void gatefold_kernel(const float* __restrict__ A, const float* __restrict__ Lw,
                                float* __restrict__ M) {
    int idx = blockIdx.x * blockDim.x + threadIdx.x;
    if (idx < FF * CC) {
        int f = idx / CC, n = idx - f * CC;
        float s = 0.0f;
        for (int k = 0; k < CC; k += 8) {
            float4 a0 = *(const float4*)&A[(size_t)f * CC + k];
            float4 a1 = *(const float4*)&A[(size_t)f * CC + k + 4];
            s = fmaf(a0.x, Lw[(size_t)(k + 0) * CC + n], s);
            s = fmaf(a0.y, Lw[(size_t)(k + 1) * CC + n], s);
            s = fmaf(a0.z, Lw[(size_t)(k + 2) * CC + n], s);
            s = fmaf(a0.w, Lw[(size_t)(k + 3) * CC + n], s);
            s = fmaf(a1.x, Lw[(size_t)(k + 4) * CC + n], s);
            s = fmaf(a1.y, Lw[(size_t)(k + 5) * CC + n], s);
            s = fmaf(a1.z, Lw[(size_t)(k + 6) * CC + n], s);
            s = fmaf(a1.w, Lw[(size_t)(k + 7) * CC + n], s);
        }
        M[idx] = s;
    }
}

// three folded gate biases: j=0 z, 1 r, 2 h
__global__ void gate_bias_all_kernel(
    const float* __restrict__ Lz_w, const float* __restrict__ Lz_b, const float* __restrict__ bz,
    const float* __restrict__ Lr_w, const float* __restrict__ Lr_b, const float* __restrict__ br,
    const float* __restrict__ Lh_w, const float* __restrict__ Lh_b, const float* __restrict__ bh,
    float* __restrict__ bvAll) {
    int j = blockIdx.y;
    int n = blockIdx.x * blockDim.x + threadIdx.x;
    if (n >= CC) return;
    const float* Lw;
    const float* Lb;
    const float* bs;
    if (j == 0)      { Lw = Lz_w; Lb = Lz_b; bs = bz; }
    else if (j == 1) { Lw = Lr_w; Lb = Lr_b; bs = br; }
    else             { Lw = Lh_w; Lb = Lh_b; bs = bh; }
    float s = Lb[n];
    for (int k = 0; k < CC; k += 8) {
#pragma unroll
        for (int q = 0; q < 8; q++)
            s = fmaf(bs[k + q], Lw[(size_t)(k + q) * CC + n], s);
    }
    bvAll[j * CC + n] = s;
}

// ---------------- bf16x3 tensor-core GEMM: BM=128, BN=128, cp.async ----------------
#define BM 128
#define BN 128
#define BKC 32
#define TSTR 40
#define PL_SZ (128 * TSTR)
#define STG  (4 * PL_SZ)
#define SMEM_BYTES (2 * STG * 2)

__device__ __forceinline__ void mma16816(float* c, const uint32_t* a, const uint32_t* b) {
    asm volatile(
        "mma.sync.aligned.m16n8k16.row.col.f32.bf16.bf16.f32 "
        "{%0,%1,%2,%3}, {%4,%5,%6,%7}, {%8,%9}, {%0,%1,%2,%3};"
        : "+f"(c[0]), "+f"(c[1]), "+f"(c[2]), "+f"(c[3])
        : "r"(a[0]), "r"(a[1]), "r"(a[2]), "r"(a[3]), "r"(b[0]), "r"(b[1]));
}

__device__ __forceinline__ void ldsm_x4(const void* p, uint32_t* r) {
    uint32_t addr = (uint32_t)__cvta_generic_to_shared(p);
    asm volatile("ldmatrix.sync.aligned.m8n8.x4.shared.b16 {%0,%1,%2,%3}, [%4];"
        : "=r"(r[0]), "=r"(r[1]), "=r"(r[2]), "=r"(r[3]) : "r"(addr));
}

__device__ __forceinline__ void cpa16(void* dst, const void* src, int sz) {
    uint32_t d = (uint32_t)__cvta_generic_to_shared(dst);
    asm volatile("cp.async.cg.shared.global [%0], [%1], 16, %2;"
                 :: "r"(d), "l"(src), "r"(sz));
}
__device__ __forceinline__ void cpa_commit() {
    asm volatile("cp.async.commit_group;");
}
template <int NW>
__device__ __forceinline__ void cpa_wait() {
    asm volatile("cp.async.wait_group %0;" :: "n"(NW));
}

// EPI: 4 relu(acc+bias)->fp32;
//      8 tanh(OldP_strided + acc) -> Cm fp32 (ld=N)
//      9 store(acc + bias) fp32
//      10 chain-collapse H: acc + d4*e1 + d3*e2 + d2*e3 + d1*e4 + b5 -> fp32 (+planes if oh)
//         Dv=dvec[4*NN], Ev=evec[4*CC] (row stride CC)
//      11 ZR from X5: sigmoid(OldP_strided + acc + d-correction via Ev[4][NZR]);
//         col<CC -> Z fp32 (ld=CC); col>=CC -> sigmoid*Hp -> Rm planes (ld=CC)
template <int EPI>
__global__ void __launch_bounds__(256, 2) bf3_gemm(
    const __nv_bfloat16* __restrict__ Ah, const __nv_bfloat16* __restrict__ Al,
    const __nv_bfloat16* __restrict__ Bh, const __nv_bfloat16* __restrict__ Bl,
    float* __restrict__ Cm, const float* __restrict__ bias,
    const float* __restrict__ Hp,
    const float* __restrict__ OldP, int oldLd,
    const float* __restrict__ Dv, const float* __restrict__ Ev,
    __nv_bfloat16* __restrict__ oh, __nv_bfloat16* __restrict__ ol,
    int M, int N, int K) {
    extern __shared__ __align__(16) __nv_bfloat16 sm[];

    int tid = threadIdx.x;
    int m0 = blockIdx.y * BM;
    int n0 = blockIdx.x * BN;
    int warp = tid >> 5, lane = tid & 31;
    int wm = warp >> 1, wn = warp & 1;
    int g = lane >> 2, tg = lane & 3;

    float c[2][8][4];
#pragma unroll
    for (int mt = 0; mt < 2; mt++)
#pragma unroll
        for (int nt = 0; nt < 8; nt++)
#pragma unroll
            for (int i = 0; i < 4; i++) c[mt][nt][i] = 0.0f;

    int r0 = tid >> 2, q0 = tid & 3;
    int r1 = (tid + 256) >> 2, q1 = (tid + 256) & 3;

    auto load_stage = [&](int st, int k0) {
        __nv_bfloat16* Ahs = sm + st * STG;
        __nv_bfloat16* Als = Ahs + PL_SZ;
        __nv_bfloat16* Bhs = Als + PL_SZ;
        __nv_bfloat16* Bls = Bhs + PL_SZ;
#pragma unroll
        for (int i = 0; i < 2; i++) {
            int row = i == 0 ? r0 : r1;
            int q = i == 0 ? q0 : q1;
            int m = m0 + row;
            int msz = (m < M) ? 16 : 0;
            size_t asrc = (size_t)(m < M ? m : 0) * K + k0 + q * 8;
            cpa16(Ahs + row * TSTR + q * 8, Ah + asrc, msz);
            cpa16(Als + row * TSTR + q * 8, Al + asrc, msz);
            size_t bsrc = (size_t)(n0 + row) * K + k0 + q * 8;
            cpa16(Bhs + row * TSTR + q * 8, Bh + bsrc, 16);
            cpa16(Bls + row * TSTR + q * 8, Bl + bsrc, 16);
        }
        cpa_commit();
    };

    auto compute = [&](int st) {
        const __nv_bfloat16* Ahs = sm + st * STG;
        const __nv_bfloat16* Als = Ahs + PL_SZ;
        const __nv_bfloat16* Bhs = Als + PL_SZ;
        const __nv_bfloat16* Bls = Bhs + PL_SZ;
#pragma unroll
        for (int ks = 0; ks < 2; ks++) {
            uint32_t ahf[2][4], alf[2][4];
            int arow = lane & 15;
            int acol = ks * 16 + (lane >> 4) * 8;
#pragma unroll
            for (int mt = 0; mt < 2; mt++) {
                int r = wm * 32 + mt * 16 + arow;
                ldsm_x4(Ahs + r * TSTR + acol, ahf[mt]);
                ldsm_x4(Als + r * TSTR + acol, alf[mt]);
            }
            uint32_t bf[8][2];
            int bm_ = lane >> 3;
            int brow_in = lane & 7;
            int bro = (bm_ >> 1) * 8 + brow_in;
            int bco = ks * 16 + (bm_ & 1) * 8;
#pragma unroll
            for (int ntp = 0; ntp < 4; ntp++) {
                int nr = wn * 64 + ntp * 16 + bro;
                uint32_t t4[4];
                ldsm_x4(Bhs + nr * TSTR + bco, t4);
                bf[ntp * 2][0] = t4[0]; bf[ntp * 2][1] = t4[1];
                bf[ntp * 2 + 1][0] = t4[2]; bf[ntp * 2 + 1][1] = t4[3];
            }
#pragma unroll
            for (int mt = 0; mt < 2; mt++)
#pragma unroll
                for (int nt = 0; nt < 8; nt++) {
                    mma16816(c[mt][nt], ahf[mt], bf[nt]);  // hi*hi
                    mma16816(c[mt][nt], alf[mt], bf[nt]);  // lo*hi
                }
#pragma unroll
            for (int ntp = 0; ntp < 4; ntp++) {
                int nr = wn * 64 + ntp * 16 + bro;
                uint32_t t4[4];
                ldsm_x4(Bls + nr * TSTR + bco, t4);
                bf[ntp * 2][0] = t4[0]; bf[ntp * 2][1] = t4[1];
                bf[ntp * 2 + 1][0] = t4[2]; bf[ntp * 2 + 1][1] = t4[3];
            }
#pragma unroll
            for (int mt = 0; mt < 2; mt++)
#pragma unroll
                for (int nt = 0; nt < 8; nt++)
                    mma16816(c[mt][nt], ahf[mt], bf[nt]);  // hi*lo
        }
    };

    int nchunks = K / BKC;
    load_stage(0, 0);
    for (int ch = 0; ch < nchunks; ch++) {
        int st = ch & 1;
        if (ch + 1 < nchunks) {
            load_stage(st ^ 1, (ch + 1) * BKC);
            cpa_wait<1>();
        } else {
            cpa_wait<0>();
        }
        __syncthreads();
        compute(st);
        __syncthreads();
    }

#pragma unroll
    for (int mt = 0; mt < 2; mt++) {
#pragma unroll
        for (int nt = 0; nt < 8; nt++) {
            int col = n0 + wn * 64 + nt * 8 + tg * 2;
            float bv0 = 0.f, bv1 = 0.f;
            if (EPI == 4 || EPI == 9 || EPI == 10) {
                bv0 = __ldg(&bias[col]); bv1 = __ldg(&bias[col + 1]);
            }
#pragma unroll
            for (int half = 0; half < 2; half++) {
                int row = m0 + wm * 32 + mt * 16 + g + half * 8;
                if (row >= M) continue;
                float v0 = c[mt][nt][half * 2 + 0];
                float v1 = c[mt][nt][half * 2 + 1];
                if (EPI == 4) {
                    size_t off = (size_t)row * N + col;
                    *(float2*)(Cm + off) = make_float2(fmaxf(v0 + bv0, 0.0f),
                                                       fmaxf(v1 + bv1, 0.0f));
                } else if (EPI == 8) {
                    float2 old = *(const float2*)(OldP + (size_t)row * oldLd + col);
                    size_t off = (size_t)row * N + col;
                    *(float2*)(Cm + off) = make_float2(tanhf(old.x + v0),
                                                       tanhf(old.y + v1));
                } else if (EPI == 9) {
                    size_t off = (size_t)row * N + col;
                    *(float2*)(Cm + off) = make_float2(v0 + bv0, v1 + bv1);
                } else if (EPI == 10) {
                    int nodei = row % NN;
                    float d1v = Dv[nodei];
                    float d2v = Dv[NN + nodei];
                    float d3v = Dv[2 * NN + nodei];
                    float d4v = Dv[3 * NN + nodei];
                    float cr0 = bv0, cr1 = bv1;
                    cr0 = fmaf(d4v, __ldg(&Ev[col]), cr0);
                    cr1 = fmaf(d4v, __ldg(&Ev[col + 1]), cr1);
                    cr0 = fmaf(d3v, __ldg(&Ev[CC + col]), cr0);
                    cr1 = fmaf(d3v, __ldg(&Ev[CC + col + 1]), cr1);
                    cr0 = fmaf(d2v, __ldg(&Ev[2 * CC + col]), cr0);
                    cr1 = fmaf(d2v, __ldg(&Ev[2 * CC + col + 1]), cr1);
                    cr0 = fmaf(d1v, __ldg(&Ev[3 * CC + col]), cr0);
                    cr1 = fmaf(d1v, __ldg(&Ev[3 * CC + col + 1]), cr1);
                    float h0 = v0 + cr0, h1 = v1 + cr1;
                    size_t off = (size_t)row * N + col;
                    *(float2*)(Cm + off) = make_float2(h0, h1);
                    if (oh) {
                        *(uint32_t*)(oh + off) = split_pack(h0, h1);
                        *(uint32_t*)(ol + off) = split_pack_lo(h0, h1);
                    }
                } else if (EPI == 11) {
                    float2 old = *(const float2*)(OldP + (size_t)row * oldLd + col);
                    int nodei = row % NN;
                    float d1v = Dv[nodei];
                    float d2v = Dv[NN + nodei];
                    float d3v = Dv[2 * NN + nodei];
                    float d4v = Dv[3 * NN + nodei];
                    float a0 = old.x + v0, a1 = old.y + v1;
                    a0 = fmaf(d4v, __ldg(&Ev[col]), a0);
                    a1 = fmaf(d4v, __ldg(&Ev[col + 1]), a1);
                    a0 = fmaf(d3v, __ldg(&Ev[NZR + col]), a0);
                    a1 = fmaf(d3v, __ldg(&Ev[NZR + col + 1]), a1);
                    a0 = fmaf(d2v, __ldg(&Ev[2 * NZR + col]), a0);
                    a1 = fmaf(d2v, __ldg(&Ev[2 * NZR + col + 1]), a1);
                    a0 = fmaf(d1v, __ldg(&Ev[3 * NZR + col]), a0);
                    a1 = fmaf(d1v, __ldg(&Ev[3 * NZR + col + 1]), a1);
                    float s0 = 1.0f / (1.0f + expf(-a0));
                    float s1 = 1.0f / (1.0f + expf(-a1));
                    if (col < CC) {
                        size_t off = (size_t)row * CC + col;
                        *(float2*)(Cm + off) = make_float2(s0, s1);
                    } else {
                        int c2 = col - CC;
                        size_t off = (size_t)row * CC + c2;
                        float2 hv = *(const float2*)(Hp + off);
                        float m0v = s0 * hv.x, m1v = s1 * hv.y;
                        *(uint32_t*)(oh + off) = split_pack(m0v, m1v);
                        *(uint32_t*)(ol + off) = split_pack_lo(m0v, m1v);
                    }
                }
            }
        }
    }
}

// ---------------- 128-wide batched propagation, unrolled x4 ----------------
template <bool WF32, bool WPL>
__global__ void __launch_bounds__(128) prop128_kernel(
    const float* __restrict__ Xin, float* __restrict__ Xout,
    __nv_bfloat16* __restrict__ oh, __nv_bfloat16* __restrict__ ol) {
    int r = blockIdx.x * 4 + (threadIdx.x >> 5);
    int t = threadIdx.x & 31;
    if (r >= MB) return;
    int p = r / NN;
    int i = r - p * NN;
    const float4* X4 = (const float4*)Xin;
    float sn = g_normself[i];
    float4 v = X4[(size_t)r * F4 + t];
    float4 acc = make_float4(sn * v.x, sn * v.y, sn * v.z, sn * v.w);
    int beg = g_rowptr[i];
    int end = g_rowptr[i + 1];
    int base = p * NN;
    int e = beg;
    for (; e + 4 <= end; e += 4) {
        int s0 = g_csrsrc[e], s1 = g_csrsrc[e + 1];
        int s2 = g_csrsrc[e + 2], s3 = g_csrsrc[e + 3];
        float w0 = g_csrnorm[e], w1 = g_csrnorm[e + 1];
        float w2 = g_csrnorm[e + 2], w3 = g_csrnorm[e + 3];
        float4 u0 = X4[(size_t)(base + s0) * F4 + t];
        float4 u1 = X4[(size_t)(base + s1) * F4 + t];
        float4 u2 = X4[(size_t)(base + s2) * F4 + t];
        float4 u3 = X4[(size_t)(base + s3) * F4 + t];
        acc.x = fmaf(w0, u0.x, acc.x); acc.y = fmaf(w0, u0.y, acc.y);
        acc.z = fmaf(w0, u0.z, acc.z); acc.w = fmaf(w0, u0.w, acc.w);
        acc.x = fmaf(w1, u1.x, acc.x); acc.y = fmaf(w1, u1.y, acc.y);
        acc.z = fmaf(w1, u1.z, acc.z); acc.w = fmaf(w1, u1.w, acc.w);
        acc.x = fmaf(w2, u2.x, acc.x); acc.y = fmaf(w2, u2.y, acc.y);
        acc.z = fmaf(w2, u2.z, acc.z); acc.w = fmaf(w2, u2.w, acc.w);
        acc.x = fmaf(w3, u3.x, acc.x); acc.y = fmaf(w3, u3.y, acc.y);
        acc.z = fmaf(w3, u3.z, acc.z); acc.w = fmaf(w3, u3.w, acc.w);
    }
    for (; e < end; e++) {
        int s = g_csrsrc[e];
        float w = g_csrnorm[e];
        float4 u = X4[(size_t)(base + s) * F4 + t];
        acc.x = fmaf(w, u.x, acc.x);
        acc.y = fmaf(w, u.y, acc.y);
        acc.z = fmaf(w, u.z, acc.z);
        acc.w = fmaf(w, u.w, acc.w);
    }
    if (WF32) ((float4*)Xout)[(size_t)r * F4 + t] = acc;
    if (WPL) {
        size_t off = (size_t)r * FF + t * 4;
        *(uint32_t*)(oh + off) = split_pack(acc.x, acc.y);
        *(uint32_t*)(oh + off + 2) = split_pack(acc.z, acc.w);
        *(uint32_t*)(ol + off) = split_pack_lo(acc.x, acc.y);
        *(uint32_t*)(ol + off + 2) = split_pack_lo(acc.z, acc.w);
    }
}

// ---------------- elementwise kernels ----------------
__global__ void extract_all_kernel(const float* __restrict__ x, float* __restrict__ Xp) {
    int idx = blockIdx.x * blockDim.x + threadIdx.x;
    if (idx < NN * FF) {
        float4 v = ((const float4*)x)[idx];
        Xp[idx] = v.x;
        Xp[NN * FF + idx] = v.y;
        Xp[2 * NN * FF + idx] = v.z;
        Xp[3 * NN * FF + idx] = v.w;
    }
}

__global__ void gru_reduce_kernel(const float* __restrict__ Z, const float* __restrict__ H,
                                  const float* __restrict__ Ht, float* __restrict__ out,
                                  __nv_bfloat16* __restrict__ oh, __nv_bfloat16* __restrict__ ol) {
    int idx = blockIdx.x * blockDim.x + threadIdx.x;
    if (idx >= NN * C4) return;
    int i = idx >> 7;
    int t = idx & 127;
    float4 acc = make_float4(0.f, 0.f, 0.f, 0.f);
#pragma unroll
    for (int p = 0; p < PP; p++) {
        size_t o4 = (size_t)(p * NN + i) * C4 + t;
        float4 z = ((const float4*)Z)[o4];
        float4 h = ((const float4*)H)[o4];
        float4 ht = ((const float4*)Ht)[o4];
        float pr = g_probs[p];
        acc.x += pr * (z.x * h.x + (1.0f - z.x) * ht.x);
        acc.y += pr * (z.y * h.y + (1.0f - z.y) * ht.y);
        acc.z += pr * (z.z * h.z + (1.0f - z.z) * ht.z);
        acc.w += pr * (z.w * h.w + (1.0f - z.w) * ht.w);
    }
    ((float4*)(out + NN))[idx] = acc;
    float4 v = make_float4(fmaxf(acc.x, 0.f), fmaxf(acc.y, 0.f),
                           fmaxf(acc.z, 0.f), fmaxf(acc.w, 0.f));
    size_t off = (size_t)idx * 4;
    *(uint32_t*)(oh + off) = split_pack(v.x, v.y);
    *(uint32_t*)(oh + off + 2) = split_pack(v.z, v.w);
    *(uint32_t*)(ol + off) = split_pack_lo(v.x, v.y);
    *(uint32_t*)(ol + off + 2) = split_pack_lo(v.z, v.w);
}

__global__ void lin2_kernel(const float* __restrict__ hid, const float* __restrict__ w,
                            const float* __restrict__ b, float* __restrict__ out) {
    int n = blockIdx.x * 8 + (threadIdx.x >> 5);
    int lane = threadIdx.x & 31;
    float s = 0.0f;
    for (int k = lane; k < HIDN; k += 32) s = fmaf(hid[(size_t)n * HIDN + k], w[k], s);
#pragma unroll
    for (int off = 16; off; off >>= 1) s += __shfl_down_sync(0xffffffffu, s, off);
    if (lane == 0) out[n] = s + b[0];
}

// ---------------- host orchestration ----------------
#define GP(sym) ({ void* _p; cudaGetSymbolAddress(&_p, sym); (__nv_bfloat16*)_p; })
#define GPF(sym) ({ void* _p; cudaGetSymbolAddress(&_p, sym); (float*)_p; })

struct GemmArgs {
    const __nv_bfloat16 *Ah, *Al, *Bh, *Bl;
    float* Cm;
    const float* bias;
    const float* Hp;
    const float* OldP;
    int oldLd;
    const float* Dv;
    const float* Ev;
    __nv_bfloat16 *oh, *ol;
    int M, N, K;
};

template <int EPI>
static inline void launch_gemm(const GemmArgs& a) {
    dim3 grid(a.N / BN, (a.M + BM - 1) / BM);
    bf3_gemm<EPI><<<grid, 256, SMEM_BYTES>>>(a.Ah, a.Al, a.Bh, a.Bl, a.Cm, a.bias,
                                             a.Hp, a.OldP, a.oldLd, a.Dv, a.Ev,
                                             a.oh, a.ol, a.M, a.N, a.K);
}

static inline void launch_wts(const float* W, int k0, int N, int Kb,
                              __nv_bfloat16* oh, __nv_bfloat16* ol) {
    dim3 grid(N / 32, Kb / 32);
    wt_split_kernel<<<grid, 256>>>(W, k0, N, Kb, oh, ol);
}

extern "C" void kernel_launch(void* const* d_in, const int* in_sizes, int n_in,
                              void* d_out, int out_size) {
    const float* x     = (const float*)d_in[0];
    const int*   ei    = (const int*)d_in[1];
    const float* ea    = (const float*)d_in[2];
    const float* W1    = (const float*)d_in[3];
    const float* b1    = (const float*)d_in[4];
    const float* W2    = (const float*)d_in[5];
    const float* b2    = (const float*)d_in[6];
    const float* W3    = (const float*)d_in[7];
    const float* b3    = (const float*)d_in[8];
    const float* W4    = (const float*)d_in[9];
    const float* b4    = (const float*)d_in[10];
    const float* W5    = (const float*)d_in[11];
    const float* b5    = (const float*)d_in[12];
    const float* Wz    = (const float*)d_in[13];
    const float* bz    = (const float*)d_in[14];
    const float* Lz_w  = (const float*)d_in[15];
    const float* Lz_b  = (const float*)d_in[16];
    const float* Wr    = (const float*)d_in[17];
    const float* br    = (const float*)d_in[18];
    const float* Lr_w  = (const float*)d_in[19];
    const float* Lr_b  = (const float*)d_in[20];
    const float* Wh    = (const float*)d_in[21];
    const float* bh    = (const float*)d_in[22];
    const float* Lh_w  = (const float*)d_in[23];
    const float* Lh_b  = (const float*)d_in[24];
    const float* attn  = (const float*)d_in[25];
    const float* lin1w = (const float*)d_in[26];
    const float* lin1b = (const float*)d_in[27];
    const float* lin2w = (const float*)d_in[28];
    const float* lin2b = (const float*)d_in[29];
    float* out = (float*)d_out;

    static bool attr_done = false;
    if (!attr_done) {
        cudaFuncSetAttribute(bf3_gemm<4>, cudaFuncAttributeMaxDynamicSharedMemorySize, SMEM_BYTES);
        cudaFuncSetAttribute(bf3_gemm<8>, cudaFuncAttributeMaxDynamicSharedMemorySize, SMEM_BYTES);
        cudaFuncSetAttribute(bf3_gemm<9>, cudaFuncAttributeMaxDynamicSharedMemorySize, SMEM_BYTES);
        cudaFuncSetAttribute(bf3_gemm<10>, cudaFuncAttributeMaxDynamicSharedMemorySize, SMEM_BYTES);
        cudaFuncSetAttribute(bf3_gemm<11>, cudaFuncAttributeMaxDynamicSharedMemorySize, SMEM_BYTES);
        attr_done = true;
    }

    float* pXp   = GPF(g_Xp);
    float* pXA   = GPF(g_XA);
    float* pXB   = GPF(g_XB);
    float* pH    = GPF(g_H);
    float* pZ    = GPF(g_Z);
    float* pHt   = GPF(g_Ht);
    float* pGC   = GPF(g_GC);
    float* phid1 = GPF(g_hid1);
    float* pMtmp = GPF(g_Mtmp);
    float* pMtmp2 = GPF(g_Mtmp2);
    float* pWc   = GPF(g_Wc);
    float* pbvAll = GPF(g_bvAll);
    float* pev   = GPF(g_ev);
    float* pEv   = GPF(g_Ev);
    float* pvt1  = GPF(g_vt1);
    float* pvt2  = GPF(g_vt2);
    float* pdv   = GPF(g_dv);

    __nv_bfloat16 *pXsh = GP(g_Xsh), *pXsl = GP(g_Xsl);
    __nv_bfloat16 *pX5h = GP(g_X5h), *pX5l = GP(g_X5l);
    __nv_bfloat16 *pRmh = GP(g_Rmh), *pRml = GP(g_Rml);
    __nv_bfloat16 *pRAh = GP(g_RAh), *pRAl = GP(g_RAl);

    __nv_bfloat16 *pWCh = GP(g_WCh), *pWCl = GP(g_WCl);
    __nv_bfloat16 *pMZRh = GP(g_MZRh), *pMZRl = GP(g_MZRl);
    __nv_bfloat16 *pMFh = GP(g_MFh), *pMFl = GP(g_MFl);
    __nv_bfloat16 *pLh2h = GP(g_Lh2h), *pLh2l = GP(g_Lh2l);
    __nv_bfloat16 *pL1th = GP(g_L1th), *pL1tl = GP(g_L1tl);

    const int gE  = (EE + 255) / 256;
    const int gN  = (NN + 255) / 256;
    const int gNC4 = (NN * C4 + 255) / 256;
    const int gNF = (NN * FF + 255) / 256;
    const int gW128 = (CC * FF + 255) / 256;

    // graph setup + CSR
    init_node_arrays<<<gN, 256>>>();
    deg_edges_kernel<<<gE, 256>>>(ei, ea);
    deg_finalize_kernel<<<gN, 256>>>();
    scan_kernel<<<1, 1024>>>();
    scatter_kernel<<<gE, 256>>>(ei, ea);
    softmax4_kernel<<<1, 32>>>(attn);

    // d vectors
    d_iter_kernel<<<gN, 256>>>(nullptr, pdv);
    d_iter_kernel<<<gN, 256>>>(pdv, pdv + NN);
    d_iter_kernel<<<gN, 256>>>(pdv + NN, pdv + 2 * NN);
    d_iter_kernel<<<gN, 256>>>(pdv + 2 * NN, pdv + 3 * NN);

    // e vectors: e1=b1W2W3W4W5, e2=b2W3W4W5, e3=b3W4W5, e4=b4W5
    vecmat_kernel<<<2, 256>>>(b4, W5, pev + 3 * CC);
    vecmat_kernel<<<2, 256>>>(b3, W4, pvt1);
    vecmat_kernel<<<2, 256>>>(pvt1, W5, pev + 2 * CC);
    vecmat_kernel<<<2, 256>>>(b2, W3, pvt1);
    vecmat_kernel<<<2, 256>>>(pvt1, W4, pvt2);
    vecmat_kernel<<<2, 256>>>(pvt2, W5, pev + CC);
    vecmat_kernel<<<2, 256>>>(b1, W2, pvt1);
    vecmat_kernel<<<2, 256>>>(pvt1, W3, pvt2);
    vecmat_kernel<<<2, 256>>>(pvt2, W4, pvt1);
    vecmat_kernel<<<2, 256>>>(pvt1, W5, pev);

    // tail weights
    launch_wts(Lh_w, CC, CC, CC, pLh2h, pLh2l);
    launch_wts(lin1w, 0, HIDN, CC, pL1th, pL1tl);

    // chain fold W~ (fp32 into g_Wc) -> split planes
    gatefold_kernel<<<gW128, 256>>>(W1, W2, pMtmp);
    gatefold_kernel<<<gW128, 256>>>(pMtmp, W3, pMtmp2);
    gatefold_kernel<<<gW128, 256>>>(pMtmp2, W4, pMtmp);
    gatefold_kernel<<<gW128, 256>>>(pMtmp, W5, pWc);
    launch_wts(pWc, 0, CC, FF, pWCh, pWCl);

    // ZR fold: MZR = W~ @ [Lz2|Lr2] -> split planes [N=1024][K=128]
    gatefold_kernel<<<gW128, 256>>>(pWc, Lz_w + (size_t)CC * CC, pMtmp);
    launch_wts(pMtmp, 0, CC, FF, pMZRh, pMZRl);
    gatefold_kernel<<<gW128, 256>>>(pWc, Lr_w + (size_t)CC * CC, pMtmp);
    launch_wts(pMtmp, 0, CC, FF, pMZRh + (size_t)CC * FF, pMZRl + (size_t)CC * FF);

    // E'_k = e_k @ [Lz2|Lr2]   (row stride NZR)
    for (int k = 0; k < 4; k++) {
        vecmat_kernel<<<2, 256>>>(pev + k * CC, Lz_w + (size_t)CC * CC, pEv + k * NZR);
        vecmat_kernel<<<2, 256>>>(pev + k * CC, Lr_w + (size_t)CC * CC, pEv + k * NZR + CC);
    }

    // gate folds [Mz|Mr|Mh]^T and biases
    gatefold_kernel<<<gW128, 256>>>(Wz, Lz_w, pMtmp);
    launch_wts(pMtmp, 0, CC, FF, pMFh, pMFl);
    gatefold_kernel<<<gW128, 256>>>(Wr, Lr_w, pMtmp);
    launch_wts(pMtmp, 0, CC, FF, pMFh + (size_t)CC * FF, pMFl + (size_t)CC * FF);
    gatefold_kernel<<<gW128, 256>>>(Wh, Lh_w, pMtmp);
    launch_wts(pMtmp, 0, CC, FF, pMFh + (size_t)2 * CC * FF, pMFl + (size_t)2 * CC * FF);
    {
        dim3 grid(2, 3);
        gate_bias_all_kernel<<<grid, 256>>>(Lz_w, Lz_b, bz, Lr_w, Lr_b, br,
                                            Lh_w, Lh_b, bh, pbvAll);
    }
    // fold b5@[Lz2|Lr2] into z/r front biases
    vecmat_add_kernel<<<2, 256>>>(b5, Lz_w + (size_t)CC * CC, pbvAll);
    vecmat_add_kernel<<<2, 256>>>(b5, Lr_w + (size_t)CC * CC, pbvAll + CC);

    // ---- batched across all 4 timesteps (M = 40000) ----
    extract_all_kernel<<<gNF, 256>>>(x, pXp);

    const int gP = (MB + 3) / 4;
    prop128_kernel<true, true><<<gP, 128>>>(pXp, pXA, pXsh, pXsl);
    GemmArgs a{};
    // front gates: GC = X1 @ [Mz|Mr|Mh] + biases (incl. b5@L folds)
    a = {pXsh, pXsl, pMFh, pMFl, pGC, pbvAll, nullptr, nullptr, 0,
         nullptr, nullptr, nullptr, nullptr, MB, NFR, FF};
    launch_gemm<9>(a);
    prop128_kernel<true, false><<<gP, 128>>>(pXA, pXB, nullptr, nullptr);
    prop128_kernel<true, false><<<gP, 128>>>(pXB, pXA, nullptr, nullptr);
    prop128_kernel<true, false><<<gP, 128>>>(pXA, pXB, nullptr, nullptr);
    prop128_kernel<false, true><<<gP, 128>>>(pXB, nullptr, pX5h, pX5l);

    // H = X5 @ W~ + rank-4 + b5 (fp32 only)
    a = {pX5h, pX5l, pWCh, pWCl, pH, b5, nullptr, nullptr, 0,
         pdv, pev, nullptr, nullptr, MB, CC, FF};
    launch_gemm<10>(a);

    // ZR from X5: [Z|R] = sigmoid(GC + X5@MZR + rank-4 via Ev)
    a = {pX5h, pX5l, pMZRh, pMZRl, pZ, nullptr, pH, pGC, NFR,
         pdv, pEv, pRmh, pRml, MB, NZR, FF};
    launch_gemm<11>(a);

    // Ht = tanh(GC[:,1024:1536] + Rm@Lh2)
    a = {pRmh, pRml, pLh2h, pLh2l, pHt, nullptr, nullptr, pGC + 2 * CC, NFR,
         nullptr, nullptr, nullptr, nullptr, MB, CC, CC};
    launch_gemm<8>(a);

    gru_reduce_kernel<<<gNC4, 256>>>(pZ, pH, pHt, out, pRAh, pRAl);

    a = {pRAh, pRAl, pL1th, pL1tl, phid1, lin1b, nullptr, nullptr, 0,
         nullptr, nullptr, nullptr, nullptr, NN, HIDN, CC};
    launch_gemm<4>(a);
    lin2_kernel<<<(NN + 7) / 8, 256>>>(phid1, lin2w, lin2b, out);
}

// round 16
// speedup vs baseline: 1.5274x; 1.0472x over previous
#include <cuda_runtime.h>
#include <cuda_bf16.h>
#include <stdint.h>
#include <math.h>

#define NN 10000
#define FF 128
#define PP 4
#define EE 160000
#define CC 512
#define HIDN 256
#define C4 (CC/4)
#define F4 (FF/4)
#define MB (NN*PP)
#define NZR (2*CC)           /* ZR width 1024 */
#define KA 256               /* concat K: [X1|X5] */

// ---------------- scratch ----------------
__device__ float g_deg[NN];
__device__ float g_dinv[NN];
__device__ float g_normself[NN];
__device__ int   g_counts[NN];
__device__ int   g_rowptr[NN + 1];
__device__ int   g_cursor[NN];
__device__ int   g_csrsrc[EE];
__device__ float g_csrnorm[EE];
__device__ float g_probs[PP];

__device__ float g_Xp[MB * FF];
__device__ float g_XA[MB * FF];
__device__ float g_XB[MB * FF];
__device__ float g_H[MB * CC];
__device__ float g_Z[MB * CC];
__device__ float g_Ht[MB * CC];
__device__ float g_GC[MB * CC];       // Gh only
__device__ float g_hid1[NN * HIDN];
__device__ float g_Mtmp[FF * CC];
__device__ float g_Mtmp2[FF * CC];
__device__ float g_Wc[FF * CC];
__device__ float g_bvAll[3 * CC];     // [bvz+b5Lz2 | bvr+b5Lr2 | bvh]
__device__ float g_ev[4 * CC];
__device__ float g_Ev[4 * NZR];
__device__ float g_vt1[CC], g_vt2[CC];
__device__ float g_dv[4 * NN];

__device__ __nv_bfloat16 g_A256h[MB * KA], g_A256l[MB * KA];  // [X1|X5] planes
__device__ __nv_bfloat16 g_Rmh[MB * CC], g_Rml[MB * CC];
__device__ __nv_bfloat16 g_RAh[NN * CC], g_RAl[NN * CC];

__device__ __nv_bfloat16 g_WCh[CC * FF], g_WCl[CC * FF];       // W~^T [512][128]
__device__ __nv_bfloat16 g_MZRh[NZR * KA], g_MZRl[NZR * KA];   // [Mz;MZRz | Mr;MZRr]^T [1024][256]
__device__ __nv_bfloat16 g_MFh[CC * FF], g_MFl[CC * FF];       // Mh^T [512][128]
__device__ __nv_bfloat16 g_Lh2h[CC * CC], g_Lh2l[CC * CC];
__device__ __nv_bfloat16 g_L1th[HIDN * CC], g_L1tl[HIDN * CC];

__device__ __forceinline__ void split_bf(float x, __nv_bfloat16& h, __nv_bfloat16& l) {
    h = __float2bfloat16(x);
    l = __float2bfloat16(x - __bfloat162float(h));
}
__device__ __forceinline__ uint32_t pack_bf2(__nv_bfloat16 a, __nv_bfloat16 b) {
    __nv_bfloat162 t(a, b);
    return *(uint32_t*)&t;
}
__device__ __forceinline__ uint32_t split_pack(float a, float b) {
    __nv_bfloat16 h0, l0, h1, l1;
    split_bf(a, h0, l0); split_bf(b, h1, l1);
    return pack_bf2(h0, h1);
}
__device__ __forceinline__ uint32_t split_pack_lo(float a, float b) {
    __nv_bfloat16 h0, l0, h1, l1;
    split_bf(a, h0, l0); split_bf(b, h1, l1);
    return pack_bf2(l0, l1);
}

// ---------------- graph setup kernels ----------------
__global__ void init_node_arrays() {
    int i = blockIdx.x * blockDim.x + threadIdx.x;
    if (i < NN) { g_deg[i] = 0.0f; g_counts[i] = 0; g_cursor[i] = 0; }
}

__global__ void deg_edges_kernel(const int* __restrict__ ei, const float* __restrict__ ea) {
    int e = blockIdx.x * blockDim.x + threadIdx.x;
    if (e < EE) {
        int dst = ei[EE + e];
        atomicAdd(&g_deg[dst], ea[e]);
        atomicAdd(&g_counts[dst], 1);
    }
}

__global__ void deg_finalize_kernel() {
    int i = blockIdx.x * blockDim.x + threadIdx.x;
    if (i < NN) {
        float d = g_deg[i] + 1.0f;
        float di = (d > 0.0f) ? rsqrtf(d) : 0.0f;
        g_dinv[i] = di;
        g_normself[i] = di * di;
    }
}

__global__ void scan_kernel() {
    __shared__ int part[1024];
    const int per = 10;
    int t = threadIdx.x;
    int base = t * per;
    int loc[per];
    int s = 0;
#pragma unroll
    for (int i = 0; i < per; i++) {
        int idx = base + i;
        int v = (idx < NN) ? g_counts[idx] : 0;
        loc[i] = s; s += v;
    }
    part[t] = s;
    __syncthreads();
    for (int off = 1; off < 1024; off <<= 1) {
        int v = (t >= off) ? part[t - off] : 0;
        __syncthreads();
        part[t] += v;
        __syncthreads();
    }
    int offb = (t == 0) ? 0 : part[t - 1];
#pragma unroll
    for (int i = 0; i < per; i++) {
        int idx = base + i;
        if (idx < NN) g_rowptr[idx] = offb + loc[i];
    }
    if (t == 1023) g_rowptr[NN] = part[1023];
}

__global__ void scatter_kernel(const int* __restrict__ ei, const float* __restrict__ ea) {
    int e = blockIdx.x * blockDim.x + threadIdx.x;
    if (e < EE) {
        int src = ei[e];
        int dst = ei[EE + e];
        float nv = g_dinv[src] * ea[e] * g_dinv[dst];
        int pos = atomicAdd(&g_cursor[dst], 1);
        int slot = g_rowptr[dst] + pos;
        g_csrsrc[slot] = src;
        g_csrnorm[slot] = nv;
    }
}

__global__ void softmax4_kernel(const float* __restrict__ attn) {
    if (threadIdx.x == 0 && blockIdx.x == 0) {
        float m = attn[0];
        for (int p = 1; p < PP; p++) m = fmaxf(m, attn[p]);
        float s = 0.0f, e[PP];
        for (int p = 0; p < PP; p++) { e[p] = expf(attn[p] - m); s += e[p]; }
        for (int p = 0; p < PP; p++) g_probs[p] = e[p] / s;
    }
}

__global__ void d_iter_kernel(const float* __restrict__ din, float* __restrict__ dout) {
    int i = blockIdx.x * blockDim.x + threadIdx.x;
    if (i >= NN) return;
    float self = (din != nullptr) ? din[i] : 1.0f;
    float acc = g_normself[i] * self;
    int beg = g_rowptr[i], end = g_rowptr[i + 1];
    for (int e = beg; e < end; e++) {
        float u = (din != nullptr) ? din[g_csrsrc[e]] : 1.0f;
        acc = fmaf(g_csrnorm[e], u, acc);
    }
    dout[i] = acc;
}

__global__ void vecmat_kernel(const float* __restrict__ v, const float* __restrict__ W,
                              float* __restrict__ out) {
    int n = blockIdx.x * blockDim.x + threadIdx.x;
    if (n >= CC) return;
    float s = 0.0f;
    for (int k = 0; k < CC; k += 8) {
#pragma unroll
        for (int j = 0; j < 8; j++)
            s = fmaf(v[k + j], W[(size_t)(k + j) * CC + n], s);
    }
    out[n] = s;
}

__global__ void vecmat_add_kernel(const float* __restrict__ v, const float* __restrict__ W,
                                  float* __restrict__ out) {
    int n = blockIdx.x * blockDim.x + threadIdx.x;
    if (n >= CC) return;
    float s = 0.0f;
    for (int k = 0; k < CC; k += 8) {
#pragma unroll
        for (int j = 0; j < 8; j++)
            s = fmaf(v[k + j], W[(size_t)(k + j) * CC + n], s);
    }
    out[n] += s;
}

// tiled transpose+split: out[n*ldo + ko + k] = split(W[(k0+k)*N + n]) ; k in [0,Kb)
__global__ void wt_split_kernel(const float* __restrict__ W, int k0, int N, int Kb,
                                int ldo, int ko,
                                __nv_bfloat16* __restrict__ oh, __nv_bfloat16* __restrict__ ol) {
    __shared__ float tile[32][33];
    int nt = blockIdx.x * 32;
    int kt = blockIdx.y * 32;
    int tx = threadIdx.x & 31;
    int ty = threadIdx.x >> 5;
#pragma unroll
    for (int j = 0; j < 32; j += 8)
        tile[ty + j][tx] = W[(size_t)(k0 + kt + ty + j) * N + nt + tx];
    __syncthreads();
#pragma unroll
    for (int j = 0; j < 32; j += 8) {
        int n = nt + ty + j;
        int k = kt + tx;
        float v = tile[tx][ty + j];
        __nv_bfloat16 h, l;
        split_bf(v, h, l);
        oh[(size_t)n * ldo + ko + k] = h;
        ol[(size_t)n * ldo + ko + k] = l;
    }
}

// M[f][n] = sum_k A[f][k] * Lw[k][n]
__global__ void gatefold_kernel(const float* __restrict__ A, const float* __restrict__ Lw,
                                float* __restrict__ M) {
    int idx = blockIdx.x * blockDim.x + threadIdx.x;
    if (idx < FF * CC) {
        int f = idx / CC, n = idx - f * CC;
        float s = 0.0f;
        for (int k = 0; k < CC; k += 8) {
            float4 a0 = *(const float4*)&A[(size_t)f * CC + k];
            float4 a1 = *(const float4*)&A[(size_t)f * CC + k + 4];
            s = fmaf(a0.x, Lw[(size_t)(k + 0) * CC + n], s);
            s = fmaf(a0.y, Lw[(size_t)(k + 1) * CC + n], s);
            s = fmaf(a0.z, Lw[(size_t)(k + 2) * CC + n], s);
            s = fmaf(a0.w, Lw[(size_t)(k + 3) * CC + n], s);
            s = fmaf(a1.x, Lw[(size_t)(k + 4) * CC + n], s);
            s = fmaf(a1.y, Lw[(size_t)(k + 5) * CC + n], s);
            s = fmaf(a1.z, Lw[(size_t)(k + 6) * CC + n], s);
            s = fmaf(a1.w, Lw[(size_t)(k + 7) * CC + n], s);
        }
        M[idx] = s;
    }
}

__global__ void gate_bias_all_kernel(
    const float* __restrict__ Lz_w, const float* __restrict__ Lz_b, const float* __restrict__ bz,
    const float* __restrict__ Lr_w, const float* __restrict__ Lr_b, const float* __restrict__ br,
    const float* __restrict__ Lh_w, const float* __restrict__ Lh_b, const float* __restrict__ bh,
    float* __restrict__ bvAll) {
    int j = blockIdx.y;
    int n = blockIdx.x * blockDim.x + threadIdx.x;
    if (n >= CC) return;
    const float* Lw;
    const float* Lb;
    const float* bs;
    if (j == 0)      { Lw = Lz_w; Lb = Lz_b; bs = bz; }
    else if (j == 1) { Lw = Lr_w; Lb = Lr_b; bs = br; }
    else             { Lw = Lh_w; Lb = Lh_b; bs = bh; }
    float s = Lb[n];
    for (int k = 0; k < CC; k += 8) {
#pragma unroll
        for (int q = 0; q < 8; q++)
            s = fmaf(bs[k + q], Lw[(size_t)(k + q) * CC + n], s);
    }
    bvAll[j * CC + n] = s;
}

// ---------------- bf16x3 tensor-core GEMM: BM=128, BN=128, cp.async, lda ----------------
#define BM 128
#define BN 128
#define BKC 32
#define TSTR 40
#define PL_SZ (128 * TSTR)
#define STG  (4 * PL_SZ)
#define SMEM_BYTES (2 * STG * 2)

__device__ __forceinline__ void mma16816(float* c, const uint32_t* a, const uint32_t* b) {
    asm volatile(
        "mma.sync.aligned.m16n8k16.row.col.f32.bf16.bf16.f32 "
        "{%0,%1,%2,%3}, {%4,%5,%6,%7}, {%8,%9}, {%0,%1,%2,%3};"
        : "+f"(c[0]), "+f"(c[1]), "+f"(c[2]), "+f"(c[3])
        : "r"(a[0]), "r"(a[1]), "r"(a[2]), "r"(a[3]), "r"(b[0]), "r"(b[1]));
}

__device__ __forceinline__ void ldsm_x4(const void* p, uint32_t* r) {
    uint32_t addr = (uint32_t)__cvta_generic_to_shared(p);
    asm volatile("ldmatrix.sync.aligned.m8n8.x4.shared.b16 {%0,%1,%2,%3}, [%4];"
        : "=r"(r[0]), "=r"(r[1]), "=r"(r[2]), "=r"(r[3]) : "r"(addr));
}

__device__ __forceinline__ void cpa16(void* dst, const void* src, int sz) {
    uint32_t d = (uint32_t)__cvta_generic_to_shared(dst);
    asm volatile("cp.async.cg.shared.global [%0], [%1], 16, %2;"
                 :: "r"(d), "l"(src), "r"(sz));
}
__device__ __forceinline__ void cpa_commit() {
    asm volatile("cp.async.commit_group;");
}
template <int NW>
__device__ __forceinline__ void cpa_wait() {
    asm volatile("cp.async.wait_group %0;" :: "n"(NW));
}

// EPI: 4 relu(acc+bias)->fp32;
//      8 tanh(OldP_strided + acc) -> Cm fp32
//      9 store(acc + bias) fp32
//      10 H: acc + rank4(Dv,Ev stride CC) + bias -> fp32
//      11 ZR: sigmoid(acc + bias + rank4(Dv,Ev stride NZR));
//         col<CC -> Z fp32 (ld CC); col>=CC -> *Hp -> Rm planes (ld CC)
template <int EPI>
__global__ void __launch_bounds__(256, 2) bf3_gemm(
    const __nv_bfloat16* __restrict__ Ah, const __nv_bfloat16* __restrict__ Al,
    const __nv_bfloat16* __restrict__ Bh, const __nv_bfloat16* __restrict__ Bl,
    float* __restrict__ Cm, const float* __restrict__ bias,
    const float* __restrict__ Hp,
    const float* __restrict__ OldP, int oldLd,
    const float* __restrict__ Dv, const float* __restrict__ Ev,
    __nv_bfloat16* __restrict__ oh, __nv_bfloat16* __restrict__ ol,
    int M, int N, int K, int lda) {
    extern __shared__ __align__(16) __nv_bfloat16 sm[];

    int tid = threadIdx.x;
    int m0 = blockIdx.y * BM;
    int n0 = blockIdx.x * BN;
    int warp = tid >> 5, lane = tid & 31;
    int wm = warp >> 1, wn = warp & 1;
    int g = lane >> 2, tg = lane & 3;

    float c[2][8][4];
#pragma unroll
    for (int mt = 0; mt < 2; mt++)
#pragma unroll
        for (int nt = 0; nt < 8; nt++)
#pragma unroll
            for (int i = 0; i < 4; i++) c[mt][nt][i] = 0.0f;

    int r0 = tid >> 2, q0 = tid & 3;
    int r1 = (tid + 256) >> 2, q1 = (tid + 256) & 3;

    auto load_stage = [&](int st, int k0) {
        __nv_bfloat16* Ahs = sm + st * STG;
        __nv_bfloat16* Als = Ahs + PL_SZ;
        __nv_bfloat16* Bhs = Als + PL_SZ;
        __nv_bfloat16* Bls = Bhs + PL_SZ;
#pragma unroll
        for (int i = 0; i < 2; i++) {
            int row = i == 0 ? r0 : r1;
            int q = i == 0 ? q0 : q1;
            int m = m0 + row;
            int msz = (m < M) ? 16 : 0;
            size_t asrc = (size_t)(m < M ? m : 0) * lda + k0 + q * 8;
            cpa16(Ahs + row * TSTR + q * 8, Ah + asrc, msz);
            cpa16(Als + row * TSTR + q * 8, Al + asrc, msz);
            size_t bsrc = (size_t)(n0 + row) * K + k0 + q * 8;
            cpa16(Bhs + row * TSTR + q * 8, Bh + bsrc, 16);
            cpa16(Bls + row * TSTR + q * 8, Bl + bsrc, 16);
        }
        cpa_commit();
    };

    auto compute = [&](int st) {
        const __nv_bfloat16* Ahs = sm + st * STG;
        const __nv_bfloat16* Als = Ahs + PL_SZ;
        const __nv_bfloat16* Bhs = Als + PL_SZ;
        const __nv_bfloat16* Bls = Bhs + PL_SZ;
#pragma unroll
        for (int ks = 0; ks < 2; ks++) {
            uint32_t ahf[2][4], alf[2][4];
            int arow = lane & 15;
            int acol = ks * 16 + (lane >> 4) * 8;
#pragma unroll
            for (int mt = 0; mt < 2; mt++) {
                int r = wm * 32 + mt * 16 + arow;
                ldsm_x4(Ahs + r * TSTR + acol, ahf[mt]);
                ldsm_x4(Als + r * TSTR + acol, alf[mt]);
            }
            uint32_t bf[8][2];
            int bm_ = lane >> 3;
            int brow_in = lane & 7;
            int bro = (bm_ >> 1) * 8 + brow_in;
            int bco = ks * 16 + (bm_ & 1) * 8;
#pragma unroll
            for (int ntp = 0; ntp < 4; ntp++) {
                int nr = wn * 64 + ntp * 16 + bro;
                uint32_t t4[4];
                ldsm_x4(Bhs + nr * TSTR + bco, t4);
                bf[ntp * 2][0] = t4[0]; bf[ntp * 2][1] = t4[1];
                bf[ntp * 2 + 1][0] = t4[2]; bf[ntp * 2 + 1][1] = t4[3];
            }
#pragma unroll
            for (int mt = 0; mt < 2; mt++)
#pragma unroll
                for (int nt = 0; nt < 8; nt++) {
                    mma16816(c[mt][nt], ahf[mt], bf[nt]);  // hi*hi
                    mma16816(c[mt][nt], alf[mt], bf[nt]);  // lo*hi
                }
#pragma unroll
            for (int ntp = 0; ntp < 4; ntp++) {
                int nr = wn * 64 + ntp * 16 + bro;
                uint32_t t4[4];
                ldsm_x4(Bls + nr * TSTR + bco, t4);
                bf[ntp * 2][0] = t4[0]; bf[ntp * 2][1] = t4[1];
                bf[ntp * 2 + 1][0] = t4[2]; bf[ntp * 2 + 1][1] = t4[3];
            }
#pragma unroll
            for (int mt = 0; mt < 2; mt++)
#pragma unroll
                for (int nt = 0; nt < 8; nt++)
                    mma16816(c[mt][nt], ahf[mt], bf[nt]);  // hi*lo
        }
    };

    int nchunks = K / BKC;
    load_stage(0, 0);
    for (int ch = 0; ch < nchunks; ch++) {
        int st = ch & 1;
        if (ch + 1 < nchunks) {
            load_stage(st ^ 1, (ch + 1) * BKC);
            cpa_wait<1>();
        } else {
            cpa_wait<0>();
        }
        __syncthreads();
        compute(st);
        __syncthreads();
    }

#pragma unroll
    for (int mt = 0; mt < 2; mt++) {
#pragma unroll
        for (int nt = 0; nt < 8; nt++) {
            int col = n0 + wn * 64 + nt * 8 + tg * 2;
            float bv0 = 0.f, bv1 = 0.f;
            if (EPI == 4 || EPI == 9 || EPI == 10 || EPI == 11) {
                bv0 = __ldg(&bias[col]); bv1 = __ldg(&bias[col + 1]);
            }
#pragma unroll
            for (int half = 0; half < 2; half++) {
                int row = m0 + wm * 32 + mt * 16 + g + half * 8;
                if (row >= M) continue;
                float v0 = c[mt][nt][half * 2 + 0];
                float v1 = c[mt][nt][half * 2 + 1];
                if (EPI == 4) {
                    size_t off = (size_t)row * N + col;
                    *(float2*)(Cm + off) = make_float2(fmaxf(v0 + bv0, 0.0f),
                                                       fmaxf(v1 + bv1, 0.0f));
                } else if (EPI == 8) {
                    float2 old = *(const float2*)(OldP + (size_t)row * oldLd + col);
                    size_t off = (size_t)row * N + col;
                    *(float2*)(Cm + off) = make_float2(tanhf(old.x + v0),
                                                       tanhf(old.y + v1));
                } else if (EPI == 9) {
                    size_t off = (size_t)row * N + col;
                    *(float2*)(Cm + off) = make_float2(v0 + bv0, v1 + bv1);
                } else if (EPI == 10) {
                    int nodei = row % NN;
                    float d1v = Dv[nodei];
                    float d2v = Dv[NN + nodei];
                    float d3v = Dv[2 * NN + nodei];
                    float d4v = Dv[3 * NN + nodei];
                    float cr0 = bv0, cr1 = bv1;
                    cr0 = fmaf(d4v, __ldg(&Ev[col]), cr0);
                    cr1 = fmaf(d4v, __ldg(&Ev[col + 1]), cr1);
                    cr0 = fmaf(d3v, __ldg(&Ev[CC + col]), cr0);
                    cr1 = fmaf(d3v, __ldg(&Ev[CC + col + 1]), cr1);
                    cr0 = fmaf(d2v, __ldg(&Ev[2 * CC + col]), cr0);
                    cr1 = fmaf(d2v, __ldg(&Ev[2 * CC + col + 1]), cr1);
                    cr0 = fmaf(d1v, __ldg(&Ev[3 * CC + col]), cr0);
                    cr1 = fmaf(d1v, __ldg(&Ev[3 * CC + col + 1]), cr1);
                    float h0 = v0 + cr0, h1 = v1 + cr1;
                    size_t off = (size_t)row * N + col;
                    *(float2*)(Cm + off) = make_float2(h0, h1);
                } else if (EPI == 11) {
                    int nodei = row % NN;
                    float d1v = Dv[nodei];
                    float d2v = Dv[NN + nodei];
                    float d3v = Dv[2 * NN + nodei];
                    float d4v = Dv[3 * NN + nodei];
                    float a0 = v0 + bv0, a1 = v1 + bv1;
                    a0 = fmaf(d4v, __ldg(&Ev[col]), a0);
                    a1 = fmaf(d4v, __ldg(&Ev[col + 1]), a1);
                    a0 = fmaf(d3v, __ldg(&Ev[NZR + col]), a0);
                    a1 = fmaf(d3v, __ldg(&Ev[NZR + col + 1]), a1);
                    a0 = fmaf(d2v, __ldg(&Ev[2 * NZR + col]), a0);
                    a1 = fmaf(d2v, __ldg(&Ev[2 * NZR + col + 1]), a1);
                    a0 = fmaf(d1v, __ldg(&Ev[3 * NZR + col]), a0);
                    a1 = fmaf(d1v, __ldg(&Ev[3 * NZR + col + 1]), a1);
                    float s0 = 1.0f / (1.0f + expf(-a0));
                    float s1 = 1.0f / (1.0f + expf(-a1));
                    if (col < CC) {
                        size_t off = (size_t)row * CC + col;
                        *(float2*)(Cm + off) = make_float2(s0, s1);
                    } else {
                        int c2 = col - CC;
                        size_t off = (size_t)row * CC + c2;
                        float2 hv = *(const float2*)(Hp + off);
                        float m0v = s0 * hv.x, m1v = s1 * hv.y;
                        *(uint32_t*)(oh + off) = split_pack(m0v, m1v);
                        *(uint32_t*)(ol + off) = split_pack_lo(m0v, m1v);
                    }
                }
            }
        }
    }
}

// ---------------- 128-wide batched propagation (plane ld parametrized) ----------------
template <bool WF32, bool WPL>
__global__ void __launch_bounds__(128) prop128_kernel(
    const float* __restrict__ Xin, float* __restrict__ Xout,
    __nv_bfloat16* __restrict__ oh, __nv_bfloat16* __restrict__ ol, int pld) {
    int r = blockIdx.x * 4 + (threadIdx.x >> 5);
    int t = threadIdx.x & 31;
    if (r >= MB) return;
    int p = r / NN;
    int i = r - p * NN;
    const float4* X4 = (const float4*)Xin;
    float sn = g_normself[i];
    float4 v = X4[(size_t)r * F4 + t];
    float4 acc = make_float4(sn * v.x, sn * v.y, sn * v.z, sn * v.w);
    int beg = g_rowptr[i];
    int end = g_rowptr[i + 1];
    int base = p * NN;
    int e = beg;
    for (; e + 4 <= end; e += 4) {
        int s0 = g_csrsrc[e], s1 = g_csrsrc[e + 1];
        int s2 = g_csrsrc[e + 2], s3 = g_csrsrc[e + 3];
        float w0 = g_csrnorm[e], w1 = g_csrnorm[e + 1];
        float w2 = g_csrnorm[e + 2], w3 = g_csrnorm[e + 3];
        float4 u0 = X4[(size_t)(base + s0) * F4 + t];
        float4 u1 = X4[(size_t)(base + s1) * F4 + t];
        float4 u2 = X4[(size_t)(base + s2) * F4 + t];
        float4 u3 = X4[(size_t)(base + s3) * F4 + t];
        acc.x = fmaf(w0, u0.x, acc.x); acc.y = fmaf(w0, u0.y, acc.y);
        acc.z = fmaf(w0, u0.z, acc.z); acc.w = fmaf(w0, u0.w, acc.w);
        acc.x = fmaf(w1, u1.x, acc.x); acc.y = fmaf(w1, u1.y, acc.y);
        acc.z = fmaf(w1, u1.z, acc.z); acc.w = fmaf(w1, u1.w, acc.w);
        acc.x = fmaf(w2, u2.x, acc.x); acc.y = fmaf(w2, u2.y, acc.y);
        acc.z = fmaf(w2, u2.z, acc.z); acc.w = fmaf(w2, u2.w, acc.w);
        acc.x = fmaf(w3, u3.x, acc.x); acc.y = fmaf(w3, u3.y, acc.y);
        acc.z = fmaf(w3, u3.z, acc.z); acc.w = fmaf(w3, u3.w, acc.w);
    }
    for (; e < end; e++) {
        int s = g_csrsrc[e];
        float w = g_csrnorm[e];
        float4 u = X4[(size_t)(base + s) * F4 + t];
        acc.x = fmaf(w, u.x, acc.x);
        acc.y = fmaf(w, u.y, acc.y);
        acc.z = fmaf(w, u.z, acc.z);
        acc.w = fmaf(w, u.w, acc.w);
    }
    if (WF32) ((float4*)Xout)[(size_t)r * F4 + t] = acc;
    if (WPL) {
        size_t off = (size_t)r * pld + t * 4;
        *(uint32_t*)(oh + off) = split_pack(acc.x, acc.y);
        *(uint32_t*)(oh + off + 2) = split_pack(acc.z, acc.w);
        *(uint32_t*)(ol + off) = split_pack_lo(acc.x, acc.y);
        *(uint32_t*)(ol + off + 2) = split_pack_lo(acc.z, acc.w);
    }
}

// ---------------- elementwise kernels ----------------
__global__ void extract_all_kernel(const float* __restrict__ x, float* __restrict__ Xp) {
    int idx = blockIdx.x * blockDim.x + threadIdx.x;
    if (idx < NN * FF) {
        float4 v = ((const float4*)x)[idx];
        Xp[idx] = v.x;
        Xp[NN * FF + idx] = v.y;
        Xp[2 * NN * FF + idx] = v.z;
        Xp[3 * NN * FF + idx] = v.w;
    }
}

__global__ void gru_reduce_kernel(const float* __restrict__ Z, const float* __restrict__ H,
                                  const float* __restrict__ Ht, float* __restrict__ out,
                                  __nv_bfloat16* __restrict__ oh, __nv_bfloat16* __restrict__ ol) {
    int idx = blockIdx.x * blockDim.x + threadIdx.x;
    if (idx >= NN * C4) return;
    int i = idx >> 7;
    int t = idx & 127;
    float4 acc = make_float4(0.f, 0.f, 0.f, 0.f);
#pragma unroll
    for (int p = 0; p < PP; p++) {
        size_t o4 = (size_t)(p * NN + i) * C4 + t;
        float4 z = ((const float4*)Z)[o4];
        float4 h = ((const float4*)H)[o4];
        float4 ht = ((const float4*)Ht)[o4];
        float pr = g_probs[p];
        acc.x += pr * (z.x * h.x + (1.0f - z.x) * ht.x);
        acc.y += pr * (z.y * h.y + (1.0f - z.y) * ht.y);
        acc.z += pr * (z.z * h.z + (1.0f - z.z) * ht.z);
        acc.w += pr * (z.w * h.w + (1.0f - z.w) * ht.w);
    }
    ((float4*)(out + NN))[idx] = acc;
    float4 v = make_float4(fmaxf(acc.x, 0.f), fmaxf(acc.y, 0.f),
                           fmaxf(acc.z, 0.f), fmaxf(acc.w, 0.f));
    size_t off = (size_t)idx * 4;
    *(uint32_t*)(oh + off) = split_pack(v.x, v.y);
    *(uint32_t*)(oh + off + 2) = split_pack(v.z, v.w);
    *(uint32_t*)(ol + off) = split_pack_lo(v.x, v.y);
    *(uint32_t*)(ol + off + 2) = split_pack_lo(v.z, v.w);
}

__global__ void lin2_kernel(const float* __restrict__ hid, const float* __restrict__ w,
                            const float* __restrict__ b, float* __restrict__ out) {
    int n = blockIdx.x * 8 + (threadIdx.x >> 5);
    int lane = threadIdx.x & 31;
    float s = 0.0f;
    for (int k = lane; k < HIDN; k += 32) s = fmaf(hid[(size_t)n * HIDN + k], w[k], s);
#pragma unroll
    for (int off = 16; off; off >>= 1) s += __shfl_down_sync(0xffffffffu, s, off);
    if (lane == 0) out[n] = s + b[0];
}

// ---------------- host orchestration ----------------
#define GP(sym) ({ void* _p; cudaGetSymbolAddress(&_p, sym); (__nv_bfloat16*)_p; })
#define GPF(sym) ({ void* _p; cudaGetSymbolAddress(&_p, sym); (float*)_p; })

struct GemmArgs {
    const __nv_bfloat16 *Ah, *Al, *Bh, *Bl;
    float* Cm;
    const float* bias;
    const float* Hp;
    const float* OldP;
    int oldLd;
    const float* Dv;
    const float* Ev;
    __nv_bfloat16 *oh, *ol;
    int M, N, K, lda;
};

template <int EPI>
static inline void launch_gemm(const GemmArgs& a) {
    dim3 grid(a.N / BN, (a.M + BM - 1) / BM);
    bf3_gemm<EPI><<<grid, 256, SMEM_BYTES>>>(a.Ah, a.Al, a.Bh, a.Bl, a.Cm, a.bias,
                                             a.Hp, a.OldP, a.oldLd, a.Dv, a.Ev,
                                             a.oh, a.ol, a.M, a.N, a.K, a.lda);
}

static inline void launch_wts(const float* W, int k0, int N, int Kb, int ldo, int ko,
                              __nv_bfloat16* oh, __nv_bfloat16* ol) {
    dim3 grid(N / 32, Kb / 32);
    wt_split_kernel<<<grid, 256>>>(W, k0, N, Kb, ldo, ko, oh, ol);
}

extern "C" void kernel_launch(void* const* d_in, const int* in_sizes, int n_in,
                              void* d_out, int out_size) {
    const float* x     = (const float*)d_in[0];
    const int*   ei    = (const int*)d_in[1];
    const float* ea    = (const float*)d_in[2];
    const float* W1    = (const float*)d_in[3];
    const float* b1    = (const float*)d_in[4];
    const float* W2    = (const float*)d_in[5];
    const float* b2    = (const float*)d_in[6];
    const float* W3    = (const float*)d_in[7];
    const float* b3    = (const float*)d_in[8];
    const float* W4    = (const float*)d_in[9];
    const float* b4    = (const float*)d_in[10];
    const float* W5    = (const float*)d_in[11];
    const float* b5    = (const float*)d_in[12];
    const float* Wz    = (const float*)d_in[13];
    const float* bz    = (const float*)d_in[14];
    const float* Lz_w  = (const float*)d_in[15];
    const float* Lz_b  = (const float*)d_in[16];
    const float* Wr    = (const float*)d_in[17];
    const float* br    = (const float*)d_in[18];
    const float* Lr_w  = (const float*)d_in[19];
    const float* Lr_b  = (const float*)d_in[20];
    const float* Wh    = (const float*)d_in[21];
    const float* bh    = (const float*)d_in[22];
    const float* Lh_w  = (const float*)d_in[23];
    const float* Lh_b  = (const float*)d_in[24];
    const float* attn  = (const float*)d_in[25];
    const float* lin1w = (const float*)d_in[26];
    const float* lin1b = (const float*)d_in[27];
    const float* lin2w = (const float*)d_in[28];
    const float* lin2b = (const float*)d_in[29];
    float* out = (float*)d_out;

    static bool attr_done = false;
    if (!attr_done) {
        cudaFuncSetAttribute(bf3_gemm<4>, cudaFuncAttributeMaxDynamicSharedMemorySize, SMEM_BYTES);
        cudaFuncSetAttribute(bf3_gemm<8>, cudaFuncAttributeMaxDynamicSharedMemorySize, SMEM_BYTES);
        cudaFuncSetAttribute(bf3_gemm<9>, cudaFuncAttributeMaxDynamicSharedMemorySize, SMEM_BYTES);
        cudaFuncSetAttribute(bf3_gemm<10>, cudaFuncAttributeMaxDynamicSharedMemorySize, SMEM_BYTES);
        cudaFuncSetAttribute(bf3_gemm<11>, cudaFuncAttributeMaxDynamicSharedMemorySize, SMEM_BYTES);
        attr_done = true;
    }

    float* pXp   = GPF(g_Xp);
    float* pXA   = GPF(g_XA);
    float* pXB   = GPF(g_XB);
    float* pH    = GPF(g_H);
    float* pZ    = GPF(g_Z);
    float* pHt   = GPF(g_Ht);
    float* pGC   = GPF(g_GC);
    float* phid1 = GPF(g_hid1);
    float* pMtmp = GPF(g_Mtmp);
    float* pMtmp2 = GPF(g_Mtmp2);
    float* pWc   = GPF(g_Wc);
    float* pbvAll = GPF(g_bvAll);
    float* pev   = GPF(g_ev);
    float* pEv   = GPF(g_Ev);
    float* pvt1  = GPF(g_vt1);
    float* pvt2  = GPF(g_vt2);
    float* pdv   = GPF(g_dv);

    __nv_bfloat16 *pAh = GP(g_A256h), *pAl = GP(g_A256l);
    __nv_bfloat16 *pRmh = GP(g_Rmh), *pRml = GP(g_Rml);
    __nv_bfloat16 *pRAh = GP(g_RAh), *pRAl = GP(g_RAl);

    __nv_bfloat16 *pWCh = GP(g_WCh), *pWCl = GP(g_WCl);
    __nv_bfloat16 *pMZRh = GP(g_MZRh), *pMZRl = GP(g_MZRl);
    __nv_bfloat16 *pMFh = GP(g_MFh), *pMFl = GP(g_MFl);
    __nv_bfloat16 *pLh2h = GP(g_Lh2h), *pLh2l = GP(g_Lh2l);
    __nv_bfloat16 *pL1th = GP(g_L1th), *pL1tl = GP(g_L1tl);

    const int gE  = (EE + 255) / 256;
    const int gN  = (NN + 255) / 256;
    const int gNC4 = (NN * C4 + 255) / 256;
    const int gNF = (NN * FF + 255) / 256;
    const int gW128 = (CC * FF + 255) / 256;

    // graph setup + CSR
    init_node_arrays<<<gN, 256>>>();
    deg_edges_kernel<<<gE, 256>>>(ei, ea);
    deg_finalize_kernel<<<gN, 256>>>();
    scan_kernel<<<1, 1024>>>();
    scatter_kernel<<<gE, 256>>>(ei, ea);
    softmax4_kernel<<<1, 32>>>(attn);

    // d vectors
    d_iter_kernel<<<gN, 256>>>(nullptr, pdv);
    d_iter_kernel<<<gN, 256>>>(pdv, pdv + NN);
    d_iter_kernel<<<gN, 256>>>(pdv + NN, pdv + 2 * NN);
    d_iter_kernel<<<gN, 256>>>(pdv + 2 * NN, pdv + 3 * NN);

    // e vectors
    vecmat_kernel<<<2, 256>>>(b4, W5, pev + 3 * CC);
    vecmat_kernel<<<2, 256>>>(b3, W4, pvt1);
    vecmat_kernel<<<2, 256>>>(pvt1, W5, pev + 2 * CC);
    vecmat_kernel<<<2, 256>>>(b2, W3, pvt1);
    vecmat_kernel<<<2, 256>>>(pvt1, W4, pvt2);
    vecmat_kernel<<<2, 256>>>(pvt2, W5, pev + CC);
    vecmat_kernel<<<2, 256>>>(b1, W2, pvt1);
    vecmat_kernel<<<2, 256>>>(pvt1, W3, pvt2);
    vecmat_kernel<<<2, 256>>>(pvt2, W4, pvt1);
    vecmat_kernel<<<2, 256>>>(pvt1, W5, pev);

    // tail weights
    launch_wts(Lh_w, CC, CC, CC, CC, 0, pLh2h, pLh2l);
    launch_wts(lin1w, 0, HIDN, CC, CC, 0, pL1th, pL1tl);

    // chain fold W~ -> split [512][128]
    gatefold_kernel<<<gW128, 256>>>(W1, W2, pMtmp);
    gatefold_kernel<<<gW128, 256>>>(pMtmp, W3, pMtmp2);
    gatefold_kernel<<<gW128, 256>>>(pMtmp2, W4, pMtmp);
    gatefold_kernel<<<gW128, 256>>>(pMtmp, W5, pWc);
    launch_wts(pWc, 0, CC, FF, FF, 0, pWCh, pWCl);

    // MZR: [Mz;MZRz] rows 0..511; [Mr;MZRr] rows 512..1023; each row K=256
    gatefold_kernel<<<gW128, 256>>>(Wz, Lz_w, pMtmp);
    launch_wts(pMtmp, 0, CC, FF, KA, 0, pMZRh, pMZRl);
    gatefold_kernel<<<gW128, 256>>>(pWc, Lz_w + (size_t)CC * CC, pMtmp);
    launch_wts(pMtmp, 0, CC, FF, KA, FF, pMZRh, pMZRl);
    gatefold_kernel<<<gW128, 256>>>(Wr, Lr_w, pMtmp);
    launch_wts(pMtmp, 0, CC, FF, KA, 0, pMZRh + (size_t)CC * KA, pMZRl + (size_t)CC * KA);
    gatefold_kernel<<<gW128, 256>>>(pWc, Lr_w + (size_t)CC * CC, pMtmp);
    launch_wts(pMtmp, 0, CC, FF, KA, FF, pMZRh + (size_t)CC * KA, pMZRl + (size_t)CC * KA);

    // E'_k = e_k @ [Lz2|Lr2]
    for (int k = 0; k < 4; k++) {
        vecmat_kernel<<<2, 256>>>(pev + k * CC, Lz_w + (size_t)CC * CC, pEv + k * NZR);
        vecmat_kernel<<<2, 256>>>(pev + k * CC, Lr_w + (size_t)CC * CC, pEv + k * NZR + CC);
    }

    // Mh fold [512][128]
    gatefold_kernel<<<gW128, 256>>>(Wh, Lh_w, pMtmp);
    launch_wts(pMtmp, 0, CC, FF, FF, 0, pMFh, pMFl);
    {
        dim3 grid(2, 3);
        gate_bias_all_kernel<<<grid, 256>>>(Lz_w, Lz_b, bz, Lr_w, Lr_b, br,
                                            Lh_w, Lh_b, bh, pbvAll);
    }
    vecmat_add_kernel<<<2, 256>>>(b5, Lz_w + (size_t)CC * CC, pbvAll);
    vecmat_add_kernel<<<2, 256>>>(b5, Lr_w + (size_t)CC * CC, pbvAll + CC);

    // ---- batched pipeline ----
    extract_all_kernel<<<gNF, 256>>>(x, pXp);

    const int gP = (MB + 3) / 4;
    // X1: fp32 -> XA, planes -> A256 cols 0..127
    prop128_kernel<true, true><<<gP, 128>>>(pXp, pXA, pAh, pAl, KA);
    // front: Gh = X1@Mh + bvh   (A=A256, lda=KA, K=128)
    GemmArgs a{};
    a = {pAh, pAl, pMFh, pMFl, pGC, pbvAll + 2 * CC, nullptr, nullptr, 0,
         nullptr, nullptr, nullptr, nullptr, MB, CC, FF, KA};
    launch_gemm<9>(a);
    // X2..X4; X5 planes -> A256 cols 128..255
    prop128_kernel<true, false><<<gP, 128>>>(pXA, pXB, nullptr, nullptr, 0);
    prop128_kernel<true, false><<<gP, 128>>>(pXB, pXA, nullptr, nullptr, 0);
    prop128_kernel<true, false><<<gP, 128>>>(pXA, pXB, nullptr, nullptr, 0);
    prop128_kernel<false, true><<<gP, 128>>>(pXB, nullptr, pAh + FF, pAl + FF, KA);

    // H = X5 @ W~ + rank4 + b5  (A=A256+128, lda=KA, K=128)
    a = {pAh + FF, pAl + FF, pWCh, pWCl, pH, b5, nullptr, nullptr, 0,
         pdv, pev, nullptr, nullptr, MB, CC, FF, KA};
    launch_gemm<10>(a);

    // ZR: [Z|R] = sigmoid(A256 @ MZR + bias + rank4)  (K=256)
    a = {pAh, pAl, pMZRh, pMZRl, pZ, pbvAll, pH, nullptr, 0,
         pdv, pEv, pRmh, pRml, MB, NZR, KA, KA};
    launch_gemm<11>(a);

    // Ht = tanh(Gh + Rm@Lh2)
    a = {pRmh, pRml, pLh2h, pLh2l, pHt, nullptr, nullptr, pGC, CC,
         nullptr, nullptr, nullptr, nullptr, MB, CC, CC, CC};
    launch_gemm<8>(a);

    gru_reduce_kernel<<<gNC4, 256>>>(pZ, pH, pHt, out, pRAh, pRAl);

    a = {pRAh, pRAl, pL1th, pL1tl, phid1, lin1b, nullptr, nullptr, 0,
         nullptr, nullptr, nullptr, nullptr, NN, HIDN, CC, CC};
    launch_gemm<4>(a);
    lin2_kernel<<<(NN + 7) / 8, 256>>>(phid1, lin2w, lin2b, out);
}

// round 17
// speedup vs baseline: 1.5747x; 1.0310x over previous
#include <cuda_runtime.h>
#include <cuda_bf16.h>
#include <stdint.h>
#include <math.h>

#define NN 10000
#define FF 128
#define PP 4
#define EE 160000
#define CC 512
#define HIDN 256
#define C4 (CC/4)
#define F4 (FF/4)
#define MB (NN*PP)
#define NZR (2*CC)
#define KA 256

// ---------------- scratch ----------------
__device__ float g_deg[NN];
__device__ float g_dinv[NN];
__device__ float g_normself[NN];
__device__ int   g_counts[NN];
__device__ int   g_rowptr[NN + 1];
__device__ int   g_cursor[NN];
__device__ int   g_csrsrc[EE];
__device__ float g_csrnorm[EE];
__device__ float g_probs[PP];

__device__ float g_Xp[MB * FF];
__device__ float g_XA[MB * FF];
__device__ float g_XB[MB * FF];
__device__ float g_H[MB * CC];
__device__ float g_Z[MB * CC];
__device__ float g_Ht[MB * CC];
__device__ float g_GC[MB * CC];
__device__ float g_hid1[NN * HIDN];
__device__ float g_Mtmp[FF * CC];
__device__ float g_Mtmp2[FF * CC];
__device__ float g_Wc[FF * CC];
__device__ float g_bvAll[3 * CC];
__device__ float g_ev[4 * CC];
__device__ float g_Ev[4 * NZR];
__device__ float g_vt1[CC], g_vt2[CC];
__device__ float g_dv[4 * NN];

__device__ __nv_bfloat16 g_A256h[MB * KA], g_A256l[MB * KA];
__device__ __nv_bfloat16 g_Rmh[MB * CC], g_Rml[MB * CC];
__device__ __nv_bfloat16 g_RAh[NN * CC], g_RAl[NN * CC];

__device__ __nv_bfloat16 g_WCh[CC * FF], g_WCl[CC * FF];
__device__ __nv_bfloat16 g_MZRh[NZR * KA], g_MZRl[NZR * KA];
__device__ __nv_bfloat16 g_MFh[CC * FF], g_MFl[CC * FF];
__device__ __nv_bfloat16 g_Lh2h[CC * CC], g_Lh2l[CC * CC];
__device__ __nv_bfloat16 g_L1th[HIDN * CC], g_L1tl[HIDN * CC];

__device__ __forceinline__ void split_bf(float x, __nv_bfloat16& h, __nv_bfloat16& l) {
    h = __float2bfloat16(x);
    l = __float2bfloat16(x - __bfloat162float(h));
}
__device__ __forceinline__ uint32_t pack_bf2(__nv_bfloat16 a, __nv_bfloat16 b) {
    __nv_bfloat162 t(a, b);
    return *(uint32_t*)&t;
}
__device__ __forceinline__ uint32_t split_pack(float a, float b) {
    __nv_bfloat16 h0, l0, h1, l1;
    split_bf(a, h0, l0); split_bf(b, h1, l1);
    return pack_bf2(h0, h1);
}
__device__ __forceinline__ uint32_t split_pack_lo(float a, float b) {
    __nv_bfloat16 h0, l0, h1, l1;
    split_bf(a, h0, l0); split_bf(b, h1, l1);
    return pack_bf2(l0, l1);
}

// ---------------- graph setup kernels ----------------
__global__ void init_node_arrays() {
    int i = blockIdx.x * blockDim.x + threadIdx.x;
    if (i < NN) { g_deg[i] = 0.0f; g_counts[i] = 0; g_cursor[i] = 0; }
}

__global__ void deg_edges_kernel(const int* __restrict__ ei, const float* __restrict__ ea) {
    int e = blockIdx.x * blockDim.x + threadIdx.x;
    if (e < EE) {
        int dst = ei[EE + e];
        atomicAdd(&g_deg[dst], ea[e]);
        atomicAdd(&g_counts[dst], 1);
    }
}

__global__ void deg_finalize_kernel() {
    int i = blockIdx.x * blockDim.x + threadIdx.x;
    if (i < NN) {
        float d = g_deg[i] + 1.0f;
        float di = (d > 0.0f) ? rsqrtf(d) : 0.0f;
        g_dinv[i] = di;
        g_normself[i] = di * di;
    }
}

__global__ void scan_kernel() {
    __shared__ int part[1024];
    const int per = 10;
    int t = threadIdx.x;
    int base = t * per;
    int loc[per];
    int s = 0;
#pragma unroll
    for (int i = 0; i < per; i++) {
        int idx = base + i;
        int v = (idx < NN) ? g_counts[idx] : 0;
        loc[i] = s; s += v;
    }
    part[t] = s;
    __syncthreads();
    for (int off = 1; off < 1024; off <<= 1) {
        int v = (t >= off) ? part[t - off] : 0;
        __syncthreads();
        part[t] += v;
        __syncthreads();
    }
    int offb = (t == 0) ? 0 : part[t - 1];
#pragma unroll
    for (int i = 0; i < per; i++) {
        int idx = base + i;
        if (idx < NN) g_rowptr[idx] = offb + loc[i];
    }
    if (t == 1023) g_rowptr[NN] = part[1023];
}

__global__ void scatter_kernel(const int* __restrict__ ei, const float* __restrict__ ea) {
    int e = blockIdx.x * blockDim.x + threadIdx.x;
    if (e < EE) {
        int src = ei[e];
        int dst = ei[EE + e];
        float nv = g_dinv[src] * ea[e] * g_dinv[dst];
        int pos = atomicAdd(&g_cursor[dst], 1);
        int slot = g_rowptr[dst] + pos;
        g_csrsrc[slot] = src;
        g_csrnorm[slot] = nv;
    }
}

__global__ void softmax4_kernel(const float* __restrict__ attn) {
    if (threadIdx.x == 0 && blockIdx.x == 0) {
        float m = attn[0];
        for (int p = 1; p < PP; p++) m = fmaxf(m, attn[p]);
        float s = 0.0f, e[PP];
        for (int p = 0; p < PP; p++) { e[p] = expf(attn[p] - m); s += e[p]; }
        for (int p = 0; p < PP; p++) g_probs[p] = e[p] / s;
    }
}

__global__ void d_iter_kernel(const float* __restrict__ din, float* __restrict__ dout) {
    int i = blockIdx.x * blockDim.x + threadIdx.x;
    if (i >= NN) return;
    float self = (din != nullptr) ? din[i] : 1.0f;
    float acc = g_normself[i] * self;
    int beg = g_rowptr[i], end = g_rowptr[i + 1];
    for (int e = beg; e < end; e++) {
        float u = (din != nullptr) ? din[g_csrsrc[e]] : 1.0f;
        acc = fmaf(g_csrnorm[e], u, acc);
    }
    dout[i] = acc;
}

__global__ void vecmat_kernel(const float* __restrict__ v, const float* __restrict__ W,
                              float* __restrict__ out) {
    int n = blockIdx.x * blockDim.x + threadIdx.x;
    if (n >= CC) return;
    float s = 0.0f;
    for (int k = 0; k < CC; k += 8) {
#pragma unroll
        for (int j = 0; j < 8; j++)
            s = fmaf(v[k + j], W[(size_t)(k + j) * CC + n], s);
    }
    out[n] = s;
}

__global__ void vecmat_add_kernel(const float* __restrict__ v, const float* __restrict__ W,
                                  float* __restrict__ out) {
    int n = blockIdx.x * blockDim.x + threadIdx.x;
    if (n >= CC) return;
    float s = 0.0f;
    for (int k = 0; k < CC; k += 8) {
#pragma unroll
        for (int j = 0; j < 8; j++)
            s = fmaf(v[k + j], W[(size_t)(k + j) * CC + n], s);
    }
    out[n] += s;
}

__global__ void wt_split_kernel(const float* __restrict__ W, int k0, int N, int Kb,
                                int ldo, int ko,
                                __nv_bfloat16* __restrict__ oh, __nv_bfloat16* __restrict__ ol) {
    __shared__ float tile[32][33];
    int nt = blockIdx.x * 32;
    int kt = blockIdx.y * 32;
    int tx = threadIdx.x & 31;
    int ty = threadIdx.x >> 5;
#pragma unroll
    for (int j = 0; j < 32; j += 8)
        tile[ty + j][tx] = W[(size_t)(k0 + kt + ty + j) * N + nt + tx];
    __syncthreads();
#pragma unroll
    for (int j = 0; j < 32; j += 8) {
        int n = nt + ty + j;
        int k = kt + tx;
        float v = tile[tx][ty + j];
        __nv_bfloat16 h, l;
        split_bf(v, h, l);
        oh[(size_t)n * ldo + ko + k] = h;
        ol[(size_t)n * ldo + ko + k] = l;
    }
}

__global__ void gatefold_kernel(const float* __restrict__ A, const float* __restrict__ Lw,
                                float* __restrict__ M) {
    int idx = blockIdx.x * blockDim.x + threadIdx.x;
    if (idx < FF * CC) {
        int f = idx / CC, n = idx - f * CC;
        float s = 0.0f;
        for (int k = 0; k < CC; k += 8) {
            float4 a0 = *(const float4*)&A[(size_t)f * CC + k];
            float4 a1 = *(const float4*)&A[(size_t)f * CC + k + 4];
            s = fmaf(a0.x, Lw[(size_t)(k + 0) * CC + n], s);
            s = fmaf(a0.y, Lw[(size_t)(k + 1) * CC + n], s);
            s = fmaf(a0.z, Lw[(size_t)(k + 2) * CC + n], s);
            s = fmaf(a0.w, Lw[(size_t)(k + 3) * CC + n], s);
            s = fmaf(a1.x, Lw[(size_t)(k + 4) * CC + n], s);
            s = fmaf(a1.y, Lw[(size_t)(k + 5) * CC + n], s);
            s = fmaf(a1.z, Lw[(size_t)(k + 6) * CC + n], s);
            s = fmaf(a1.w, Lw[(size_t)(k + 7) * CC + n], s);
        }
        M[idx] = s;
    }
}

__global__ void gate_bias_all_kernel(
    const float* __restrict__ Lz_w, const float* __restrict__ Lz_b, const float* __restrict__ bz,
    const float* __restrict__ Lr_w, const float* __restrict__ Lr_b, const float* __restrict__ br,
    const float* __restrict__ Lh_w, const float* __restrict__ Lh_b, const float* __restrict__ bh,
    float* __restrict__ bvAll) {
    int j = blockIdx.y;
    int n = blockIdx.x * blockDim.x + threadIdx.x;
    if (n >= CC) return;
    const float* Lw;
    const float* Lb;
    const float* bs;
    if (j == 0)      { Lw = Lz_w; Lb = Lz_b; bs = bz; }
    else if (j == 1) { Lw = Lr_w; Lb = Lr_b; bs = br; }
    else             { Lw = Lh_w; Lb = Lh_b; bs = bh; }
    float s = Lb[n];
    for (int k = 0; k < CC; k += 8) {
#pragma unroll
        for (int q = 0; q < 8; q++)
            s = fmaf(bs[k + q], Lw[(size_t)(k + q) * CC + n], s);
    }
    bvAll[j * CC + n] = s;
}

// ---------------- bf16x3 tensor-core GEMM ----------------
#define BM 128
#define BN 128
#define BKC 32
#define TSTR 40
#define PL_SZ (128 * TSTR)
#define STG  (4 * PL_SZ)
#define SMEM_BYTES (2 * STG * 2)

__device__ __forceinline__ void mma16816(float* c, const uint32_t* a, const uint32_t* b) {
    asm volatile(
        "mma.sync.aligned.m16n8k16.row.col.f32.bf16.bf16.f32 "
        "{%0,%1,%2,%3}, {%4,%5,%6,%7}, {%8,%9}, {%0,%1,%2,%3};"
        : "+f"(c[0]), "+f"(c[1]), "+f"(c[2]), "+f"(c[3])
        : "r"(a[0]), "r"(a[1]), "r"(a[2]), "r"(a[3]), "r"(b[0]), "r"(b[1]));
}

__device__ __forceinline__ void ldsm_x4(const void* p, uint32_t* r) {
    uint32_t addr = (uint32_t)__cvta_generic_to_shared(p);
    asm volatile("ldmatrix.sync.aligned.m8n8.x4.shared.b16 {%0,%1,%2,%3}, [%4];"
        : "=r"(r[0]), "=r"(r[1]), "=r"(r[2]), "=r"(r[3]) : "r"(addr));
}

__device__ __forceinline__ void cpa16(void* dst, const void* src, int sz) {
    uint32_t d = (uint32_t)__cvta_generic_to_shared(dst);
    asm volatile("cp.async.cg.shared.global [%0], [%1], 16, %2;"
                 :: "r"(d), "l"(src), "r"(sz));
}
__device__ __forceinline__ void cpa_commit() {
    asm volatile("cp.async.commit_group;");
}
template <int NW>
__device__ __forceinline__ void cpa_wait() {
    asm volatile("cp.async.wait_group %0;" :: "n"(NW));
}

// EPI: 4 relu(acc+bias); 8 tanh(old+acc); 9 store(acc+bias);
//      10 H rank4; 11 ZR sigmoid rank4
template <int EPI>
__global__ void __launch_bounds__(256, 2) bf3_gemm(
    const __nv_bfloat16* __restrict__ Ah, const __nv_bfloat16* __restrict__ Al,
    const __nv_bfloat16* __restrict__ Bh, const __nv_bfloat16* __restrict__ Bl,
    float* __restrict__ Cm, const float* __restrict__ bias,
    const float* __restrict__ Hp,
    const float* __restrict__ OldP, int oldLd,
    const float* __restrict__ Dv, const float* __restrict__ Ev,
    __nv_bfloat16* __restrict__ oh, __nv_bfloat16* __restrict__ ol,
    int M, int N, int K, int lda) {
    extern __shared__ __align__(16) __nv_bfloat16 sm[];

    int tid = threadIdx.x;
    int m0 = blockIdx.y * BM;
    int n0 = blockIdx.x * BN;
    int warp = tid >> 5, lane = tid & 31;
    int wm = warp >> 1, wn = warp & 1;
    int g = lane >> 2, tg = lane & 3;

    float c[2][8][4];
#pragma unroll
    for (int mt = 0; mt < 2; mt++)
#pragma unroll
        for (int nt = 0; nt < 8; nt++)
#pragma unroll
            for (int i = 0; i < 4; i++) c[mt][nt][i] = 0.0f;

    int r0 = tid >> 2, q0 = tid & 3;
    int r1 = (tid + 256) >> 2, q1 = (tid + 256) & 3;

    auto load_stage = [&](int st, int k0) {
        __nv_bfloat16* Ahs = sm + st * STG;
        __nv_bfloat16* Als = Ahs + PL_SZ;
        __nv_bfloat16* Bhs = Als + PL_SZ;
        __nv_bfloat16* Bls = Bhs + PL_SZ;
#pragma unroll
        for (int i = 0; i < 2; i++) {
            int row = i == 0 ? r0 : r1;
            int q = i == 0 ? q0 : q1;
            int m = m0 + row;
            int msz = (m < M) ? 16 : 0;
            size_t asrc = (size_t)(m < M ? m : 0) * lda + k0 + q * 8;
            cpa16(Ahs + row * TSTR + q * 8, Ah + asrc, msz);
            cpa16(Als + row * TSTR + q * 8, Al + asrc, msz);
            size_t bsrc = (size_t)(n0 + row) * K + k0 + q * 8;
            cpa16(Bhs + row * TSTR + q * 8, Bh + bsrc, 16);
            cpa16(Bls + row * TSTR + q * 8, Bl + bsrc, 16);
        }
        cpa_commit();
    };

    auto compute = [&](int st) {
        const __nv_bfloat16* Ahs = sm + st * STG;
        const __nv_bfloat16* Als = Ahs + PL_SZ;
        const __nv_bfloat16* Bhs = Als + PL_SZ;
        const __nv_bfloat16* Bls = Bhs + PL_SZ;
#pragma unroll
        for (int ks = 0; ks < 2; ks++) {
            uint32_t ahf[2][4], alf[2][4];
            int arow = lane & 15;
            int acol = ks * 16 + (lane >> 4) * 8;
#pragma unroll
            for (int mt = 0; mt < 2; mt++) {
                int r = wm * 32 + mt * 16 + arow;
                ldsm_x4(Ahs + r * TSTR + acol, ahf[mt]);
                ldsm_x4(Als + r * TSTR + acol, alf[mt]);
            }
            uint32_t bf[8][2];
            int bm_ = lane >> 3;
            int brow_in = lane & 7;
            int bro = (bm_ >> 1) * 8 + brow_in;
            int bco = ks * 16 + (bm_ & 1) * 8;
#pragma unroll
            for (int ntp = 0; ntp < 4; ntp++) {
                int nr = wn * 64 + ntp * 16 + bro;
                uint32_t t4[4];
                ldsm_x4(Bhs + nr * TSTR + bco, t4);
                bf[ntp * 2][0] = t4[0]; bf[ntp * 2][1] = t4[1];
                bf[ntp * 2 + 1][0] = t4[2]; bf[ntp * 2 + 1][1] = t4[3];
            }
#pragma unroll
            for (int mt = 0; mt < 2; mt++)
#pragma unroll
                for (int nt = 0; nt < 8; nt++) {
                    mma16816(c[mt][nt], ahf[mt], bf[nt]);
                    mma16816(c[mt][nt], alf[mt], bf[nt]);
                }
#pragma unroll
            for (int ntp = 0; ntp < 4; ntp++) {
                int nr = wn * 64 + ntp * 16 + bro;
                uint32_t t4[4];
                ldsm_x4(Bls + nr * TSTR + bco, t4);
                bf[ntp * 2][0] = t4[0]; bf[ntp * 2][1] = t4[1];
                bf[ntp * 2 + 1][0] = t4[2]; bf[ntp * 2 + 1][1] = t4[3];
            }
#pragma unroll
            for (int mt = 0; mt < 2; mt++)
#pragma unroll
                for (int nt = 0; nt < 8; nt++)
                    mma16816(c[mt][nt], ahf[mt], bf[nt]);
        }
    };

    int nchunks = K / BKC;
    load_stage(0, 0);
    for (int ch = 0; ch < nchunks; ch++) {
        int st = ch & 1;
        if (ch + 1 < nchunks) {
            load_stage(st ^ 1, (ch + 1) * BKC);
            cpa_wait<1>();
        } else {
            cpa_wait<0>();
        }
        __syncthreads();
        compute(st);
        __syncthreads();
    }

#pragma unroll
    for (int mt = 0; mt < 2; mt++) {
#pragma unroll
        for (int nt = 0; nt < 8; nt++) {
            int col = n0 + wn * 64 + nt * 8 + tg * 2;
            float bv0 = 0.f, bv1 = 0.f;
            if (EPI == 4 || EPI == 9 || EPI == 10 || EPI == 11) {
                bv0 = __ldg(&bias[col]); bv1 = __ldg(&bias[col + 1]);
            }
#pragma unroll
            for (int half = 0; half < 2; half++) {
                int row = m0 + wm * 32 + mt * 16 + g + half * 8;
                if (row >= M) continue;
                float v0 = c[mt][nt][half * 2 + 0];
                float v1 = c[mt][nt][half * 2 + 1];
                if (EPI == 4) {
                    size_t off = (size_t)row * N + col;
                    *(float2*)(Cm + off) = make_float2(fmaxf(v0 + bv0, 0.0f),
                                                       fmaxf(v1 + bv1, 0.0f));
                } else if (EPI == 8) {
                    float2 old = *(const float2*)(OldP + (size_t)row * oldLd + col);
                    size_t off = (size_t)row * N + col;
                    *(float2*)(Cm + off) = make_float2(tanhf(old.x + v0),
                                                       tanhf(old.y + v1));
                } else if (EPI == 9) {
                    size_t off = (size_t)row * N + col;
                    *(float2*)(Cm + off) = make_float2(v0 + bv0, v1 + bv1);
                } else if (EPI == 10) {
                    int nodei = row % NN;
                    float d1v = Dv[nodei];
                    float d2v = Dv[NN + nodei];
                    float d3v = Dv[2 * NN + nodei];
                    float d4v = Dv[3 * NN + nodei];
                    float cr0 = bv0, cr1 = bv1;
                    cr0 = fmaf(d4v, __ldg(&Ev[col]), cr0);
                    cr1 = fmaf(d4v, __ldg(&Ev[col + 1]), cr1);
                    cr0 = fmaf(d3v, __ldg(&Ev[CC + col]), cr0);
                    cr1 = fmaf(d3v, __ldg(&Ev[CC + col + 1]), cr1);
                    cr0 = fmaf(d2v, __ldg(&Ev[2 * CC + col]), cr0);
                    cr1 = fmaf(d2v, __ldg(&Ev[2 * CC + col + 1]), cr1);
                    cr0 = fmaf(d1v, __ldg(&Ev[3 * CC + col]), cr0);
                    cr1 = fmaf(d1v, __ldg(&Ev[3 * CC + col + 1]), cr1);
                    float h0 = v0 + cr0, h1 = v1 + cr1;
                    size_t off = (size_t)row * N + col;
                    *(float2*)(Cm + off) = make_float2(h0, h1);
                } else if (EPI == 11) {
                    int nodei = row % NN;
                    float d1v = Dv[nodei];
                    float d2v = Dv[NN + nodei];
                    float d3v = Dv[2 * NN + nodei];
                    float d4v = Dv[3 * NN + nodei];
                    float a0 = v0 + bv0, a1 = v1 + bv1;
                    a0 = fmaf(d4v, __ldg(&Ev[col]), a0);
                    a1 = fmaf(d4v, __ldg(&Ev[col + 1]), a1);
                    a0 = fmaf(d3v, __ldg(&Ev[NZR + col]), a0);
                    a1 = fmaf(d3v, __ldg(&Ev[NZR + col + 1]), a1);
                    a0 = fmaf(d2v, __ldg(&Ev[2 * NZR + col]), a0);
                    a1 = fmaf(d2v, __ldg(&Ev[2 * NZR + col + 1]), a1);
                    a0 = fmaf(d1v, __ldg(&Ev[3 * NZR + col]), a0);
                    a1 = fmaf(d1v, __ldg(&Ev[3 * NZR + col + 1]), a1);
                    float s0 = 1.0f / (1.0f + expf(-a0));
                    float s1 = 1.0f / (1.0f + expf(-a1));
                    if (col < CC) {
                        size_t off = (size_t)row * CC + col;
                        *(float2*)(Cm + off) = make_float2(s0, s1);
                    } else {
                        int c2 = col - CC;
                        size_t off = (size_t)row * CC + c2;
                        float2 hv = *(const float2*)(Hp + off);
                        float m0v = s0 * hv.x, m1v = s1 * hv.y;
                        *(uint32_t*)(oh + off) = split_pack(m0v, m1v);
                        *(uint32_t*)(ol + off) = split_pack_lo(m0v, m1v);
                    }
                }
            }
        }
    }
}

// ---------------- 128-wide batched propagation ----------------
template <bool WF32, bool WPL>
__global__ void __launch_bounds__(128) prop128_kernel(
    const float* __restrict__ Xin, float* __restrict__ Xout,
    __nv_bfloat16* __restrict__ oh, __nv_bfloat16* __restrict__ ol, int pld) {
    int r = blockIdx.x * 4 + (threadIdx.x >> 5);
    int t = threadIdx.x & 31;
    if (r >= MB) return;
    int p = r / NN;
    int i = r - p * NN;
    const float4* X4 = (const float4*)Xin;
    float sn = g_normself[i];
    float4 v = X4[(size_t)r * F4 + t];
    float4 acc = make_float4(sn * v.x, sn * v.y, sn * v.z, sn * v.w);
    int beg = g_rowptr[i];
    int end = g_rowptr[i + 1];
    int base = p * NN;
    int e = beg;
    for (; e + 4 <= end; e += 4) {
        int s0 = g_csrsrc[e], s1 = g_csrsrc[e + 1];
        int s2 = g_csrsrc[e + 2], s3 = g_csrsrc[e + 3];
        float w0 = g_csrnorm[e], w1 = g_csrnorm[e + 1];
        float w2 = g_csrnorm[e + 2], w3 = g_csrnorm[e + 3];
        float4 u0 = X4[(size_t)(base + s0) * F4 + t];
        float4 u1 = X4[(size_t)(base + s1) * F4 + t];
        float4 u2 = X4[(size_t)(base + s2) * F4 + t];
        float4 u3 = X4[(size_t)(base + s3) * F4 + t];
        acc.x = fmaf(w0, u0.x, acc.x); acc.y = fmaf(w0, u0.y, acc.y);
        acc.z = fmaf(w0, u0.z, acc.z); acc.w = fmaf(w0, u0.w, acc.w);
        acc.x = fmaf(w1, u1.x, acc.x); acc.y = fmaf(w1, u1.y, acc.y);
        acc.z = fmaf(w1, u1.z, acc.z); acc.w = fmaf(w1, u1.w, acc.w);
        acc.x = fmaf(w2, u2.x, acc.x); acc.y = fmaf(w2, u2.y, acc.y);
        acc.z = fmaf(w2, u2.z, acc.z); acc.w = fmaf(w2, u2.w, acc.w);
        acc.x = fmaf(w3, u3.x, acc.x); acc.y = fmaf(w3, u3.y, acc.y);
        acc.z = fmaf(w3, u3.z, acc.z); acc.w = fmaf(w3, u3.w, acc.w);
    }
    for (; e < end; e++) {
        int s = g_csrsrc[e];
        float w = g_csrnorm[e];
        float4 u = X4[(size_t)(base + s) * F4 + t];
        acc.x = fmaf(w, u.x, acc.x);
        acc.y = fmaf(w, u.y, acc.y);
        acc.z = fmaf(w, u.z, acc.z);
        acc.w = fmaf(w, u.w, acc.w);
    }
    if (WF32) ((float4*)Xout)[(size_t)r * F4 + t] = acc;
    if (WPL) {
        size_t off = (size_t)r * pld + t * 4;
        *(uint32_t*)(oh + off) = split_pack(acc.x, acc.y);
        *(uint32_t*)(oh + off + 2) = split_pack(acc.z, acc.w);
        *(uint32_t*)(ol + off) = split_pack_lo(acc.x, acc.y);
        *(uint32_t*)(ol + off + 2) = split_pack_lo(acc.z, acc.w);
    }
}

// ---------------- elementwise kernels ----------------
__global__ void extract_all_kernel(const float* __restrict__ x, float* __restrict__ Xp) {
    int idx = blockIdx.x * blockDim.x + threadIdx.x;
    if (idx < NN * FF) {
        float4 v = ((const float4*)x)[idx];
        Xp[idx] = v.x;
        Xp[NN * FF + idx] = v.y;
        Xp[2 * NN * FF + idx] = v.z;
        Xp[3 * NN * FF + idx] = v.w;
    }
}

__global__ void gru_reduce_kernel(const float* __restrict__ Z, const float* __restrict__ H,
                                  const float* __restrict__ Ht, float* __restrict__ out,
                                  __nv_bfloat16* __restrict__ oh, __nv_bfloat16* __restrict__ ol) {
    int idx = blockIdx.x * blockDim.x + threadIdx.x;
    if (idx >= NN * C4) return;
    int i = idx >> 7;
    int t = idx & 127;
    float4 acc = make_float4(0.f, 0.f, 0.f, 0.f);
#pragma unroll
    for (int p = 0; p < PP; p++) {
        size_t o4 = (size_t)(p * NN + i) * C4 + t;
        float4 z = ((const float4*)Z)[o4];
        float4 h = ((const float4*)H)[o4];
        float4 ht = ((const float4*)Ht)[o4];
        float pr = g_probs[p];
        acc.x += pr * (z.x * h.x + (1.0f - z.x) * ht.x);
        acc.y += pr * (z.y * h.y + (1.0f - z.y) * ht.y);
        acc.z += pr * (z.z * h.z + (1.0f - z.z) * ht.z);
        acc.w += pr * (z.w * h.w + (1.0f - z.w) * ht.w);
    }
    ((float4*)(out + NN))[idx] = acc;
    float4 v = make_float4(fmaxf(acc.x, 0.f), fmaxf(acc.y, 0.f),
                           fmaxf(acc.z, 0.f), fmaxf(acc.w, 0.f));
    size_t off = (size_t)idx * 4;
    *(uint32_t*)(oh + off) = split_pack(v.x, v.y);
    *(uint32_t*)(oh + off + 2) = split_pack(v.z, v.w);
    *(uint32_t*)(ol + off) = split_pack_lo(v.x, v.y);
    *(uint32_t*)(ol + off + 2) = split_pack_lo(v.z, v.w);
}

__global__ void lin2_kernel(const float* __restrict__ hid, const float* __restrict__ w,
                            const float* __restrict__ b, float* __restrict__ out) {
    int n = blockIdx.x * 8 + (threadIdx.x >> 5);
    int lane = threadIdx.x & 31;
    float s = 0.0f;
    for (int k = lane; k < HIDN; k += 32) s = fmaf(hid[(size_t)n * HIDN + k], w[k], s);
#pragma unroll
    for (int off = 16; off; off >>= 1) s += __shfl_down_sync(0xffffffffu, s, off);
    if (lane == 0) out[n] = s + b[0];
}

// ---------------- host orchestration ----------------
#define GP(sym) ({ void* _p; cudaGetSymbolAddress(&_p, sym); (__nv_bfloat16*)_p; })
#define GPF(sym) ({ void* _p; cudaGetSymbolAddress(&_p, sym); (float*)_p; })

struct GemmArgs {
    const __nv_bfloat16 *Ah, *Al, *Bh, *Bl;
    float* Cm;
    const float* bias;
    const float* Hp;
    const float* OldP;
    int oldLd;
    const float* Dv;
    const float* Ev;
    __nv_bfloat16 *oh, *ol;
    int M, N, K, lda;
};

template <int EPI>
static inline void launch_gemm(const GemmArgs& a, cudaStream_t s) {
    dim3 grid(a.N / BN, (a.M + BM - 1) / BM);
    bf3_gemm<EPI><<<grid, 256, SMEM_BYTES, s>>>(a.Ah, a.Al, a.Bh, a.Bl, a.Cm, a.bias,
                                                a.Hp, a.OldP, a.oldLd, a.Dv, a.Ev,
                                                a.oh, a.ol, a.M, a.N, a.K, a.lda);
}

static inline void launch_wts(const float* W, int k0, int N, int Kb, int ldo, int ko,
                              __nv_bfloat16* oh, __nv_bfloat16* ol, cudaStream_t s) {
    dim3 grid(N / 32, Kb / 32);
    wt_split_kernel<<<grid, 256, 0, s>>>(W, k0, N, Kb, ldo, ko, oh, ol);
}

extern "C" void kernel_launch(void* const* d_in, const int* in_sizes, int n_in,
                              void* d_out, int out_size) {
    const float* x     = (const float*)d_in[0];
    const int*   ei    = (const int*)d_in[1];
    const float* ea    = (const float*)d_in[2];
    const float* W1    = (const float*)d_in[3];
    const float* b1    = (const float*)d_in[4];
    const float* W2    = (const float*)d_in[5];
    const float* b2    = (const float*)d_in[6];
    const float* W3    = (const float*)d_in[7];
    const float* b3    = (const float*)d_in[8];
    const float* W4    = (const float*)d_in[9];
    const float* b4    = (const float*)d_in[10];
    const float* W5    = (const float*)d_in[11];
    const float* b5    = (const float*)d_in[12];
    const float* Wz    = (const float*)d_in[13];
    const float* bz    = (const float*)d_in[14];
    const float* Lz_w  = (const float*)d_in[15];
    const float* Lz_b  = (const float*)d_in[16];
    const float* Wr    = (const float*)d_in[17];
    const float* br    = (const float*)d_in[18];
    const float* Lr_w  = (const float*)d_in[19];
    const float* Lr_b  = (const float*)d_in[20];
    const float* Wh    = (const float*)d_in[21];
    const float* bh    = (const float*)d_in[22];
    const float* Lh_w  = (const float*)d_in[23];
    const float* Lh_b  = (const float*)d_in[24];
    const float* attn  = (const float*)d_in[25];
    const float* lin1w = (const float*)d_in[26];
    const float* lin1b = (const float*)d_in[27];
    const float* lin2w = (const float*)d_in[28];
    const float* lin2b = (const float*)d_in[29];
    float* out = (float*)d_out;

    static bool init_done = false;
    static cudaStream_t sB;
    static cudaEvent_t evFork, evJoin;
    if (!init_done) {
        cudaFuncSetAttribute(bf3_gemm<4>, cudaFuncAttributeMaxDynamicSharedMemorySize, SMEM_BYTES);
        cudaFuncSetAttribute(bf3_gemm<8>, cudaFuncAttributeMaxDynamicSharedMemorySize, SMEM_BYTES);
        cudaFuncSetAttribute(bf3_gemm<9>, cudaFuncAttributeMaxDynamicSharedMemorySize, SMEM_BYTES);
        cudaFuncSetAttribute(bf3_gemm<10>, cudaFuncAttributeMaxDynamicSharedMemorySize, SMEM_BYTES);
        cudaFuncSetAttribute(bf3_gemm<11>, cudaFuncAttributeMaxDynamicSharedMemorySize, SMEM_BYTES);
        cudaStreamCreateWithFlags(&sB, cudaStreamNonBlocking);
        cudaEventCreateWithFlags(&evFork, cudaEventDisableTiming);
        cudaEventCreateWithFlags(&evJoin, cudaEventDisableTiming);
        init_done = true;
    }
    cudaStream_t s0 = 0;

    float* pXp   = GPF(g_Xp);
    float* pXA   = GPF(g_XA);
    float* pXB   = GPF(g_XB);
    float* pH    = GPF(g_H);
    float* pZ    = GPF(g_Z);
    float* pHt   = GPF(g_Ht);
    float* pGC   = GPF(g_GC);
    float* phid1 = GPF(g_hid1);
    float* pMtmp = GPF(g_Mtmp);
    float* pMtmp2 = GPF(g_Mtmp2);
    float* pWc   = GPF(g_Wc);
    float* pbvAll = GPF(g_bvAll);
    float* pev   = GPF(g_ev);
    float* pEv   = GPF(g_Ev);
    float* pvt1  = GPF(g_vt1);
    float* pvt2  = GPF(g_vt2);
    float* pdv   = GPF(g_dv);

    __nv_bfloat16 *pAh = GP(g_A256h), *pAl = GP(g_A256l);
    __nv_bfloat16 *pRmh = GP(g_Rmh), *pRml = GP(g_Rml);
    __nv_bfloat16 *pRAh = GP(g_RAh), *pRAl = GP(g_RAl);

    __nv_bfloat16 *pWCh = GP(g_WCh), *pWCl = GP(g_WCl);
    __nv_bfloat16 *pMZRh = GP(g_MZRh), *pMZRl = GP(g_MZRl);
    __nv_bfloat16 *pMFh = GP(g_MFh), *pMFl = GP(g_MFl);
    __nv_bfloat16 *pLh2h = GP(g_Lh2h), *pLh2l = GP(g_Lh2l);
    __nv_bfloat16 *pL1th = GP(g_L1th), *pL1tl = GP(g_L1tl);

    const int gE  = (EE + 255) / 256;
    const int gN  = (NN + 255) / 256;
    const int gNC4 = (NN * C4 + 255) / 256;
    const int gNF = (NN * FF + 255) / 256;
    const int gW128 = (CC * FF + 255) / 256;

    // ---- fork: weight prep on sB ----
    cudaEventRecord(evFork, s0);
    cudaStreamWaitEvent(sB, evFork, 0);

    // [sB] weight-only preparation
    softmax4_kernel<<<1, 32, 0, sB>>>(attn);
    // e vectors
    vecmat_kernel<<<2, 256, 0, sB>>>(b4, W5, pev + 3 * CC);
    vecmat_kernel<<<2, 256, 0, sB>>>(b3, W4, pvt1);
    vecmat_kernel<<<2, 256, 0, sB>>>(pvt1, W5, pev + 2 * CC);
    vecmat_kernel<<<2, 256, 0, sB>>>(b2, W3, pvt1);
    vecmat_kernel<<<2, 256, 0, sB>>>(pvt1, W4, pvt2);
    vecmat_kernel<<<2, 256, 0, sB>>>(pvt2, W5, pev + CC);
    vecmat_kernel<<<2, 256, 0, sB>>>(b1, W2, pvt1);
    vecmat_kernel<<<2, 256, 0, sB>>>(pvt1, W3, pvt2);
    vecmat_kernel<<<2, 256, 0, sB>>>(pvt2, W4, pvt1);
    vecmat_kernel<<<2, 256, 0, sB>>>(pvt1, W5, pev);
    // tail weights
    launch_wts(Lh_w, CC, CC, CC, CC, 0, pLh2h, pLh2l, sB);
    launch_wts(lin1w, 0, HIDN, CC, CC, 0, pL1th, pL1tl, sB);
    // chain fold W~
    gatefold_kernel<<<gW128, 256, 0, sB>>>(W1, W2, pMtmp);
    gatefold_kernel<<<gW128, 256, 0, sB>>>(pMtmp, W3, pMtmp2);
    gatefold_kernel<<<gW128, 256, 0, sB>>>(pMtmp2, W4, pMtmp);
    gatefold_kernel<<<gW128, 256, 0, sB>>>(pMtmp, W5, pWc);
    launch_wts(pWc, 0, CC, FF, FF, 0, pWCh, pWCl, sB);
    // MZR
    gatefold_kernel<<<gW128, 256, 0, sB>>>(Wz, Lz_w, pMtmp);
    launch_wts(pMtmp, 0, CC, FF, KA, 0, pMZRh, pMZRl, sB);
    gatefold_kernel<<<gW128, 256, 0, sB>>>(pWc, Lz_w + (size_t)CC * CC, pMtmp);
    launch_wts(pMtmp, 0, CC, FF, KA, FF, pMZRh, pMZRl, sB);
    gatefold_kernel<<<gW128, 256, 0, sB>>>(Wr, Lr_w, pMtmp);
    launch_wts(pMtmp, 0, CC, FF, KA, 0, pMZRh + (size_t)CC * KA, pMZRl + (size_t)CC * KA, sB);
    gatefold_kernel<<<gW128, 256, 0, sB>>>(pWc, Lr_w + (size_t)CC * CC, pMtmp);
    launch_wts(pMtmp, 0, CC, FF, KA, FF, pMZRh + (size_t)CC * KA, pMZRl + (size_t)CC * KA, sB);
    // E'_k
    for (int k = 0; k < 4; k++) {
        vecmat_kernel<<<2, 256, 0, sB>>>(pev + k * CC, Lz_w + (size_t)CC * CC, pEv + k * NZR);
        vecmat_kernel<<<2, 256, 0, sB>>>(pev + k * CC, Lr_w + (size_t)CC * CC, pEv + k * NZR + CC);
    }
    // Mh fold
    gatefold_kernel<<<gW128, 256, 0, sB>>>(Wh, Lh_w, pMtmp);
    launch_wts(pMtmp, 0, CC, FF, FF, 0, pMFh, pMFl, sB);
    {
        dim3 grid(2, 3);
        gate_bias_all_kernel<<<grid, 256, 0, sB>>>(Lz_w, Lz_b, bz, Lr_w, Lr_b, br,
                                                   Lh_w, Lh_b, bh, pbvAll);
    }
    vecmat_add_kernel<<<2, 256, 0, sB>>>(b5, Lz_w + (size_t)CC * CC, pbvAll);
    vecmat_add_kernel<<<2, 256, 0, sB>>>(b5, Lr_w + (size_t)CC * CC, pbvAll + CC);
    cudaEventRecord(evJoin, sB);

    // [s0] graph setup + CSR + d vectors + data spine
    init_node_arrays<<<gN, 256, 0, s0>>>();
    deg_edges_kernel<<<gE, 256, 0, s0>>>(ei, ea);
    deg_finalize_kernel<<<gN, 256, 0, s0>>>();
    scan_kernel<<<1, 1024, 0, s0>>>();
    scatter_kernel<<<gE, 256, 0, s0>>>(ei, ea);
    d_iter_kernel<<<gN, 256, 0, s0>>>(nullptr, pdv);
    d_iter_kernel<<<gN, 256, 0, s0>>>(pdv, pdv + NN);
    d_iter_kernel<<<gN, 256, 0, s0>>>(pdv + NN, pdv + 2 * NN);
    d_iter_kernel<<<gN, 256, 0, s0>>>(pdv + 2 * NN, pdv + 3 * NN);

    extract_all_kernel<<<gNF, 256, 0, s0>>>(x, pXp);

    const int gP = (MB + 3) / 4;
    prop128_kernel<true, true><<<gP, 128, 0, s0>>>(pXp, pXA, pAh, pAl, KA);
    prop128_kernel<true, false><<<gP, 128, 0, s0>>>(pXA, pXB, nullptr, nullptr, 0);
    prop128_kernel<true, false><<<gP, 128, 0, s0>>>(pXB, pXA, nullptr, nullptr, 0);
    prop128_kernel<true, false><<<gP, 128, 0, s0>>>(pXA, pXB, nullptr, nullptr, 0);
    prop128_kernel<false, true><<<gP, 128, 0, s0>>>(pXB, nullptr, pAh + FF, pAl + FF, KA);

    // ---- join: GEMMs need folded weights ----
    cudaStreamWaitEvent(s0, evJoin, 0);

    GemmArgs a{};
    // front: Gh = X1@Mh + bvh
    a = {pAh, pAl, pMFh, pMFl, pGC, pbvAll + 2 * CC, nullptr, nullptr, 0,
         nullptr, nullptr, nullptr, nullptr, MB, CC, FF, KA};
    launch_gemm<9>(a, s0);

    // H = X5 @ W~ + rank4 + b5
    a = {pAh + FF, pAl + FF, pWCh, pWCl, pH, b5, nullptr, nullptr, 0,
         pdv, pev, nullptr, nullptr, MB, CC, FF, KA};
    launch_gemm<10>(a, s0);

    // ZR
    a = {pAh, pAl, pMZRh, pMZRl, pZ, pbvAll, pH, nullptr, 0,
         pdv, pEv, pRmh, pRml, MB, NZR, KA, KA};
    launch_gemm<11>(a, s0);

    // Ht = tanh(Gh + Rm@Lh2)
    a = {pRmh, pRml, pLh2h, pLh2l, pHt, nullptr, nullptr, pGC, CC,
         nullptr, nullptr, nullptr, nullptr, MB, CC, CC, CC};
    launch_gemm<8>(a, s0);

    gru_reduce_kernel<<<gNC4, 256, 0, s0>>>(pZ, pH, pHt, out, pRAh, pRAl);

    a = {pRAh, pRAl, pL1th, pL1tl, phid1, lin1b, nullptr, nullptr, 0,
         nullptr, nullptr, nullptr, nullptr, NN, HIDN, CC, CC};
    launch_gemm<4>(a, s0);
    lin2_kernel<<<(NN + 7) / 8, 256, 0, s0>>>(phid1, lin2w, lin2b, out);
}